// round 1
// baseline (speedup 1.0000x reference)
#include <cuda_runtime.h>
#include <math.h>

// ---------------- problem constants ----------------
#define BATCH 32
#define SEQ   257
#define DIM   1024
#define NHEAD 16
#define HDIM  64
#define NEXP  8
#define TOPK  2
#define RANK  16
#define GHID  256
#define SD    (SEQ*DIM)          // 263168
#define MROWS (BATCH*SEQ)        // 8224
#define SS    (SEQ*SEQ)          // 66049
#define ATTN_SCALE 0.125f        // 64^-0.5

// ---------------- static device scratch (no allocations allowed) ----------------
__device__ int   g_idx[BATCH*TOPK];
__device__ float g_gates[BATCH*TOPK];
// folded low-rank factors per projection (q,k,v,o) per batch sample
// Vw[p][b][j][d]  j = k*RANK+r,  value = S[e][r]*V[e][r][d]
// Uw[p][b][n][j]  value = gate_k * U[e][n][r]
__device__ float g_Vw[4ll*BATCH*32*DIM];     // 16 MB
__device__ float g_Uw[4ll*BATCH*DIM*32];     // 16 MB
__device__ float g_t [4ll*BATCH*SEQ*32];     // ~4.2 MB  (x @ Vw^T per proj)
__device__ float g_q [MROWS*DIM];
__device__ float g_k [MROWS*DIM];
__device__ float g_v [MROWS*DIM];
__device__ float g_scores[(long)BATCH*NHEAD*SS]; // 135 MB
__device__ float g_ctx[MROWS*DIM];

// ---------------- gating ----------------
__global__ void gating_kernel(const float* __restrict__ x,
                              const float* __restrict__ gw1, const float* __restrict__ gb1,
                              const float* __restrict__ gw2, const float* __restrict__ gb2,
                              int* __restrict__ idx, float* __restrict__ gates)
{
    int b = blockIdx.x;
    int tid = threadIdx.x;                 // 256 threads
    __shared__ float pooled[DIM];
    __shared__ float h[GHID];
    __shared__ float logits[NEXP];

    const float* xb = x + (long)b * SD;
    for (int d = tid; d < DIM; d += 256) {
        float s = 0.f;
        for (int t = 0; t < SEQ; t++) s += xb[(long)t*DIM + d];
        pooled[d] = s * (1.0f / SEQ);
    }
    __syncthreads();
    {
        float s = gb1[tid];
        const float* w = gw1 + (long)tid * DIM;
        #pragma unroll 8
        for (int d = 0; d < DIM; d++) s += pooled[d] * w[d];
        h[tid] = fmaxf(s, 0.f);
    }
    __syncthreads();
    if (tid < NEXP) {
        float s = gb2[tid];
        const float* w = gw2 + (long)tid * GHID;
        for (int g = 0; g < GHID; g++) s += h[g] * w[g];
        logits[tid] = s;
    }
    __syncthreads();
    if (tid == 0) {
        int i1 = 0; float v1 = logits[0];
        for (int e = 1; e < NEXP; e++) if (logits[e] > v1) { v1 = logits[e]; i1 = e; }
        int i2 = -1; float v2 = -3.0e38f;
        for (int e = 0; e < NEXP; e++) if (e != i1 && logits[e] > v2) { v2 = logits[e]; i2 = e; }
        float e2 = expf(v2 - v1);
        float inv = 1.f / (1.f + e2);
        idx[b*2] = i1; idx[b*2+1] = i2;
        gates[b*2] = inv; gates[b*2+1] = e2 * inv;
    }
}

// ---------------- fold S into V and gates into U (per batch sample) ----------------
__global__ void build_uv_kernel(const float* __restrict__ U,   // (E, D, R)
                                const float* __restrict__ Sg,  // (E, R)
                                const float* __restrict__ V,   // (E, R, D)
                                const int* __restrict__ idx, const float* __restrict__ gates,
                                float* __restrict__ Vw,        // (B, 32, D)
                                float* __restrict__ Uw)        // (B, D, 32)
{
    int b = blockIdx.x;
    int tid = threadIdx.x;
    int e0 = idx[b*2], e1 = idx[b*2+1];
    float g0 = gates[b*2], g1 = gates[b*2+1];
    float* vw = Vw + (long)b * 32 * DIM;
    float* uw = Uw + (long)b * DIM * 32;

    for (int i = tid; i < 32*DIM; i += 256) {
        int j = i >> 10, d = i & (DIM-1);
        int k = j >> 4, r = j & 15;
        int e = k ? e1 : e0;
        vw[i] = Sg[e*RANK + r] * V[((long)e*RANK + r)*DIM + d];
    }
    for (int i = tid; i < DIM*32; i += 256) {
        int n = i >> 5, j = i & 31;
        int k = j >> 4, r = j & 15;
        int e = k ? e1 : e0;
        float g = k ? g1 : g0;
        uw[i] = g * U[((long)e*DIM + n)*RANK + r];
    }
}

// ---------------- generic batched SGEMM ----------------
// C = alpha * A @ op(B) [+ bias[n]] [+= C]
// BT=true : B is (N,K) row-major  -> B[n*ldb+k]
// BT=false: B is (K,N) row-major  -> B[k*ldb+n]
// batch z: ptr offset = (z/zdiv)*s1 + (z%zdiv)*s2
#define BM 64
#define BN 64
#define BKK 16

template<bool BT, bool ACC, bool BIAS>
__global__ void sgemm_kernel(const float* __restrict__ A, const float* __restrict__ B,
                             float* __restrict__ C, const float* __restrict__ bias,
                             int M, int N, int K, int lda, int ldb, int ldc,
                             long sA1, long sA2, long sB1, long sB2, long sC1, long sC2,
                             int zdiv, float alpha)
{
    int z = blockIdx.z;
    long zq = z / zdiv, zr = z % zdiv;
    A += zq*sA1 + zr*sA2;
    B += zq*sB1 + zr*sB2;
    C += zq*sC1 + zr*sC2;

    int m0 = blockIdx.y * BM, n0 = blockIdx.x * BN;
    __shared__ float As[BKK][BM+1];
    __shared__ float Bs[BKK][BN+1];

    int tid = threadIdx.x;
    int tx = tid & 15, ty = tid >> 4;
    float acc[4][4] = {};

    for (int k0 = 0; k0 < K; k0 += BKK) {
        for (int i = tid; i < BM*BKK; i += 256) {
            int m = i / BKK, k = i % BKK;
            int gm = m0 + m, gk = k0 + k;
            As[k][m] = (gm < M && gk < K) ? A[(long)gm*lda + gk] : 0.f;
        }
        if (BT) {
            for (int i = tid; i < BN*BKK; i += 256) {
                int n = i / BKK, k = i % BKK;
                int gn = n0 + n, gk = k0 + k;
                Bs[k][n] = (gn < N && gk < K) ? B[(long)gn*ldb + gk] : 0.f;
            }
        } else {
            for (int i = tid; i < BN*BKK; i += 256) {
                int k = i / BN, n = i % BN;
                int gn = n0 + n, gk = k0 + k;
                Bs[k][n] = (gn < N && gk < K) ? B[(long)gk*ldb + gn] : 0.f;
            }
        }
        __syncthreads();
        #pragma unroll
        for (int k = 0; k < BKK; k++) {
            float a[4], bb[4];
            #pragma unroll
            for (int i = 0; i < 4; i++) a[i] = As[k][ty*4+i];
            #pragma unroll
            for (int j = 0; j < 4; j++) bb[j] = Bs[k][tx*4+j];
            #pragma unroll
            for (int i = 0; i < 4; i++)
                #pragma unroll
                for (int j = 0; j < 4; j++)
                    acc[i][j] += a[i] * bb[j];
        }
        __syncthreads();
    }

    #pragma unroll
    for (int i = 0; i < 4; i++) {
        int gm = m0 + ty*4 + i;
        if (gm >= M) continue;
        #pragma unroll
        for (int j = 0; j < 4; j++) {
            int gn = n0 + tx*4 + j;
            if (gn >= N) continue;
            float v = acc[i][j] * alpha;
            if (BIAS) v += bias[gn];
            long off = (long)gm*ldc + gn;
            if (ACC) v += C[off];
            C[off] = v;
        }
    }
}

// ---------------- row softmax over 257 ----------------
__global__ void softmax_kernel(float* __restrict__ scores)
{
    long row = blockIdx.x;
    float* p = scores + row * SEQ;
    int tid = threadIdx.x;        // 256
    __shared__ float red[256];

    float m = -3.0e38f;
    for (int i = tid; i < SEQ; i += 256) m = fmaxf(m, p[i]);
    red[tid] = m; __syncthreads();
    for (int s = 128; s > 0; s >>= 1) { if (tid < s) red[tid] = fmaxf(red[tid], red[tid+s]); __syncthreads(); }
    m = red[0]; __syncthreads();

    float sum = 0.f;
    for (int i = tid; i < SEQ; i += 256) { float e = expf(p[i] - m); p[i] = e; sum += e; }
    red[tid] = sum; __syncthreads();
    for (int s = 128; s > 0; s >>= 1) { if (tid < s) red[tid] += red[tid+s]; __syncthreads(); }
    float inv = 1.f / red[0];
    for (int i = tid; i < SEQ; i += 256) p[i] *= inv;
}

// ---------------- host launch ----------------
static void* dsym(const void* symbol) { void* p = nullptr; cudaGetSymbolAddress(&p, symbol); return p; }
static inline dim3 ggrid(int N, int M, int Z) { return dim3((N+BN-1)/BN, (M+BM-1)/BM, Z); }

extern "C" void kernel_launch(void* const* d_in, const int* in_sizes, int n_in,
                              void* d_out, int out_size)
{
    const float* x   = (const float*)d_in[0];
    const float* gw1 = (const float*)d_in[1];
    const float* gb1 = (const float*)d_in[2];
    const float* gw2 = (const float*)d_in[3];
    const float* gb2 = (const float*)d_in[4];
    const float* Wm[4]; const float* Ue[4]; const float* Se[4]; const float* Ve[4]; const float* bi[4];
    for (int p = 0; p < 4; p++) {
        Wm[p] = (const float*)d_in[5 + p*5 + 0];
        Ue[p] = (const float*)d_in[5 + p*5 + 1];
        Se[p] = (const float*)d_in[5 + p*5 + 2];
        Ve[p] = (const float*)d_in[5 + p*5 + 3];
        bi[p] = (const float*)d_in[5 + p*5 + 4];
    }
    float* out = (float*)d_out;

    int*   idxp   = (int*)dsym(g_idx);
    float* gatesp = (float*)dsym(g_gates);
    float* Vw     = (float*)dsym(g_Vw);
    float* Uw     = (float*)dsym(g_Uw);
    float* tbuf   = (float*)dsym(g_t);
    float* bq     = (float*)dsym(g_q);
    float* bk     = (float*)dsym(g_k);
    float* bv     = (float*)dsym(g_v);
    float* sc     = (float*)dsym(g_scores);
    float* ctx    = (float*)dsym(g_ctx);

    const long VW_PER = (long)BATCH*32*DIM;
    const long UW_PER = (long)BATCH*DIM*32;
    const long T_PER  = (long)BATCH*SEQ*32;

    // 1) gating
    gating_kernel<<<BATCH, 256>>>(x, gw1, gb1, gw2, gb2, idxp, gatesp);

    // 2) fold expert factors for all 4 projections
    for (int p = 0; p < 4; p++)
        build_uv_kernel<<<BATCH, 256>>>(Ue[p], Se[p], Ve[p], idxp, gatesp,
                                        Vw + p*VW_PER, Uw + p*UW_PER);

    // 3) q,k,v projections: main GEMM + low-rank expert path
    float* qkv[3] = { bq, bk, bv };
    for (int p = 0; p < 3; p++) {
        // t = x @ Vw^T   (per-b batched: M=257,N=32,K=1024)
        sgemm_kernel<true,false,false><<<ggrid(32, SEQ, BATCH), 256>>>(
            x, Vw + p*VW_PER, tbuf + p*T_PER, nullptr,
            SEQ, 32, DIM, DIM, DIM, 32,
            (long)SD, 0, (long)32*DIM, 0, (long)SEQ*32, 0, 1, 1.f);
        // main: out = x @ Wm^T + bias   (M=8224,N=1024,K=1024)
        sgemm_kernel<true,false,true><<<ggrid(DIM, MROWS, 1), 256>>>(
            x, Wm[p], qkv[p], bi[p],
            MROWS, DIM, DIM, DIM, DIM, DIM,
            0, 0, 0, 0, 0, 0, 1, 1.f);
        // expert: out += t @ Uw^T   (per-b batched: M=257,N=1024,K=32)
        sgemm_kernel<true,true,false><<<ggrid(DIM, SEQ, BATCH), 256>>>(
            tbuf + p*T_PER, Uw + p*UW_PER, qkv[p], nullptr,
            SEQ, DIM, 32, 32, 32, DIM,
            (long)SEQ*32, 0, (long)DIM*32, 0, (long)SD, 0, 1, 1.f);
    }

    // 4) attention scores = SCALE * q @ k^T   batched over (b,h): M=N=257,K=64
    sgemm_kernel<true,false,false><<<ggrid(SEQ, SEQ, BATCH*NHEAD), 256>>>(
        bq, bk, sc, nullptr,
        SEQ, SEQ, HDIM, DIM, DIM, SEQ,
        (long)SD, (long)HDIM, (long)SD, (long)HDIM,
        (long)NHEAD*SS, (long)SS, NHEAD, ATTN_SCALE);

    // 5) row softmax
    softmax_kernel<<<(unsigned)((long)BATCH*NHEAD*SEQ), 256>>>(sc);

    // 6) ctx = probs @ v   batched: M=257,N=64,K=257  (B not transposed)
    sgemm_kernel<false,false,false><<<ggrid(HDIM, SEQ, BATCH*NHEAD), 256>>>(
        sc, bv, ctx, nullptr,
        SEQ, HDIM, SEQ, SEQ, DIM, DIM,
        (long)NHEAD*SS, (long)SS, (long)SD, (long)HDIM,
        (long)SD, (long)HDIM, NHEAD, 1.f);

    // 7) output projection on ctx -> d_out
    {
        int p = 3;
        sgemm_kernel<true,false,false><<<ggrid(32, SEQ, BATCH), 256>>>(
            ctx, Vw + p*VW_PER, tbuf + p*T_PER, nullptr,
            SEQ, 32, DIM, DIM, DIM, 32,
            (long)SD, 0, (long)32*DIM, 0, (long)SEQ*32, 0, 1, 1.f);
        sgemm_kernel<true,false,true><<<ggrid(DIM, MROWS, 1), 256>>>(
            ctx, Wm[p], out, bi[p],
            MROWS, DIM, DIM, DIM, DIM, DIM,
            0, 0, 0, 0, 0, 0, 1, 1.f);
        sgemm_kernel<true,true,false><<<ggrid(DIM, SEQ, BATCH), 256>>>(
            tbuf + p*T_PER, Uw + p*UW_PER, out, nullptr,
            SEQ, DIM, 32, 32, 32, DIM,
            (long)SEQ*32, 0, (long)DIM*32, 0, (long)SD, 0, 1, 1.f);
    }
}

// round 2
// speedup vs baseline: 2.0240x; 2.0240x over previous
#include <cuda_runtime.h>
#include <math.h>
#include <stdint.h>

// ---------------- problem constants ----------------
#define BATCH 32
#define SEQ   257
#define DIM   1024
#define NHEAD 16
#define HDIM  64
#define NEXP  8
#define TOPK  2
#define RANK  16
#define GHID  256
#define SD    (SEQ*DIM)          // 263168
#define MROWS (BATCH*SEQ)        // 8224
#define SS    (SEQ*SEQ)          // 66049
#define ATTN_SCALE 0.125f        // 64^-0.5

// ---------------- static device scratch ----------------
__device__ int   g_idx[BATCH*TOPK];
__device__ float g_gates[BATCH*TOPK];
__device__ float g_Vw[4ll*BATCH*32*DIM];
__device__ float g_Uw[4ll*BATCH*DIM*32];
__device__ float g_t [4ll*BATCH*SEQ*32];
__device__ float g_q [MROWS*DIM];
__device__ float g_k [MROWS*DIM];
__device__ float g_v [MROWS*DIM];
__device__ float g_scores[(long)BATCH*NHEAD*SS]; // 135 MB
__device__ float g_ctx[MROWS*DIM];

// ---------------- gating (exact fp32; expert selection must be stable) ----------------
__global__ void gating_kernel(const float* __restrict__ x,
                              const float* __restrict__ gw1, const float* __restrict__ gb1,
                              const float* __restrict__ gw2, const float* __restrict__ gb2,
                              int* __restrict__ idx, float* __restrict__ gates)
{
    int b = blockIdx.x;
    int tid = threadIdx.x;                 // 256 threads
    __shared__ float pooled[DIM];
    __shared__ float h[GHID];
    __shared__ float logits[NEXP];

    const float* xb = x + (long)b * SD;
    for (int d = tid; d < DIM; d += 256) {
        float s = 0.f;
        for (int t = 0; t < SEQ; t++) s += xb[(long)t*DIM + d];
        pooled[d] = s * (1.0f / SEQ);
    }
    __syncthreads();
    {
        float s = gb1[tid];
        const float* w = gw1 + (long)tid * DIM;
        #pragma unroll 8
        for (int d = 0; d < DIM; d++) s += pooled[d] * w[d];
        h[tid] = fmaxf(s, 0.f);
    }
    __syncthreads();
    if (tid < NEXP) {
        float s = gb2[tid];
        const float* w = gw2 + (long)tid * GHID;
        for (int g = 0; g < GHID; g++) s += h[g] * w[g];
        logits[tid] = s;
    }
    __syncthreads();
    if (tid == 0) {
        int i1 = 0; float v1 = logits[0];
        for (int e = 1; e < NEXP; e++) if (logits[e] > v1) { v1 = logits[e]; i1 = e; }
        int i2 = -1; float v2 = -3.0e38f;
        for (int e = 0; e < NEXP; e++) if (e != i1 && logits[e] > v2) { v2 = logits[e]; i2 = e; }
        float e2 = expf(v2 - v1);
        float inv = 1.f / (1.f + e2);
        idx[b*2] = i1; idx[b*2+1] = i2;
        gates[b*2] = inv; gates[b*2+1] = e2 * inv;
    }
}

// ---------------- fold S into V and gates into U ----------------
__global__ void build_uv_kernel(const float* __restrict__ U,   // (E, D, R)
                                const float* __restrict__ Sg,  // (E, R)
                                const float* __restrict__ V,   // (E, R, D)
                                const int* __restrict__ idx, const float* __restrict__ gates,
                                float* __restrict__ Vw,        // (B, 32, D)
                                float* __restrict__ Uw)        // (B, D, 32)
{
    int b = blockIdx.x;
    int tid = threadIdx.x;
    int e0 = idx[b*2], e1 = idx[b*2+1];
    float g0 = gates[b*2], g1 = gates[b*2+1];
    float* vw = Vw + (long)b * 32 * DIM;
    float* uw = Uw + (long)b * DIM * 32;

    for (int i = tid; i < 32*DIM; i += 256) {
        int j = i >> 10, d = i & (DIM-1);
        int k = j >> 4, r = j & 15;
        int e = k ? e1 : e0;
        vw[i] = Sg[e*RANK + r] * V[((long)e*RANK + r)*DIM + d];
    }
    for (int i = tid; i < DIM*32; i += 256) {
        int n = i >> 5, j = i & 31;
        int k = j >> 4, r = j & 15;
        int e = k ? e1 : e0;
        float g = k ? g1 : g0;
        uw[i] = g * U[((long)e*DIM + n)*RANK + r];
    }
}

// ---------------- TF32 tensor-core batched GEMM ----------------
// C = alpha * A @ op(B) [+ bias[n]] [+= C]
// BT=true : B is (N,K) row-major;  BT=false: B is (K,N) row-major
// AV4/BV4: float4 global loads are legal (contract: lda/ldb and K (or N) %4==0, base aligned)
#define TBM 128
#define TBN 64
#define TBK 32

__device__ __forceinline__ uint32_t f2tf(float x) {
    uint32_t r; asm("cvt.rna.tf32.f32 %0, %1;" : "=r"(r) : "f"(x)); return r;
}

__device__ __forceinline__ void mma_tf32(float c[4], const uint32_t a[4], const uint32_t b[2]) {
    asm volatile(
        "mma.sync.aligned.m16n8k8.row.col.f32.tf32.tf32.f32 "
        "{%0,%1,%2,%3}, {%4,%5,%6,%7}, {%8,%9}, {%0,%1,%2,%3};"
        : "+f"(c[0]), "+f"(c[1]), "+f"(c[2]), "+f"(c[3])
        : "r"(a[0]), "r"(a[1]), "r"(a[2]), "r"(a[3]), "r"(b[0]), "r"(b[1]));
}

template<bool BT, bool ACC, bool BIAS, bool AV4, bool BV4>
__global__ void tgemm_kernel(const float* __restrict__ A, const float* __restrict__ B,
                             float* __restrict__ C, const float* __restrict__ bias,
                             int M, int N, int K, int lda, int ldb, int ldc,
                             long sA1, long sA2, long sB1, long sB2, long sC1, long sC2,
                             int zdiv, float alpha)
{
    int z = blockIdx.z;
    long zq = z / zdiv, zr = z % zdiv;
    A += zq*sA1 + zr*sA2;
    B += zq*sB1 + zr*sB2;
    C += zq*sC1 + zr*sC2;

    int m0 = blockIdx.y * TBM, n0 = blockIdx.x * TBN;
    __shared__ uint32_t As[TBM][TBK+4];   // stride 36 words -> frag banks 4g+tg, conflict-free
    __shared__ uint32_t Bs[TBK][TBN+8];   // stride 72 words -> frag banks 8tg+g, conflict-free

    int tid = threadIdx.x;
    int warp = tid >> 5, lane = tid & 31;
    int wm = (warp & 3) * 32;   // 4 warps along M
    int wn = (warp >> 2) * 32;  // 2 warps along N
    int g = lane >> 2, tg = lane & 3;

    float acc[2][4][4] = {};

    for (int k0 = 0; k0 < K; k0 += TBK) {
        // ---- A tile -> smem (tf32) ----
        if (AV4) {
            #pragma unroll
            for (int i = tid; i < TBM*(TBK/4); i += 256) {
                int m = i / (TBK/4), k4 = i % (TBK/4);
                int gm = m0 + m, gk = k0 + k4*4;
                float4 v = make_float4(0.f,0.f,0.f,0.f);
                if (gm < M && gk < K) v = *(const float4*)(A + (long)gm*lda + gk);
                As[m][k4*4+0] = f2tf(v.x); As[m][k4*4+1] = f2tf(v.y);
                As[m][k4*4+2] = f2tf(v.z); As[m][k4*4+3] = f2tf(v.w);
            }
        } else {
            for (int i = tid; i < TBM*TBK; i += 256) {
                int m = i / TBK, k = i % TBK;
                int gm = m0 + m, gk = k0 + k;
                float v = (gm < M && gk < K) ? A[(long)gm*lda + gk] : 0.f;
                As[m][k] = f2tf(v);
            }
        }
        // ---- B tile -> smem (tf32), layout Bs[k][n] ----
        if (BT) {
            if (BV4) {
                #pragma unroll
                for (int i = tid; i < TBN*(TBK/4); i += 256) {
                    int n = i / (TBK/4), k4 = i % (TBK/4);
                    int gn = n0 + n, gk = k0 + k4*4;
                    float4 v = make_float4(0.f,0.f,0.f,0.f);
                    if (gn < N && gk < K) v = *(const float4*)(B + (long)gn*ldb + gk);
                    Bs[k4*4+0][n] = f2tf(v.x); Bs[k4*4+1][n] = f2tf(v.y);
                    Bs[k4*4+2][n] = f2tf(v.z); Bs[k4*4+3][n] = f2tf(v.w);
                }
            } else {
                for (int i = tid; i < TBN*TBK; i += 256) {
                    int n = i / TBK, k = i % TBK;
                    int gn = n0 + n, gk = k0 + k;
                    float v = (gn < N && gk < K) ? B[(long)gn*ldb + gk] : 0.f;
                    Bs[k][n] = f2tf(v);
                }
            }
        } else {
            if (BV4) {
                #pragma unroll
                for (int i = tid; i < TBK*(TBN/4); i += 256) {
                    int k = i / (TBN/4), n4 = i % (TBN/4);
                    int gk = k0 + k, gn = n0 + n4*4;
                    float4 v = make_float4(0.f,0.f,0.f,0.f);
                    if (gk < K && gn < N) v = *(const float4*)(B + (long)gk*ldb + gn);
                    Bs[k][n4*4+0] = f2tf(v.x); Bs[k][n4*4+1] = f2tf(v.y);
                    Bs[k][n4*4+2] = f2tf(v.z); Bs[k][n4*4+3] = f2tf(v.w);
                }
            } else {
                for (int i = tid; i < TBK*TBN; i += 256) {
                    int k = i / TBN, n = i % TBN;
                    int gk = k0 + k, gn = n0 + n;
                    float v = (gk < K && gn < N) ? B[(long)gk*ldb + gn] : 0.f;
                    Bs[k][n] = f2tf(v);
                }
            }
        }
        __syncthreads();

        #pragma unroll
        for (int kk = 0; kk < TBK/8; kk++) {
            uint32_t a[2][4], bf[4][2];
            #pragma unroll
            for (int i = 0; i < 2; i++) {
                int r = wm + i*16;
                a[i][0] = As[r + g    ][kk*8 + tg    ];
                a[i][1] = As[r + g + 8][kk*8 + tg    ];
                a[i][2] = As[r + g    ][kk*8 + tg + 4];
                a[i][3] = As[r + g + 8][kk*8 + tg + 4];
            }
            #pragma unroll
            for (int j = 0; j < 4; j++) {
                bf[j][0] = Bs[kk*8 + tg    ][wn + j*8 + g];
                bf[j][1] = Bs[kk*8 + tg + 4][wn + j*8 + g];
            }
            #pragma unroll
            for (int i = 0; i < 2; i++)
                #pragma unroll
                for (int j = 0; j < 4; j++)
                    mma_tf32(acc[i][j], a[i], bf[j]);
        }
        __syncthreads();
    }

    // ---- epilogue ----
    #pragma unroll
    for (int i = 0; i < 2; i++) {
        #pragma unroll
        for (int rs = 0; rs < 2; rs++) {
            int gm = m0 + wm + i*16 + g + rs*8;
            if (gm >= M) continue;
            #pragma unroll
            for (int j = 0; j < 4; j++) {
                int gn = n0 + wn + j*8 + tg*2;
                float v0 = acc[i][j][rs*2+0] * alpha;
                float v1 = acc[i][j][rs*2+1] * alpha;
                if (gn < N) {
                    long off = (long)gm*ldc + gn;
                    float v = v0;
                    if (BIAS) v += bias[gn];
                    if (ACC)  v += C[off];
                    C[off] = v;
                }
                if (gn + 1 < N) {
                    long off = (long)gm*ldc + gn + 1;
                    float v = v1;
                    if (BIAS) v += bias[gn+1];
                    if (ACC)  v += C[off];
                    C[off] = v;
                }
            }
        }
    }
}

// ---------------- row softmax over 257 ----------------
__global__ void softmax_kernel(float* __restrict__ scores)
{
    long row = blockIdx.x;
    float* p = scores + row * SEQ;
    int tid = threadIdx.x;        // 256
    __shared__ float red[256];

    float m = -3.0e38f;
    for (int i = tid; i < SEQ; i += 256) m = fmaxf(m, p[i]);
    red[tid] = m; __syncthreads();
    for (int s = 128; s > 0; s >>= 1) { if (tid < s) red[tid] = fmaxf(red[tid], red[tid+s]); __syncthreads(); }
    m = red[0]; __syncthreads();

    float sum = 0.f;
    for (int i = tid; i < SEQ; i += 256) { float e = expf(p[i] - m); p[i] = e; sum += e; }
    red[tid] = sum; __syncthreads();
    for (int s = 128; s > 0; s >>= 1) { if (tid < s) red[tid] += red[tid+s]; __syncthreads(); }
    float inv = 1.f / red[0];
    for (int i = tid; i < SEQ; i += 256) p[i] *= inv;
}

// ---------------- host launch ----------------
static void* dsym(const void* symbol) { void* p = nullptr; cudaGetSymbolAddress(&p, symbol); return p; }
static inline dim3 tgrid(int N, int M, int Z) { return dim3((N+TBN-1)/TBN, (M+TBM-1)/TBM, Z); }

extern "C" void kernel_launch(void* const* d_in, const int* in_sizes, int n_in,
                              void* d_out, int out_size)
{
    const float* x   = (const float*)d_in[0];
    const float* gw1 = (const float*)d_in[1];
    const float* gb1 = (const float*)d_in[2];
    const float* gw2 = (const float*)d_in[3];
    const float* gb2 = (const float*)d_in[4];
    const float* Wm[4]; const float* Ue[4]; const float* Se[4]; const float* Ve[4]; const float* bi[4];
    for (int p = 0; p < 4; p++) {
        Wm[p] = (const float*)d_in[5 + p*5 + 0];
        Ue[p] = (const float*)d_in[5 + p*5 + 1];
        Se[p] = (const float*)d_in[5 + p*5 + 2];
        Ve[p] = (const float*)d_in[5 + p*5 + 3];
        bi[p] = (const float*)d_in[5 + p*5 + 4];
    }
    float* out = (float*)d_out;

    int*   idxp   = (int*)dsym(g_idx);
    float* gatesp = (float*)dsym(g_gates);
    float* Vw     = (float*)dsym(g_Vw);
    float* Uw     = (float*)dsym(g_Uw);
    float* tbuf   = (float*)dsym(g_t);
    float* bq     = (float*)dsym(g_q);
    float* bk     = (float*)dsym(g_k);
    float* bv     = (float*)dsym(g_v);
    float* sc     = (float*)dsym(g_scores);
    float* ctx    = (float*)dsym(g_ctx);

    const long VW_PER = (long)BATCH*32*DIM;
    const long UW_PER = (long)BATCH*DIM*32;
    const long T_PER  = (long)BATCH*SEQ*32;

    // 1) gating (exact fp32)
    gating_kernel<<<BATCH, 256>>>(x, gw1, gb1, gw2, gb2, idxp, gatesp);

    // 2) fold expert factors
    for (int p = 0; p < 4; p++)
        build_uv_kernel<<<BATCH, 256>>>(Ue[p], Se[p], Ve[p], idxp, gatesp,
                                        Vw + p*VW_PER, Uw + p*UW_PER);

    // 3) q,k,v projections
    float* qkv[3] = { bq, bk, bv };
    for (int p = 0; p < 3; p++) {
        // t = x @ Vw^T  (per-b: M=257,N=32,K=1024)
        tgemm_kernel<true,false,false,true,true><<<tgrid(32, SEQ, BATCH), 256>>>(
            x, Vw + p*VW_PER, tbuf + p*T_PER, nullptr,
            SEQ, 32, DIM, DIM, DIM, 32,
            (long)SD, 0, (long)32*DIM, 0, (long)SEQ*32, 0, 1, 1.f);
        // main: out = x @ Wm^T + bias  (M=8224,N=1024,K=1024)
        tgemm_kernel<true,false,true,true,true><<<tgrid(DIM, MROWS, 1), 256>>>(
            x, Wm[p], qkv[p], bi[p],
            MROWS, DIM, DIM, DIM, DIM, DIM,
            0, 0, 0, 0, 0, 0, 1, 1.f);
        // expert: out += t @ Uw^T  (per-b: M=257,N=1024,K=32)
        tgemm_kernel<true,true,false,true,true><<<tgrid(DIM, SEQ, BATCH), 256>>>(
            tbuf + p*T_PER, Uw + p*UW_PER, qkv[p], nullptr,
            SEQ, DIM, 32, 32, 32, DIM,
            (long)SEQ*32, 0, (long)DIM*32, 0, (long)SD, 0, 1, 1.f);
    }

    // 4) scores = SCALE * q @ k^T  batched (b,h): M=N=257,K=64
    tgemm_kernel<true,false,false,true,true><<<tgrid(SEQ, SEQ, BATCH*NHEAD), 256>>>(
        bq, bk, sc, nullptr,
        SEQ, SEQ, HDIM, DIM, DIM, SEQ,
        (long)SD, (long)HDIM, (long)SD, (long)HDIM,
        (long)NHEAD*SS, (long)SS, NHEAD, ATTN_SCALE);

    // 5) softmax
    softmax_kernel<<<(unsigned)((long)BATCH*NHEAD*SEQ), 256>>>(sc);

    // 6) ctx = probs @ v  batched: M=257,N=64,K=257 (A unaligned lda=257 -> scalar loads)
    tgemm_kernel<false,false,false,false,true><<<tgrid(HDIM, SEQ, BATCH*NHEAD), 256>>>(
        sc, bv, ctx, nullptr,
        SEQ, HDIM, SEQ, SEQ, DIM, DIM,
        (long)NHEAD*SS, (long)SS, (long)SD, (long)HDIM,
        (long)SD, (long)HDIM, NHEAD, 1.f);

    // 7) output projection
    {
        int p = 3;
        tgemm_kernel<true,false,false,true,true><<<tgrid(32, SEQ, BATCH), 256>>>(
            ctx, Vw + p*VW_PER, tbuf + p*T_PER, nullptr,
            SEQ, 32, DIM, DIM, DIM, 32,
            (long)SD, 0, (long)32*DIM, 0, (long)SEQ*32, 0, 1, 1.f);
        tgemm_kernel<true,false,true,true,true><<<tgrid(DIM, MROWS, 1), 256>>>(
            ctx, Wm[p], out, bi[p],
            MROWS, DIM, DIM, DIM, DIM, DIM,
            0, 0, 0, 0, 0, 0, 1, 1.f);
        tgemm_kernel<true,true,false,true,true><<<tgrid(DIM, SEQ, BATCH), 256>>>(
            tbuf + p*T_PER, Uw + p*UW_PER, out, nullptr,
            SEQ, DIM, 32, 32, 32, DIM,
            (long)SEQ*32, 0, (long)DIM*32, 0, (long)SD, 0, 1, 1.f);
    }
}

// round 3
// speedup vs baseline: 2.4320x; 1.2016x over previous
#include <cuda_runtime.h>
#include <math.h>
#include <stdint.h>

// ---------------- problem constants ----------------
#define BATCH 32
#define SEQ   257
#define SEQP  288                // padded score row stride (mult of 32, 16B aligned)
#define DIM   1024
#define NHEAD 16
#define HDIM  64
#define NEXP  8
#define TOPK  2
#define RANK  16
#define GHID  256
#define SD    (SEQ*DIM)          // 263168
#define MROWS (BATCH*SEQ)        // 8224
#define ATTN_SCALE 0.125f

// ---------------- static device scratch ----------------
__device__ int   g_idx[BATCH*TOPK];
__device__ float g_gates[BATCH*TOPK];
__device__ float g_xr [MROWS*DIM];               // tf32-rounded x
__device__ float g_Wmr[4ll*DIM*DIM];             // tf32-rounded main weights
__device__ float g_Vw[4ll*BATCH*32*DIM];
__device__ float g_Uw[4ll*BATCH*DIM*32];
__device__ float g_t [4ll*BATCH*SEQ*32];
__device__ float g_q [MROWS*DIM];
__device__ float g_k [MROWS*DIM];
__device__ float g_v [MROWS*DIM + 32*1024];      // padded: probs@V k-tail overreads
__device__ float g_scores[(long)BATCH*NHEAD*SEQ*SEQP]; // ~152 MB
__device__ float g_ctx[MROWS*DIM];

__device__ __forceinline__ uint32_t f2tf(float x) {
    uint32_t r; asm("cvt.rna.tf32.f32 %0, %1;" : "=r"(r) : "f"(x)); return r;
}
__device__ __forceinline__ float f2tff(float x) { return __uint_as_float(f2tf(x)); }

// ---------------- tf32 rounding copy ----------------
__global__ void round_kernel(const float* __restrict__ src, float* __restrict__ dst, long n)
{
    long i = (long)blockIdx.x * blockDim.x + threadIdx.x;
    long stride = (long)gridDim.x * blockDim.x;
    for (; i < n; i += stride) dst[i] = f2tff(src[i]);
}

// ---------------- gating (exact fp32) ----------------
__global__ void gating_kernel(const float* __restrict__ x,
                              const float* __restrict__ gw1, const float* __restrict__ gb1,
                              const float* __restrict__ gw2, const float* __restrict__ gb2,
                              int* __restrict__ idx, float* __restrict__ gates)
{
    int b = blockIdx.x;
    int tid = threadIdx.x;                 // 256 threads
    __shared__ float pooled[DIM];
    __shared__ float h[GHID];
    __shared__ float logits[NEXP];

    const float* xb = x + (long)b * SD;
    for (int d = tid; d < DIM; d += 256) {
        float s = 0.f;
        for (int t = 0; t < SEQ; t++) s += xb[(long)t*DIM + d];
        pooled[d] = s * (1.0f / SEQ);
    }
    __syncthreads();
    {
        float s = gb1[tid];
        const float* w = gw1 + (long)tid * DIM;
        #pragma unroll 8
        for (int d = 0; d < DIM; d++) s += pooled[d] * w[d];
        h[tid] = fmaxf(s, 0.f);
    }
    __syncthreads();
    if (tid < NEXP) {
        float s = gb2[tid];
        const float* w = gw2 + (long)tid * GHID;
        for (int g = 0; g < GHID; g++) s += h[g] * w[g];
        logits[tid] = s;
    }
    __syncthreads();
    if (tid == 0) {
        int i1 = 0; float v1 = logits[0];
        for (int e = 1; e < NEXP; e++) if (logits[e] > v1) { v1 = logits[e]; i1 = e; }
        int i2 = -1; float v2 = -3.0e38f;
        for (int e = 0; e < NEXP; e++) if (e != i1 && logits[e] > v2) { v2 = logits[e]; i2 = e; }
        float e2 = expf(v2 - v1);
        float inv = 1.f / (1.f + e2);
        idx[b*2] = i1; idx[b*2+1] = i2;
        gates[b*2] = inv; gates[b*2+1] = e2 * inv;
    }
}

// ---------------- fold S into V, gates into U (tf32-rounded outputs) ----------------
__global__ void build_uv_kernel(const float* __restrict__ U, const float* __restrict__ Sg,
                                const float* __restrict__ V,
                                const int* __restrict__ idx, const float* __restrict__ gates,
                                float* __restrict__ Vw, float* __restrict__ Uw)
{
    int b = blockIdx.x;
    int tid = threadIdx.x;
    int e0 = idx[b*2], e1 = idx[b*2+1];
    float g0 = gates[b*2], g1 = gates[b*2+1];
    float* vw = Vw + (long)b * 32 * DIM;
    float* uw = Uw + (long)b * DIM * 32;

    for (int i = tid; i < 32*DIM; i += 256) {
        int j = i >> 10, d = i & (DIM-1);
        int k = j >> 4, r = j & 15;
        int e = k ? e1 : e0;
        vw[i] = f2tff(Sg[e*RANK + r] * V[((long)e*RANK + r)*DIM + d]);
    }
    for (int i = tid; i < DIM*32; i += 256) {
        int n = i >> 5, j = i & 31;
        int k = j >> 4, r = j & 15;
        int e = k ? e1 : e0;
        float g = k ? g1 : g0;
        uw[i] = f2tff(g * U[((long)e*DIM + n)*RANK + r]);
    }
}

// ---------------- TF32 tensor-core batched GEMM (frag-major smem, reg prefetch) ----
// C = alpha * A @ op(B) [+ bias] [+= C]; inputs must already be tf32-rounded fp32.
// Alignment contract: A,B base and lda,ldb,K (and batch strides) give 16B-aligned rows;
// K % 32 == 0.
#define TBM 128
#define TBN 64
#define TBK 32

__device__ __forceinline__ void mma_tf32(float c[4], const uint32_t a[4], const uint32_t b[2]) {
    asm volatile(
        "mma.sync.aligned.m16n8k8.row.col.f32.tf32.tf32.f32 "
        "{%0,%1,%2,%3}, {%4,%5,%6,%7}, {%8,%9}, {%0,%1,%2,%3};"
        : "+f"(c[0]), "+f"(c[1]), "+f"(c[2]), "+f"(c[3])
        : "r"(a[0]), "r"(a[1]), "r"(a[2]), "r"(a[3]), "r"(b[0]), "r"(b[1]));
}

// frag-major offsets
__device__ __forceinline__ int a_off(int kk, int mt, int lane) { return ((kk*8 + mt)*32 + lane)*4; }
__device__ __forceinline__ int b_off(int kk, int nt, int lane) { return ((kk*8 + nt)*32 + lane)*2; }

template<bool BT, bool ACC, bool BIAS, bool ROUND>
__global__ __launch_bounds__(256, 2)
void tgemm_kernel(const float* __restrict__ A, const float* __restrict__ B,
                  float* __restrict__ C, const float* __restrict__ bias,
                  int M, int N, int K, int lda, int ldb, int ldc,
                  long sA1, long sA2, long sB1, long sB2, long sC1, long sC2,
                  int zdiv, float alpha)
{
    int z = blockIdx.z;
    long zq = z / zdiv, zr = z % zdiv;
    A += zq*sA1 + zr*sA2;
    B += zq*sB1 + zr*sB2;
    C += zq*sC1 + zr*sC2;

    int m0 = blockIdx.y * TBM, n0 = blockIdx.x * TBN;
    __shared__ __align__(16) float As[4*8*32*4];  // [kk][mt][lane][4]  16KB
    __shared__ __align__(16) float Bs[4*8*32*2];  // [kk][nt][lane][2]   8KB

    int tid = threadIdx.x;
    int warp = tid >> 5, lane = tid & 31;
    int mt0 = (warp & 3) * 2;   // warp covers mtiles mt0, mt0+1 (32 rows)
    int nt0 = (warp >> 2) * 4;  // warp covers ntiles nt0..nt0+3 (32 cols)
    int g = lane >> 2, tg = lane & 3;

    float acc[2][4][4] = {};
    float4 ar[4];
    float4 br[2];

    const int KB = K / TBK;

    // ---- register load of tile kb ----
    auto load_regs = [&](int kb) {
        int k0 = kb * TBK;
        #pragma unroll
        for (int i = 0; i < 4; i++) {
            int f4 = i*256 + tid;
            int m = f4 >> 3, k4 = f4 & 7;
            int gm = m0 + m;
            if (gm < M) ar[i] = *(const float4*)(A + (long)gm*lda + k0 + k4*4);
            else        ar[i] = make_float4(0.f,0.f,0.f,0.f);
        }
        if (BT) {
            #pragma unroll
            for (int i = 0; i < 2; i++) {
                int f4 = i*256 + tid;
                int n = f4 >> 3, k4 = f4 & 7;
                int gn = n0 + n;
                if (gn < N) br[i] = *(const float4*)(B + (long)gn*ldb + k0 + k4*4);
                else        br[i] = make_float4(0.f,0.f,0.f,0.f);
            }
        } else {
            #pragma unroll
            for (int i = 0; i < 2; i++) {
                int f4 = i*256 + tid;
                int k = f4 >> 4, n4 = f4 & 15;
                int gn = n0 + n4*4;
                if (gn < N) br[i] = *(const float4*)(B + (long)(k0 + k)*ldb + gn);
                else        br[i] = make_float4(0.f,0.f,0.f,0.f);
            }
        }
    };

    // ---- regs -> frag-major smem ----
    auto sts = [&]() {
        #pragma unroll
        for (int i = 0; i < 4; i++) {
            int f4 = i*256 + tid;
            int m = f4 >> 3, k4 = f4 & 7;
            int kk = k4 >> 1;
            int slot = ((m & 15) >> 3) + 2*(k4 & 1);
            int base = a_off(kk, m >> 4, (m & 7)*4) + slot;  // lane=(m&7)*4 + c
            As[base +  0] = ar[i].x;
            As[base +  4] = ar[i].y;
            As[base +  8] = ar[i].z;
            As[base + 12] = ar[i].w;
        }
        if (BT) {
            #pragma unroll
            for (int i = 0; i < 2; i++) {
                int f4 = i*256 + tid;
                int n = f4 >> 3, k4 = f4 & 7;
                int kk = k4 >> 1;
                int slot = k4 & 1;
                int base = b_off(kk, n >> 3, (n & 7)*4) + slot;  // lane=(n&7)*4 + c
                Bs[base + 0] = br[i].x;
                Bs[base + 2] = br[i].y;
                Bs[base + 4] = br[i].z;
                Bs[base + 6] = br[i].w;
            }
        } else {
            #pragma unroll
            for (int i = 0; i < 2; i++) {
                int f4 = i*256 + tid;
                int k = f4 >> 4, n4 = f4 & 15;
                int kk = k >> 3, k8 = k & 7;
                int slot = k8 >> 2;
                int nt = n4 >> 1;
                int lanebase = ((n4 & 1)*4)*4 + (k8 & 3); // lane=((n4&1)*4+c)*4+(k8&3)
                int base = b_off(kk, nt, 0) + slot;
                Bs[base + (lanebase + 0*4)*2] = br[i].x;
                Bs[base + (lanebase + 1*4)*2] = br[i].y;
                Bs[base + (lanebase + 2*4)*2] = br[i].z;
                Bs[base + (lanebase + 3*4)*2] = br[i].w;
            }
        }
    };

    // ---- prologue ----
    load_regs(0);
    sts();
    __syncthreads();

    for (int kb = 0; kb < KB; kb++) {
        if (kb + 1 < KB) load_regs(kb + 1);   // prefetch next tile into regs

        #pragma unroll
        for (int kk = 0; kk < 4; kk++) {
            float4 af[2];
            af[0] = *(const float4*)&As[a_off(kk, mt0    , lane)];
            af[1] = *(const float4*)&As[a_off(kk, mt0 + 1, lane)];
            float2 bf[4];
            #pragma unroll
            for (int j = 0; j < 4; j++)
                bf[j] = *(const float2*)&Bs[b_off(kk, nt0 + j, lane)];
            #pragma unroll
            for (int i = 0; i < 2; i++) {
                uint32_t a[4] = { __float_as_uint(af[i].x), __float_as_uint(af[i].y),
                                  __float_as_uint(af[i].z), __float_as_uint(af[i].w) };
                #pragma unroll
                for (int j = 0; j < 4; j++) {
                    uint32_t b2[2] = { __float_as_uint(bf[j].x), __float_as_uint(bf[j].y) };
                    mma_tf32(acc[i][j], a, b2);
                }
            }
        }

        if (kb + 1 < KB) {
            __syncthreads();
            sts();
            __syncthreads();
        }
    }

    // ---- epilogue ----
    int wm = mt0 * 16, wn = nt0 * 8;
    #pragma unroll
    for (int i = 0; i < 2; i++) {
        #pragma unroll
        for (int rs = 0; rs < 2; rs++) {
            int gm = m0 + wm + i*16 + g + rs*8;
            if (gm >= M) continue;
            #pragma unroll
            for (int j = 0; j < 4; j++) {
                int gn = n0 + wn + j*8 + tg*2;
                #pragma unroll
                for (int c = 0; c < 2; c++) {
                    if (gn + c >= N) continue;
                    long off = (long)gm*ldc + gn + c;
                    float v = acc[i][j][rs*2+c] * alpha;
                    if (BIAS) v += bias[gn+c];
                    if (ACC)  v += C[off];
                    if (ROUND) v = f2tff(v);
                    C[off] = v;
                }
            }
        }
    }
}

// ---------------- softmax: 1 warp per row, rounds output, zero-pads to SEQP ------
__global__ void softmax_kernel(float* __restrict__ scores)
{
    int warp = threadIdx.x >> 5, lane = threadIdx.x & 31;
    long row = (long)blockIdx.x * 4 + warp;
    float* p = scores + row * SEQP;

    float vals[9];
    float m = -3.0e38f;
    #pragma unroll
    for (int i = 0; i < 9; i++) {
        int idx = lane + i*32;
        vals[i] = (idx < SEQ) ? p[idx] : -3.0e38f;
        m = fmaxf(m, vals[i]);
    }
    #pragma unroll
    for (int s = 16; s > 0; s >>= 1) m = fmaxf(m, __shfl_xor_sync(0xffffffffu, m, s));

    float sum = 0.f;
    #pragma unroll
    for (int i = 0; i < 9; i++) {
        int idx = lane + i*32;
        float e = (idx < SEQ) ? expf(vals[i] - m) : 0.f;
        vals[i] = e;
        sum += e;
    }
    #pragma unroll
    for (int s = 16; s > 0; s >>= 1) sum += __shfl_xor_sync(0xffffffffu, sum, s);
    float inv = 1.f / sum;

    #pragma unroll
    for (int i = 0; i < 9; i++) {
        int idx = lane + i*32;
        if (idx < SEQP) p[idx] = (idx < SEQ) ? f2tff(vals[i] * inv) : 0.f;
    }
}

// ---------------- host launch ----------------
static void* dsym(const void* symbol) { void* p = nullptr; cudaGetSymbolAddress(&p, symbol); return p; }
static inline dim3 tgrid(int N, int M, int Z) { return dim3((N+TBN-1)/TBN, (M+TBM-1)/TBM, Z); }

extern "C" void kernel_launch(void* const* d_in, const int* in_sizes, int n_in,
                              void* d_out, int out_size)
{
    const float* x   = (const float*)d_in[0];
    const float* gw1 = (const float*)d_in[1];
    const float* gb1 = (const float*)d_in[2];
    const float* gw2 = (const float*)d_in[3];
    const float* gb2 = (const float*)d_in[4];
    const float* Wm[4]; const float* Ue[4]; const float* Se[4]; const float* Ve[4]; const float* bi[4];
    for (int p = 0; p < 4; p++) {
        Wm[p] = (const float*)d_in[5 + p*5 + 0];
        Ue[p] = (const float*)d_in[5 + p*5 + 1];
        Se[p] = (const float*)d_in[5 + p*5 + 2];
        Ve[p] = (const float*)d_in[5 + p*5 + 3];
        bi[p] = (const float*)d_in[5 + p*5 + 4];
    }
    float* out = (float*)d_out;

    int*   idxp   = (int*)dsym(g_idx);
    float* gatesp = (float*)dsym(g_gates);
    float* xr     = (float*)dsym(g_xr);
    float* Wmr    = (float*)dsym(g_Wmr);
    float* Vw     = (float*)dsym(g_Vw);
    float* Uw     = (float*)dsym(g_Uw);
    float* tbuf   = (float*)dsym(g_t);
    float* bq     = (float*)dsym(g_q);
    float* bk     = (float*)dsym(g_k);
    float* bv     = (float*)dsym(g_v);
    float* sc     = (float*)dsym(g_scores);
    float* ctx    = (float*)dsym(g_ctx);

    const long VW_PER = (long)BATCH*32*DIM;
    const long UW_PER = (long)BATCH*DIM*32;
    const long T_PER  = (long)BATCH*SEQ*32;
    const long SCB    = (long)SEQ*SEQP;        // per-(b,h) score block

    // 0) tf32 pre-rounding of GEMM inputs
    round_kernel<<<1184, 256>>>(x, xr, (long)MROWS*DIM);
    for (int p = 0; p < 4; p++)
        round_kernel<<<1184, 256>>>(Wm[p], Wmr + (long)p*DIM*DIM, (long)DIM*DIM);

    // 1) gating (exact fp32 on original x)
    gating_kernel<<<BATCH, 256>>>(x, gw1, gb1, gw2, gb2, idxp, gatesp);

    // 2) fold expert factors (rounded)
    for (int p = 0; p < 4; p++)
        build_uv_kernel<<<BATCH, 256>>>(Ue[p], Se[p], Ve[p], idxp, gatesp,
                                        Vw + p*VW_PER, Uw + p*UW_PER);

    // 3) q,k,v projections
    float* qkv[3] = { bq, bk, bv };
    for (int p = 0; p < 3; p++) {
        // t = x @ Vw^T  (per-b: M=257,N=32,K=1024), rounded output
        tgemm_kernel<true,false,false,true><<<tgrid(32, SEQ, BATCH), 256>>>(
            xr, Vw + p*VW_PER, tbuf + p*T_PER, nullptr,
            SEQ, 32, DIM, DIM, DIM, 32,
            (long)SD, 0, (long)32*DIM, 0, (long)SEQ*32, 0, 1, 1.f);
        // main: out = x @ Wm^T + bias  (M=8224,N=1024,K=1024), unrounded
        tgemm_kernel<true,false,true,false><<<tgrid(DIM, MROWS, 1), 256>>>(
            xr, Wmr + (long)p*DIM*DIM, qkv[p], bi[p],
            MROWS, DIM, DIM, DIM, DIM, DIM,
            0, 0, 0, 0, 0, 0, 1, 1.f);
        // expert: out += t @ Uw^T  (per-b: M=257,N=1024,K=32), rounded (final writer)
        tgemm_kernel<true,true,false,true><<<tgrid(DIM, SEQ, BATCH), 256>>>(
            tbuf + p*T_PER, Uw + p*UW_PER, qkv[p], nullptr,
            SEQ, DIM, 32, 32, 32, DIM,
            (long)SEQ*32, 0, (long)DIM*32, 0, (long)SD, 0, 1, 1.f);
    }

    // 4) scores = SCALE * q @ k^T  batched (b,h): M=N=257, K=64, ldc=SEQP
    tgemm_kernel<true,false,false,false><<<tgrid(SEQ, SEQ, BATCH*NHEAD), 256>>>(
        bq, bk, sc, nullptr,
        SEQ, SEQ, HDIM, DIM, DIM, SEQP,
        (long)SD, (long)HDIM, (long)SD, (long)HDIM,
        (long)NHEAD*SCB, SCB, NHEAD, ATTN_SCALE);

    // 5) softmax (rounds + zero-pads rows to SEQP)
    softmax_kernel<<<(unsigned)((long)BATCH*NHEAD*SEQ/4 + 1), 128>>>(sc);

    // 6) ctx = probs @ v  batched: M=257,N=64,K=SEQP (zero-padded tail)
    tgemm_kernel<false,false,false,true><<<tgrid(HDIM, SEQ, BATCH*NHEAD), 256>>>(
        sc, bv, ctx, nullptr,
        SEQ, HDIM, SEQP, SEQP, DIM, DIM,
        (long)NHEAD*SCB, SCB, (long)SD, (long)HDIM,
        (long)SD, (long)HDIM, NHEAD, 1.f);

    // 7) output projection -> d_out (never rounded)
    {
        int p = 3;
        tgemm_kernel<true,false,false,true><<<tgrid(32, SEQ, BATCH), 256>>>(
            ctx, Vw + p*VW_PER, tbuf + p*T_PER, nullptr,
            SEQ, 32, DIM, DIM, DIM, 32,
            (long)SD, 0, (long)32*DIM, 0, (long)SEQ*32, 0, 1, 1.f);
        tgemm_kernel<true,false,true,false><<<tgrid(DIM, MROWS, 1), 256>>>(
            ctx, Wmr + (long)p*DIM*DIM, out, bi[p],
            MROWS, DIM, DIM, DIM, DIM, DIM,
            0, 0, 0, 0, 0, 0, 1, 1.f);
        tgemm_kernel<true,true,false,false><<<tgrid(DIM, SEQ, BATCH), 256>>>(
            tbuf + p*T_PER, Uw + p*UW_PER, out, nullptr,
            SEQ, DIM, 32, 32, 32, DIM,
            (long)SEQ*32, 0, (long)DIM*32, 0, (long)SD, 0, 1, 1.f);
    }
}

// round 5
// speedup vs baseline: 2.6539x; 1.0912x over previous
#include <cuda_runtime.h>
#include <math.h>
#include <stdint.h>

// ---------------- problem constants ----------------
#define BATCH 32
#define SEQ   257
#define SEQP  288
#define DIM   1024
#define QKVD  3072
#define NHEAD 16
#define HDIM  64
#define NEXP  8
#define TOPK  2
#define RANK  16
#define GHID  256
#define SD    (SEQ*DIM)
#define MROWS (BATCH*SEQ)        // 8224
#define ATTN_SCALE 0.125f

// ---------------- static device scratch ----------------
__device__ int   g_idx[BATCH*TOPK];
__device__ float g_gates[BATCH*TOPK];
__device__ float g_xr [MROWS*DIM];
__device__ float g_Wmr[4ll*DIM*DIM];             // rows 0..3071 = concat(Wq,Wk,Wv); 3072..4095 = Wo
__device__ float g_bcat[QKVD];
__device__ float g_Vw[4ll*BATCH*32*DIM];
__device__ float g_Uw[4ll*BATCH*DIM*32];
__device__ float g_t [4ll*BATCH*SEQ*32];
__device__ float g_qkv[(long)MROWS*QKVD + 32*QKVD];   // fused q|k|v, padded for k-tail overreads
__device__ float g_scores[(long)BATCH*NHEAD*SEQ*SEQP];
__device__ float g_ctx[MROWS*DIM];

__device__ __forceinline__ uint32_t f2tf(float x) {
    uint32_t r; asm("cvt.rna.tf32.f32 %0, %1;" : "=r"(r) : "f"(x)); return r;
}
__device__ __forceinline__ float f2tff(float x) { return __uint_as_float(f2tf(x)); }

// ---------------- tf32 rounding copy ----------------
__global__ void round_kernel(const float* __restrict__ src, float* __restrict__ dst, long n)
{
    long i = (long)blockIdx.x * blockDim.x + threadIdx.x;
    long stride = (long)gridDim.x * blockDim.x;
    for (; i < n; i += stride) dst[i] = f2tff(src[i]);
}

__global__ void concat_bias_kernel(const float* __restrict__ b0, const float* __restrict__ b1,
                                   const float* __restrict__ b2, float* __restrict__ dst)
{
    int i = blockIdx.x * 256 + threadIdx.x;
    if (i < DIM) dst[i] = b0[i];
    else if (i < 2*DIM) dst[i] = b1[i - DIM];
    else if (i < 3*DIM) dst[i] = b2[i - 2*DIM];
}

// ---------------- gating (exact fp32) ----------------
__global__ void gating_kernel(const float* __restrict__ x,
                              const float* __restrict__ gw1, const float* __restrict__ gb1,
                              const float* __restrict__ gw2, const float* __restrict__ gb2,
                              int* __restrict__ idx, float* __restrict__ gates)
{
    int b = blockIdx.x;
    int tid = threadIdx.x;
    __shared__ float pooled[DIM];
    __shared__ float h[GHID];
    __shared__ float logits[NEXP];

    const float* xb = x + (long)b * SD;
    for (int d = tid; d < DIM; d += 256) {
        float s = 0.f;
        for (int t = 0; t < SEQ; t++) s += xb[(long)t*DIM + d];
        pooled[d] = s * (1.0f / SEQ);
    }
    __syncthreads();
    {
        float s = gb1[tid];
        const float* w = gw1 + (long)tid * DIM;
        #pragma unroll 8
        for (int d = 0; d < DIM; d++) s += pooled[d] * w[d];
        h[tid] = fmaxf(s, 0.f);
    }
    __syncthreads();
    if (tid < NEXP) {
        float s = gb2[tid];
        const float* w = gw2 + (long)tid * GHID;
        for (int g = 0; g < GHID; g++) s += h[g] * w[g];
        logits[tid] = s;
    }
    __syncthreads();
    if (tid == 0) {
        int i1 = 0; float v1 = logits[0];
        for (int e = 1; e < NEXP; e++) if (logits[e] > v1) { v1 = logits[e]; i1 = e; }
        int i2 = -1; float v2 = -3.0e38f;
        for (int e = 0; e < NEXP; e++) if (e != i1 && logits[e] > v2) { v2 = logits[e]; i2 = e; }
        float e2 = expf(v2 - v1);
        float inv = 1.f / (1.f + e2);
        idx[b*2] = i1; idx[b*2+1] = i2;
        gates[b*2] = inv; gates[b*2+1] = e2 * inv;
    }
}

// ---------------- fold S into V, gates into U ----------------
__global__ void build_uv_kernel(const float* __restrict__ U, const float* __restrict__ Sg,
                                const float* __restrict__ V,
                                const int* __restrict__ idx, const float* __restrict__ gates,
                                float* __restrict__ Vw, float* __restrict__ Uw)
{
    int b = blockIdx.x;
    int tid = threadIdx.x;
    int e0 = idx[b*2], e1 = idx[b*2+1];
    float g0 = gates[b*2], g1 = gates[b*2+1];
    float* vw = Vw + (long)b * 32 * DIM;
    float* uw = Uw + (long)b * DIM * 32;

    for (int i = tid; i < 32*DIM; i += 256) {
        int j = i >> 10, d = i & (DIM-1);
        int k = j >> 4, r = j & 15;
        int e = k ? e1 : e0;
        vw[i] = f2tff(Sg[e*RANK + r] * V[((long)e*RANK + r)*DIM + d]);
    }
    for (int i = tid; i < DIM*32; i += 256) {
        int n = i >> 5, j = i & 31;
        int k = j >> 4, r = j & 15;
        int e = k ? e1 : e0;
        float g = k ? g1 : g0;
        uw[i] = f2tff(g * U[((long)e*DIM + n)*RANK + r]);
    }
}

// ---------------- MMA primitive ----------------
__device__ __forceinline__ void mma_tf32(float c[4], const uint32_t a[4], const uint32_t b[2]) {
    asm volatile(
        "mma.sync.aligned.m16n8k8.row.col.f32.tf32.tf32.f32 "
        "{%0,%1,%2,%3}, {%4,%5,%6,%7}, {%8,%9}, {%0,%1,%2,%3};"
        : "+f"(c[0]), "+f"(c[1]), "+f"(c[2]), "+f"(c[3])
        : "r"(a[0]), "r"(a[1]), "r"(a[2]), "r"(a[3]), "r"(b[0]), "r"(b[1]));
}
__device__ __forceinline__ int a_off(int kk, int mt, int lane) { return ((kk*8 + mt)*32 + lane)*4; }
__device__ __forceinline__ int b_off(int kk, int nt, int lane) { return ((kk*8 + nt)*32 + lane)*2; }
__device__ __forceinline__ int bw_off(int kk, int np, int lane) { return ((kk*8 + np)*32 + lane)*4; }

// ==================== WIDE GEMM: C[M,N] = A[M,1024] @ B[N,1024]^T + bias ===========
// TBM=128, TBN=128, TBK=32, 8 warps, warp tile 32x64, double-buffered, 1 sync/iter.
// lda = DIM (1024). N % 128 == 0. Row predication on M only.
__global__ __launch_bounds__(256)
void tgemm_wide(const float* __restrict__ A, const float* __restrict__ B,
                const float* __restrict__ bias, float* __restrict__ C,
                int M, int N, int ldc)
{
    extern __shared__ __align__(16) float sw[];
    // layout (floats): A0 @0, B0 @4096, A1 @8192, B1 @12288  (each 16KB)
    int m0 = blockIdx.y * 128, n0 = blockIdx.x * 128;

    int tid = threadIdx.x;
    int warp = tid >> 5, lane = tid & 31;
    int mt0 = (warp & 3) * 2;     // 2 mtiles (32 rows)
    int np0 = (warp >> 2) * 4;    // 4 n-pairs (8 ntiles = 64 cols)
    int g = lane >> 2, tg = lane & 3;

    float acc[2][8][4] = {};
    float4 ar[4], br[4];

    const int KB = DIM / 32;   // 32

    auto load_regs = [&](int kb) {
        int k0 = kb * 32;
        #pragma unroll
        for (int i = 0; i < 4; i++) {
            int f4 = i*256 + tid;
            int row = f4 >> 3, c4 = f4 & 7;
            int gm = m0 + row;
            if (gm < M) ar[i] = *(const float4*)(A + (long)gm*DIM + k0 + c4*4);
            else        ar[i] = make_float4(0.f,0.f,0.f,0.f);
        }
        #pragma unroll
        for (int i = 0; i < 4; i++) {
            int f4 = i*256 + tid;
            int row = f4 >> 3, c4 = f4 & 7;
            br[i] = *(const float4*)(B + (long)(n0 + row)*DIM + k0 + c4*4);
        }
    };

    auto sts = [&](int s) {
        float* As = sw + s*8192;
        float* Bs = sw + s*8192 + 4096;
        #pragma unroll
        for (int i = 0; i < 4; i++) {
            int f4 = i*256 + tid;
            int row = f4 >> 3, c4 = f4 & 7;
            int kk = c4 >> 1;
            int slot = ((row & 15) >> 3) + 2*(c4 & 1);
            int base = a_off(kk, row >> 4, (row & 7)*4) + slot;
            As[base +  0] = ar[i].x;
            As[base +  4] = ar[i].y;
            As[base +  8] = ar[i].z;
            As[base + 12] = ar[i].w;
        }
        #pragma unroll
        for (int i = 0; i < 4; i++) {
            int f4 = i*256 + tid;
            int row = f4 >> 3, c4 = f4 & 7;
            int nt = row >> 3, gg = row & 7;
            int kk = c4 >> 1;
            int slot = (nt & 1)*2 + (c4 & 1);
            int base = bw_off(kk, nt >> 1, gg*4) + slot;
            Bs[base +  0] = br[i].x;
            Bs[base +  4] = br[i].y;
            Bs[base +  8] = br[i].z;
            Bs[base + 12] = br[i].w;
        }
    };

    auto compute = [&](int s) {
        const float* As = sw + s*8192;
        const float* Bs = sw + s*8192 + 4096;
        #pragma unroll
        for (int kk = 0; kk < 4; kk++) {
            float4 af[2];
            af[0] = *(const float4*)&As[a_off(kk, mt0    , lane)];
            af[1] = *(const float4*)&As[a_off(kk, mt0 + 1, lane)];
            float4 bp[4];
            #pragma unroll
            for (int t = 0; t < 4; t++)
                bp[t] = *(const float4*)&Bs[bw_off(kk, np0 + t, lane)];
            #pragma unroll
            for (int i = 0; i < 2; i++) {
                uint32_t a[4] = { __float_as_uint(af[i].x), __float_as_uint(af[i].y),
                                  __float_as_uint(af[i].z), __float_as_uint(af[i].w) };
                #pragma unroll
                for (int t = 0; t < 4; t++) {
                    uint32_t b0[2] = { __float_as_uint(bp[t].x), __float_as_uint(bp[t].y) };
                    uint32_t b1[2] = { __float_as_uint(bp[t].z), __float_as_uint(bp[t].w) };
                    mma_tf32(acc[i][2*t    ], a, b0);
                    mma_tf32(acc[i][2*t + 1], a, b1);
                }
            }
        }
    };

    load_regs(0);
    sts(0);
    __syncthreads();

    for (int kb = 0; kb < KB; kb++) {
        int s = kb & 1;
        if (kb + 1 < KB) load_regs(kb + 1);
        compute(s);
        if (kb + 1 < KB) {
            sts(s ^ 1);
            __syncthreads();
        }
    }

    // epilogue
    #pragma unroll
    for (int i = 0; i < 2; i++) {
        #pragma unroll
        for (int rs = 0; rs < 2; rs++) {
            int gm = m0 + (mt0 + i)*16 + g + rs*8;
            if (gm >= M) continue;
            #pragma unroll
            for (int j = 0; j < 8; j++) {
                int gn = n0 + (np0*2 + j)*8 + tg*2;
                long off = (long)gm*ldc + gn;
                C[off    ] = acc[i][j][rs*2+0] + bias[gn];
                C[off + 1] = acc[i][j][rs*2+1] + bias[gn+1];
            }
        }
    }
}

// ==================== general batched GEMM (small shapes) ====================
#define TBM 128
#define TBN 64
#define TBK 32

template<bool BT, bool ACC, bool BIAS, bool ROUND>
__global__ __launch_bounds__(256, 2)
void tgemm_kernel(const float* __restrict__ A, const float* __restrict__ B,
                  float* __restrict__ C, const float* __restrict__ bias,
                  int M, int N, int K, int lda, int ldb, int ldc,
                  long sA1, long sA2, long sB1, long sB2, long sC1, long sC2,
                  int zdiv, float alpha)
{
    int z = blockIdx.z;
    long zq = z / zdiv, zr = z % zdiv;
    A += zq*sA1 + zr*sA2;
    B += zq*sB1 + zr*sB2;
    C += zq*sC1 + zr*sC2;

    int m0 = blockIdx.y * TBM, n0 = blockIdx.x * TBN;
    __shared__ __align__(16) float As[4*8*32*4];
    __shared__ __align__(16) float Bs[4*8*32*2];

    int tid = threadIdx.x;
    int warp = tid >> 5, lane = tid & 31;
    int mt0 = (warp & 3) * 2;
    int nt0 = (warp >> 2) * 4;
    int g = lane >> 2, tg = lane & 3;

    float acc[2][4][4] = {};
    float4 ar[4];
    float4 br[2];

    const int KB = K / TBK;

    auto load_regs = [&](int kb) {
        int k0 = kb * TBK;
        #pragma unroll
        for (int i = 0; i < 4; i++) {
            int f4 = i*256 + tid;
            int m = f4 >> 3, k4 = f4 & 7;
            int gm = m0 + m;
            if (gm < M) ar[i] = *(const float4*)(A + (long)gm*lda + k0 + k4*4);
            else        ar[i] = make_float4(0.f,0.f,0.f,0.f);
        }
        if (BT) {
            #pragma unroll
            for (int i = 0; i < 2; i++) {
                int f4 = i*256 + tid;
                int n = f4 >> 3, k4 = f4 & 7;
                int gn = n0 + n;
                if (gn < N) br[i] = *(const float4*)(B + (long)gn*ldb + k0 + k4*4);
                else        br[i] = make_float4(0.f,0.f,0.f,0.f);
            }
        } else {
            #pragma unroll
            for (int i = 0; i < 2; i++) {
                int f4 = i*256 + tid;
                int k = f4 >> 4, n4 = f4 & 15;
                int gn = n0 + n4*4;
                if (gn < N) br[i] = *(const float4*)(B + (long)(k0 + k)*ldb + gn);
                else        br[i] = make_float4(0.f,0.f,0.f,0.f);
            }
        }
    };

    auto sts = [&]() {
        #pragma unroll
        for (int i = 0; i < 4; i++) {
            int f4 = i*256 + tid;
            int m = f4 >> 3, k4 = f4 & 7;
            int kk = k4 >> 1;
            int slot = ((m & 15) >> 3) + 2*(k4 & 1);
            int base = a_off(kk, m >> 4, (m & 7)*4) + slot;
            As[base +  0] = ar[i].x;
            As[base +  4] = ar[i].y;
            As[base +  8] = ar[i].z;
            As[base + 12] = ar[i].w;
        }
        if (BT) {
            #pragma unroll
            for (int i = 0; i < 2; i++) {
                int f4 = i*256 + tid;
                int n = f4 >> 3, k4 = f4 & 7;
                int kk = k4 >> 1;
                int slot = k4 & 1;
                int base = b_off(kk, n >> 3, (n & 7)*4) + slot;
                Bs[base + 0] = br[i].x;
                Bs[base + 2] = br[i].y;
                Bs[base + 4] = br[i].z;
                Bs[base + 6] = br[i].w;
            }
        } else {
            #pragma unroll
            for (int i = 0; i < 2; i++) {
                int f4 = i*256 + tid;
                int k = f4 >> 4, n4 = f4 & 15;
                int kk = k >> 3, k8 = k & 7;
                int slot = k8 >> 2;
                int nt = n4 >> 1;
                int lanebase = ((n4 & 1)*4)*4 + (k8 & 3);
                int base = b_off(kk, nt, 0) + slot;
                Bs[base + (lanebase + 0*4)*2] = br[i].x;
                Bs[base + (lanebase + 1*4)*2] = br[i].y;
                Bs[base + (lanebase + 2*4)*2] = br[i].z;
                Bs[base + (lanebase + 3*4)*2] = br[i].w;
            }
        }
    };

    load_regs(0);
    sts();
    __syncthreads();

    for (int kb = 0; kb < KB; kb++) {
        if (kb + 1 < KB) load_regs(kb + 1);

        #pragma unroll
        for (int kk = 0; kk < 4; kk++) {
            float4 af[2];
            af[0] = *(const float4*)&As[a_off(kk, mt0    , lane)];
            af[1] = *(const float4*)&As[a_off(kk, mt0 + 1, lane)];
            float2 bf[4];
            #pragma unroll
            for (int j = 0; j < 4; j++)
                bf[j] = *(const float2*)&Bs[b_off(kk, nt0 + j, lane)];
            #pragma unroll
            for (int i = 0; i < 2; i++) {
                uint32_t a[4] = { __float_as_uint(af[i].x), __float_as_uint(af[i].y),
                                  __float_as_uint(af[i].z), __float_as_uint(af[i].w) };
                #pragma unroll
                for (int j = 0; j < 4; j++) {
                    uint32_t b2[2] = { __float_as_uint(bf[j].x), __float_as_uint(bf[j].y) };
                    mma_tf32(acc[i][j], a, b2);
                }
            }
        }

        if (kb + 1 < KB) {
            __syncthreads();
            sts();
            __syncthreads();
        }
    }

    int wm = mt0 * 16, wn = nt0 * 8;
    #pragma unroll
    for (int i = 0; i < 2; i++) {
        #pragma unroll
        for (int rs = 0; rs < 2; rs++) {
            int gm = m0 + wm + i*16 + g + rs*8;
            if (gm >= M) continue;
            #pragma unroll
            for (int j = 0; j < 4; j++) {
                int gn = n0 + wn + j*8 + tg*2;
                #pragma unroll
                for (int c = 0; c < 2; c++) {
                    if (gn + c >= N) continue;
                    long off = (long)gm*ldc + gn + c;
                    float v = acc[i][j][rs*2+c] * alpha;
                    if (BIAS) v += bias[gn+c];
                    if (ACC)  v += C[off];
                    if (ROUND) v = f2tff(v);
                    C[off] = v;
                }
            }
        }
    }
}

// ---------------- softmax ----------------
__global__ void softmax_kernel(float* __restrict__ scores)
{
    int warp = threadIdx.x >> 5, lane = threadIdx.x & 31;
    long row = (long)blockIdx.x * 4 + warp;
    float* p = scores + row * SEQP;

    float vals[9];
    float m = -3.0e38f;
    #pragma unroll
    for (int i = 0; i < 9; i++) {
        int idx = lane + i*32;
        vals[i] = (idx < SEQ) ? p[idx] : -3.0e38f;
        m = fmaxf(m, vals[i]);
    }
    #pragma unroll
    for (int s = 16; s > 0; s >>= 1) m = fmaxf(m, __shfl_xor_sync(0xffffffffu, m, s));

    float sum = 0.f;
    #pragma unroll
    for (int i = 0; i < 9; i++) {
        int idx = lane + i*32;
        float e = (idx < SEQ) ? expf(vals[i] - m) : 0.f;
        vals[i] = e;
        sum += e;
    }
    #pragma unroll
    for (int s = 16; s > 0; s >>= 1) sum += __shfl_xor_sync(0xffffffffu, sum, s);
    float inv = 1.f / sum;

    #pragma unroll
    for (int i = 0; i < 9; i++) {
        int idx = lane + i*32;
        if (idx < SEQP) p[idx] = (idx < SEQ) ? f2tff(vals[i] * inv) : 0.f;
    }
}

// ---------------- host launch ----------------
static void* dsym(const void* symbol) { void* p = nullptr; cudaGetSymbolAddress(&p, symbol); return p; }
static inline dim3 tgrid(int N, int M, int Z) { return dim3((N+TBN-1)/TBN, (M+TBM-1)/TBM, Z); }
#define WIDE_SMEM 65536

extern "C" void kernel_launch(void* const* d_in, const int* in_sizes, int n_in,
                              void* d_out, int out_size)
{
    const float* x   = (const float*)d_in[0];
    const float* gw1 = (const float*)d_in[1];
    const float* gb1 = (const float*)d_in[2];
    const float* gw2 = (const float*)d_in[3];
    const float* gb2 = (const float*)d_in[4];
    const float* Wm[4]; const float* Ue[4]; const float* Se[4]; const float* Ve[4]; const float* bi[4];
    for (int p = 0; p < 4; p++) {
        Wm[p] = (const float*)d_in[5 + p*5 + 0];
        Ue[p] = (const float*)d_in[5 + p*5 + 1];
        Se[p] = (const float*)d_in[5 + p*5 + 2];
        Ve[p] = (const float*)d_in[5 + p*5 + 3];
        bi[p] = (const float*)d_in[5 + p*5 + 4];
    }
    float* out = (float*)d_out;

    int*   idxp   = (int*)dsym(g_idx);
    float* gatesp = (float*)dsym(g_gates);
    float* xr     = (float*)dsym(g_xr);
    float* Wmr    = (float*)dsym(g_Wmr);
    float* bcat   = (float*)dsym(g_bcat);
    float* Vw     = (float*)dsym(g_Vw);
    float* Uw     = (float*)dsym(g_Uw);
    float* tbuf   = (float*)dsym(g_t);
    float* qkv    = (float*)dsym(g_qkv);
    float* sc     = (float*)dsym(g_scores);
    float* ctx    = (float*)dsym(g_ctx);

    const long VW_PER = (long)BATCH*32*DIM;
    const long UW_PER = (long)BATCH*DIM*32;
    const long T_PER  = (long)BATCH*SEQ*32;
    const long SCB    = (long)SEQ*SEQP;

    cudaFuncSetAttribute(tgemm_wide, cudaFuncAttributeMaxDynamicSharedMemorySize, WIDE_SMEM);

    // 0) tf32 pre-rounding (Wmr rows 0..3071 = Wq|Wk|Wv, 3072..4095 = Wo) + bias concat
    round_kernel<<<1184, 256>>>(x, xr, (long)MROWS*DIM);
    for (int p = 0; p < 4; p++)
        round_kernel<<<1184, 256>>>(Wm[p], Wmr + (long)p*DIM*DIM, (long)DIM*DIM);
    concat_bias_kernel<<<12, 256>>>(bi[0], bi[1], bi[2], bcat);

    // 1) gating
    gating_kernel<<<BATCH, 256>>>(x, gw1, gb1, gw2, gb2, idxp, gatesp);

    // 2) fold expert factors
    for (int p = 0; p < 4; p++)
        build_uv_kernel<<<BATCH, 256>>>(Ue[p], Se[p], Ve[p], idxp, gatesp,
                                        Vw + p*VW_PER, Uw + p*UW_PER);

    // 3a) fused main projection: qkv = x @ [Wq|Wk|Wv]^T + bcat   (M=8224, N=3072)
    tgemm_wide<<<dim3(QKVD/128, (MROWS + 127)/128), 256, WIDE_SMEM>>>(
        xr, Wmr, bcat, qkv, MROWS, QKVD, QKVD);

    // 3b) expert low-rank path per projection
    for (int p = 0; p < 3; p++) {
        tgemm_kernel<true,false,false,true><<<tgrid(32, SEQ, BATCH), 256>>>(
            xr, Vw + p*VW_PER, tbuf + p*T_PER, nullptr,
            SEQ, 32, DIM, DIM, DIM, 32,
            (long)SD, 0, (long)32*DIM, 0, (long)SEQ*32, 0, 1, 1.f);
        tgemm_kernel<true,true,false,true><<<tgrid(DIM, SEQ, BATCH), 256>>>(
            tbuf + p*T_PER, Uw + p*UW_PER, qkv + p*DIM, nullptr,
            SEQ, DIM, 32, 32, 32, QKVD,
            (long)SEQ*32, 0, (long)DIM*32, 0, (long)SEQ*QKVD, 0, 1, 1.f);
    }

    // 4) scores = SCALE * q @ k^T  batched (b,h): M=N=257, K=64
    tgemm_kernel<true,false,false,false><<<tgrid(SEQ, SEQ, BATCH*NHEAD), 256>>>(
        qkv, qkv + DIM, sc, nullptr,
        SEQ, SEQ, HDIM, QKVD, QKVD, SEQP,
        (long)SEQ*QKVD, (long)HDIM, (long)SEQ*QKVD, (long)HDIM,
        (long)NHEAD*SCB, SCB, NHEAD, ATTN_SCALE);

    // 5) softmax
    softmax_kernel<<<(unsigned)((long)BATCH*NHEAD*SEQ/4 + 1), 128>>>(sc);

    // 6) ctx = probs @ v
    tgemm_kernel<false,false,false,true><<<tgrid(HDIM, SEQ, BATCH*NHEAD), 256>>>(
        sc, qkv + 2*DIM, ctx, nullptr,
        SEQ, HDIM, SEQP, SEQP, QKVD, DIM,
        (long)NHEAD*SCB, SCB, (long)SEQ*QKVD, (long)HDIM,
        (long)SD, (long)HDIM, NHEAD, 1.f);

    // 7) output projection -> d_out
    {
        int p = 3;
        tgemm_kernel<true,false,false,true><<<tgrid(32, SEQ, BATCH), 256>>>(
            ctx, Vw + p*VW_PER, tbuf + p*T_PER, nullptr,
            SEQ, 32, DIM, DIM, DIM, 32,
            (long)SD, 0, (long)32*DIM, 0, (long)SEQ*32, 0, 1, 1.f);
        tgemm_wide<<<dim3(DIM/128, (MROWS + 127)/128), 256, WIDE_SMEM>>>(
            ctx, Wmr + 3ll*DIM*DIM, bi[3], out, MROWS, DIM, DIM);
        tgemm_kernel<true,true,false,false><<<tgrid(DIM, SEQ, BATCH), 256>>>(
            tbuf + p*T_PER, Uw + p*UW_PER, out, nullptr,
            SEQ, DIM, 32, 32, 32, DIM,
            (long)SEQ*32, 0, (long)DIM*32, 0, (long)SD, 0, 1, 1.f);
    }
}

// round 6
// speedup vs baseline: 2.9394x; 1.1076x over previous
#include <cuda_runtime.h>
#include <math.h>
#include <stdint.h>

// ---------------- problem constants ----------------
#define BATCH 32
#define SEQ   257
#define SEQP  288
#define DIM   1024
#define QKVD  3072
#define NHEAD 16
#define HDIM  64
#define NEXP  8
#define TOPK  2
#define RANK  16
#define GHID  256
#define SD    (SEQ*DIM)
#define MROWS (BATCH*SEQ)        // 8224
#define ATTN_SCALE 0.125f

// ---------------- static device scratch ----------------
__device__ int   g_idx[BATCH*TOPK];
__device__ float g_gates[BATCH*TOPK];
__device__ float g_pooled[BATCH*DIM];
__device__ float g_xr [MROWS*DIM];
__device__ float g_Wmr[4ll*DIM*DIM];             // rows 0..3071 = Wq|Wk|Wv; 3072..4095 = Wo
__device__ float g_bcat[QKVD];
__device__ float g_Vw[4ll*BATCH*32*DIM];
__device__ float g_Uw[4ll*BATCH*DIM*32];
__device__ float g_t [4ll*BATCH*SEQ*32];
__device__ float g_qkv[(long)MROWS*QKVD + 32*QKVD];
__device__ float g_scores[(long)BATCH*NHEAD*SEQ*SEQP];
__device__ float g_ctx[MROWS*DIM];

__device__ __forceinline__ uint32_t f2tf(float x) {
    uint32_t r; asm("cvt.rna.tf32.f32 %0, %1;" : "=r"(r) : "f"(x)); return r;
}
__device__ __forceinline__ float f2tff(float x) { return __uint_as_float(f2tf(x)); }

// ---------------- rounding kernels ----------------
__global__ void round_kernel(const float* __restrict__ src, float* __restrict__ dst, long n)
{
    long i = (long)blockIdx.x * blockDim.x + threadIdx.x;
    long stride = (long)gridDim.x * blockDim.x;
    for (; i < n; i += stride) dst[i] = f2tff(src[i]);
}

__global__ void round4_kernel(const float* __restrict__ w0, const float* __restrict__ w1,
                              const float* __restrict__ w2, const float* __restrict__ w3,
                              float* __restrict__ dst)
{
    const long NW = (long)DIM*DIM;
    long i = (long)blockIdx.x * blockDim.x + threadIdx.x;
    long stride = (long)gridDim.x * blockDim.x;
    for (; i < 4*NW; i += stride) {
        int p = (int)(i / NW); long j = i - (long)p*NW;
        const float* w = (p == 0) ? w0 : (p == 1) ? w1 : (p == 2) ? w2 : w3;
        dst[i] = f2tff(w[j]);
    }
}

__global__ void concat_bias_kernel(const float* __restrict__ b0, const float* __restrict__ b1,
                                   const float* __restrict__ b2, float* __restrict__ dst)
{
    int i = blockIdx.x * 256 + threadIdx.x;
    if (i < DIM) dst[i] = b0[i];
    else if (i < 2*DIM) dst[i] = b1[i - DIM];
    else if (i < 3*DIM) dst[i] = b2[i - 2*DIM];
}

// ---------------- pooling: grid (8, 32), block 256 ----------------
__global__ void pool_kernel(const float* __restrict__ x, float* __restrict__ pooled)
{
    int b = blockIdx.y;
    int d = blockIdx.x * 128 + (threadIdx.x & 127);
    int half = threadIdx.x >> 7;
    const float* xb = x + (long)b*SD + d;
    int t0 = half * 129;
    int t1 = half ? SEQ : 129;
    float s = 0.f;
    for (int t = t0; t < t1; t++) s += xb[(long)t*DIM];
    __shared__ float red[256];
    red[threadIdx.x] = s;
    __syncthreads();
    if (half == 0)
        pooled[b*DIM + d] = (red[threadIdx.x] + red[threadIdx.x + 128]) * (1.0f / SEQ);
}

// ---------------- gating MLP (exact fp32) ----------------
__global__ void gating_kernel(const float* __restrict__ pooled,
                              const float* __restrict__ gw1, const float* __restrict__ gb1,
                              const float* __restrict__ gw2, const float* __restrict__ gb2,
                              int* __restrict__ idx, float* __restrict__ gates)
{
    int b = blockIdx.x;
    int tid = threadIdx.x;
    __shared__ float pl[DIM];
    __shared__ float h[GHID];
    __shared__ float logits[NEXP];

    for (int d = tid; d < DIM; d += 256) pl[d] = pooled[b*DIM + d];
    __syncthreads();
    {
        float s = gb1[tid];
        const float* w = gw1 + (long)tid * DIM;
        #pragma unroll 8
        for (int d = 0; d < DIM; d++) s += pl[d] * w[d];
        h[tid] = fmaxf(s, 0.f);
    }
    __syncthreads();
    if (tid < NEXP) {
        float s = gb2[tid];
        const float* w = gw2 + (long)tid * GHID;
        for (int g = 0; g < GHID; g++) s += h[g] * w[g];
        logits[tid] = s;
    }
    __syncthreads();
    if (tid == 0) {
        int i1 = 0; float v1 = logits[0];
        for (int e = 1; e < NEXP; e++) if (logits[e] > v1) { v1 = logits[e]; i1 = e; }
        int i2 = -1; float v2 = -3.0e38f;
        for (int e = 0; e < NEXP; e++) if (e != i1 && logits[e] > v2) { v2 = logits[e]; i2 = e; }
        float e2 = expf(v2 - v1);
        float inv = 1.f / (1.f + e2);
        idx[b*2] = i1; idx[b*2+1] = i2;
        gates[b*2] = inv; gates[b*2+1] = e2 * inv;
    }
}

// ---------------- fused fold: grid 128 blocks, blockIdx = p*32 + b ----------------
__global__ void build_uv_kernel(const float* __restrict__ U0, const float* __restrict__ U1,
                                const float* __restrict__ U2, const float* __restrict__ U3,
                                const float* __restrict__ S0, const float* __restrict__ S1,
                                const float* __restrict__ S2, const float* __restrict__ S3,
                                const float* __restrict__ V0, const float* __restrict__ V1,
                                const float* __restrict__ V2, const float* __restrict__ V3,
                                const int* __restrict__ idx, const float* __restrict__ gates,
                                float* __restrict__ VwAll, float* __restrict__ UwAll)
{
    int p = blockIdx.x >> 5, b = blockIdx.x & 31;
    const float* U = (p == 0) ? U0 : (p == 1) ? U1 : (p == 2) ? U2 : U3;
    const float* Sg = (p == 0) ? S0 : (p == 1) ? S1 : (p == 2) ? S2 : S3;
    const float* V = (p == 0) ? V0 : (p == 1) ? V1 : (p == 2) ? V2 : V3;
    int tid = threadIdx.x;
    int e0 = idx[b*2], e1 = idx[b*2+1];
    float g0 = gates[b*2], g1 = gates[b*2+1];
    float* vw = VwAll + ((long)p*BATCH + b) * 32 * DIM;
    float* uw = UwAll + ((long)p*BATCH + b) * DIM * 32;

    for (int i = tid; i < 32*DIM; i += 256) {
        int j = i >> 10, d = i & (DIM-1);
        int k = j >> 4, r = j & 15;
        int e = k ? e1 : e0;
        vw[i] = f2tff(Sg[e*RANK + r] * V[((long)e*RANK + r)*DIM + d]);
    }
    for (int i = tid; i < DIM*32; i += 256) {
        int n = i >> 5, j = i & 31;
        int k = j >> 4, r = j & 15;
        int e = k ? e1 : e0;
        float g = k ? g1 : g0;
        uw[i] = f2tff(g * U[((long)e*DIM + n)*RANK + r]);
    }
}

// ---------------- MMA primitive ----------------
__device__ __forceinline__ void mma_tf32(float c[4], const uint32_t a[4], const uint32_t b[2]) {
    asm volatile(
        "mma.sync.aligned.m16n8k8.row.col.f32.tf32.tf32.f32 "
        "{%0,%1,%2,%3}, {%4,%5,%6,%7}, {%8,%9}, {%0,%1,%2,%3};"
        : "+f"(c[0]), "+f"(c[1]), "+f"(c[2]), "+f"(c[3])
        : "r"(a[0]), "r"(a[1]), "r"(a[2]), "r"(a[3]), "r"(b[0]), "r"(b[1]));
}
__device__ __forceinline__ int a_off(int kk, int mt, int lane) { return ((kk*8 + mt)*32 + lane)*4; }
__device__ __forceinline__ int b_off(int kk, int nt, int lane) { return ((kk*8 + nt)*32 + lane)*2; }
__device__ __forceinline__ int bw_off(int kk, int np, int lane) { return ((kk*8 + np)*32 + lane)*4; }

// ==================== WIDE GEMM: C[M,N] = A[M,1024] @ B[N,1024]^T + bias ===========
__global__ __launch_bounds__(256)
void tgemm_wide(const float* __restrict__ A, const float* __restrict__ B,
                const float* __restrict__ bias, float* __restrict__ C,
                int M, int N, int ldc)
{
    extern __shared__ __align__(16) float sw[];
    int m0 = blockIdx.y * 128, n0 = blockIdx.x * 128;

    int tid = threadIdx.x;
    int warp = tid >> 5, lane = tid & 31;
    int mt0 = (warp & 3) * 2;
    int np0 = (warp >> 2) * 4;
    int g = lane >> 2, tg = lane & 3;

    float acc[2][8][4] = {};
    float4 ar[4], br[4];

    const int KB = DIM / 32;

    auto load_regs = [&](int kb) {
        int k0 = kb * 32;
        #pragma unroll
        for (int i = 0; i < 4; i++) {
            int f4 = i*256 + tid;
            int row = f4 >> 3, c4 = f4 & 7;
            int gm = m0 + row;
            if (gm < M) ar[i] = *(const float4*)(A + (long)gm*DIM + k0 + c4*4);
            else        ar[i] = make_float4(0.f,0.f,0.f,0.f);
        }
        #pragma unroll
        for (int i = 0; i < 4; i++) {
            int f4 = i*256 + tid;
            int row = f4 >> 3, c4 = f4 & 7;
            br[i] = *(const float4*)(B + (long)(n0 + row)*DIM + k0 + c4*4);
        }
    };

    auto sts = [&](int s) {
        float* As = sw + s*8192;
        float* Bs = sw + s*8192 + 4096;
        #pragma unroll
        for (int i = 0; i < 4; i++) {
            int f4 = i*256 + tid;
            int row = f4 >> 3, c4 = f4 & 7;
            int kk = c4 >> 1;
            int slot = ((row & 15) >> 3) + 2*(c4 & 1);
            int base = a_off(kk, row >> 4, (row & 7)*4) + slot;
            As[base +  0] = ar[i].x;
            As[base +  4] = ar[i].y;
            As[base +  8] = ar[i].z;
            As[base + 12] = ar[i].w;
        }
        #pragma unroll
        for (int i = 0; i < 4; i++) {
            int f4 = i*256 + tid;
            int row = f4 >> 3, c4 = f4 & 7;
            int nt = row >> 3, gg = row & 7;
            int kk = c4 >> 1;
            int slot = (nt & 1)*2 + (c4 & 1);
            int base = bw_off(kk, nt >> 1, gg*4) + slot;
            Bs[base +  0] = br[i].x;
            Bs[base +  4] = br[i].y;
            Bs[base +  8] = br[i].z;
            Bs[base + 12] = br[i].w;
        }
    };

    auto compute = [&](int s) {
        const float* As = sw + s*8192;
        const float* Bs = sw + s*8192 + 4096;
        #pragma unroll
        for (int kk = 0; kk < 4; kk++) {
            float4 af[2];
            af[0] = *(const float4*)&As[a_off(kk, mt0    , lane)];
            af[1] = *(const float4*)&As[a_off(kk, mt0 + 1, lane)];
            float4 bp[4];
            #pragma unroll
            for (int t = 0; t < 4; t++)
                bp[t] = *(const float4*)&Bs[bw_off(kk, np0 + t, lane)];
            #pragma unroll
            for (int i = 0; i < 2; i++) {
                uint32_t a[4] = { __float_as_uint(af[i].x), __float_as_uint(af[i].y),
                                  __float_as_uint(af[i].z), __float_as_uint(af[i].w) };
                #pragma unroll
                for (int t = 0; t < 4; t++) {
                    uint32_t b0[2] = { __float_as_uint(bp[t].x), __float_as_uint(bp[t].y) };
                    uint32_t b1[2] = { __float_as_uint(bp[t].z), __float_as_uint(bp[t].w) };
                    mma_tf32(acc[i][2*t    ], a, b0);
                    mma_tf32(acc[i][2*t + 1], a, b1);
                }
            }
        }
    };

    load_regs(0);
    sts(0);
    __syncthreads();

    for (int kb = 0; kb < KB; kb++) {
        int s = kb & 1;
        if (kb + 1 < KB) load_regs(kb + 1);
        compute(s);
        if (kb + 1 < KB) {
            sts(s ^ 1);
            __syncthreads();
        }
    }

    #pragma unroll
    for (int i = 0; i < 2; i++) {
        #pragma unroll
        for (int rs = 0; rs < 2; rs++) {
            int gm = m0 + (mt0 + i)*16 + g + rs*8;
            if (gm >= M) continue;
            #pragma unroll
            for (int j = 0; j < 8; j++) {
                int gn = n0 + (np0*2 + j)*8 + tg*2;
                long off = (long)gm*ldc + gn;
                C[off    ] = acc[i][j][rs*2+0] + bias[gn];
                C[off + 1] = acc[i][j][rs*2+1] + bias[gn+1];
            }
        }
    }
}

// ==================== general batched GEMM ====================
#define TBM 128
#define TBN 64
#define TBK 32

template<bool BT, bool ACC, bool BIAS, bool ROUND>
__global__ __launch_bounds__(256, 2)
void tgemm_kernel(const float* __restrict__ A, const float* __restrict__ B,
                  float* __restrict__ C, const float* __restrict__ bias,
                  int M, int N, int K, int lda, int ldb, int ldc,
                  long sA1, long sA2, long sB1, long sB2, long sC1, long sC2,
                  int zdiv, float alpha)
{
    int z = blockIdx.z;
    long zq = z / zdiv, zr = z % zdiv;
    A += zq*sA1 + zr*sA2;
    B += zq*sB1 + zr*sB2;
    C += zq*sC1 + zr*sC2;

    int m0 = blockIdx.y * TBM, n0 = blockIdx.x * TBN;
    __shared__ __align__(16) float As[4*8*32*4];
    __shared__ __align__(16) float Bs[4*8*32*2];

    int tid = threadIdx.x;
    int warp = tid >> 5, lane = tid & 31;
    int mt0 = (warp & 3) * 2;
    int nt0 = (warp >> 2) * 4;
    int g = lane >> 2, tg = lane & 3;

    float acc[2][4][4] = {};
    float4 ar[4];
    float4 br[2];

    const int KB = K / TBK;

    auto load_regs = [&](int kb) {
        int k0 = kb * TBK;
        #pragma unroll
        for (int i = 0; i < 4; i++) {
            int f4 = i*256 + tid;
            int m = f4 >> 3, k4 = f4 & 7;
            int gm = m0 + m;
            if (gm < M) ar[i] = *(const float4*)(A + (long)gm*lda + k0 + k4*4);
            else        ar[i] = make_float4(0.f,0.f,0.f,0.f);
        }
        if (BT) {
            #pragma unroll
            for (int i = 0; i < 2; i++) {
                int f4 = i*256 + tid;
                int n = f4 >> 3, k4 = f4 & 7;
                int gn = n0 + n;
                if (gn < N) br[i] = *(const float4*)(B + (long)gn*ldb + k0 + k4*4);
                else        br[i] = make_float4(0.f,0.f,0.f,0.f);
            }
        } else {
            #pragma unroll
            for (int i = 0; i < 2; i++) {
                int f4 = i*256 + tid;
                int k = f4 >> 4, n4 = f4 & 15;
                int gn = n0 + n4*4;
                if (gn < N) br[i] = *(const float4*)(B + (long)(k0 + k)*ldb + gn);
                else        br[i] = make_float4(0.f,0.f,0.f,0.f);
            }
        }
    };

    auto sts = [&]() {
        #pragma unroll
        for (int i = 0; i < 4; i++) {
            int f4 = i*256 + tid;
            int m = f4 >> 3, k4 = f4 & 7;
            int kk = k4 >> 1;
            int slot = ((m & 15) >> 3) + 2*(k4 & 1);
            int base = a_off(kk, m >> 4, (m & 7)*4) + slot;
            As[base +  0] = ar[i].x;
            As[base +  4] = ar[i].y;
            As[base +  8] = ar[i].z;
            As[base + 12] = ar[i].w;
        }
        if (BT) {
            #pragma unroll
            for (int i = 0; i < 2; i++) {
                int f4 = i*256 + tid;
                int n = f4 >> 3, k4 = f4 & 7;
                int kk = k4 >> 1;
                int slot = k4 & 1;
                int base = b_off(kk, n >> 3, (n & 7)*4) + slot;
                Bs[base + 0] = br[i].x;
                Bs[base + 2] = br[i].y;
                Bs[base + 4] = br[i].z;
                Bs[base + 6] = br[i].w;
            }
        } else {
            #pragma unroll
            for (int i = 0; i < 2; i++) {
                int f4 = i*256 + tid;
                int k = f4 >> 4, n4 = f4 & 15;
                int kk = k >> 3, k8 = k & 7;
                int slot = k8 >> 2;
                int nt = n4 >> 1;
                int lanebase = ((n4 & 1)*4)*4 + (k8 & 3);
                int base = b_off(kk, nt, 0) + slot;
                Bs[base + (lanebase + 0*4)*2] = br[i].x;
                Bs[base + (lanebase + 1*4)*2] = br[i].y;
                Bs[base + (lanebase + 2*4)*2] = br[i].z;
                Bs[base + (lanebase + 3*4)*2] = br[i].w;
            }
        }
    };

    load_regs(0);
    sts();
    __syncthreads();

    for (int kb = 0; kb < KB; kb++) {
        if (kb + 1 < KB) load_regs(kb + 1);

        #pragma unroll
        for (int kk = 0; kk < 4; kk++) {
            float4 af[2];
            af[0] = *(const float4*)&As[a_off(kk, mt0    , lane)];
            af[1] = *(const float4*)&As[a_off(kk, mt0 + 1, lane)];
            float2 bf[4];
            #pragma unroll
            for (int j = 0; j < 4; j++)
                bf[j] = *(const float2*)&Bs[b_off(kk, nt0 + j, lane)];
            #pragma unroll
            for (int i = 0; i < 2; i++) {
                uint32_t a[4] = { __float_as_uint(af[i].x), __float_as_uint(af[i].y),
                                  __float_as_uint(af[i].z), __float_as_uint(af[i].w) };
                #pragma unroll
                for (int j = 0; j < 4; j++) {
                    uint32_t b2[2] = { __float_as_uint(bf[j].x), __float_as_uint(bf[j].y) };
                    mma_tf32(acc[i][j], a, b2);
                }
            }
        }

        if (kb + 1 < KB) {
            __syncthreads();
            sts();
            __syncthreads();
        }
    }

    int wm = mt0 * 16, wn = nt0 * 8;
    #pragma unroll
    for (int i = 0; i < 2; i++) {
        #pragma unroll
        for (int rs = 0; rs < 2; rs++) {
            int gm = m0 + wm + i*16 + g + rs*8;
            if (gm >= M) continue;
            #pragma unroll
            for (int j = 0; j < 4; j++) {
                int gn = n0 + wn + j*8 + tg*2;
                #pragma unroll
                for (int c = 0; c < 2; c++) {
                    if (gn + c >= N) continue;
                    long off = (long)gm*ldc + gn + c;
                    float v = acc[i][j][rs*2+c] * alpha;
                    if (BIAS) v += bias[gn+c];
                    if (ACC)  v += C[off];
                    if (ROUND) v = f2tff(v);
                    C[off] = v;
                }
            }
        }
    }
}

// ---------------- softmax ----------------
__global__ void softmax_kernel(float* __restrict__ scores)
{
    int warp = threadIdx.x >> 5, lane = threadIdx.x & 31;
    long row = (long)blockIdx.x * 4 + warp;
    float* p = scores + row * SEQP;

    float vals[9];
    float m = -3.0e38f;
    #pragma unroll
    for (int i = 0; i < 9; i++) {
        int idx = lane + i*32;
        vals[i] = (idx < SEQ) ? p[idx] : -3.0e38f;
        m = fmaxf(m, vals[i]);
    }
    #pragma unroll
    for (int s = 16; s > 0; s >>= 1) m = fmaxf(m, __shfl_xor_sync(0xffffffffu, m, s));

    float sum = 0.f;
    #pragma unroll
    for (int i = 0; i < 9; i++) {
        int idx = lane + i*32;
        float e = (idx < SEQ) ? expf(vals[i] - m) : 0.f;
        vals[i] = e;
        sum += e;
    }
    #pragma unroll
    for (int s = 16; s > 0; s >>= 1) sum += __shfl_xor_sync(0xffffffffu, sum, s);
    float inv = 1.f / sum;

    #pragma unroll
    for (int i = 0; i < 9; i++) {
        int idx = lane + i*32;
        if (idx < SEQP) p[idx] = (idx < SEQ) ? f2tff(vals[i] * inv) : 0.f;
    }
}

// ---------------- host launch ----------------
static void* dsym(const void* symbol) { void* p = nullptr; cudaGetSymbolAddress(&p, symbol); return p; }
static inline dim3 tgrid(int N, int M, int Z) { return dim3((N+TBN-1)/TBN, (M+TBM-1)/TBM, Z); }
#define WIDE_SMEM 65536

extern "C" void kernel_launch(void* const* d_in, const int* in_sizes, int n_in,
                              void* d_out, int out_size)
{
    const float* x   = (const float*)d_in[0];
    const float* gw1 = (const float*)d_in[1];
    const float* gb1 = (const float*)d_in[2];
    const float* gw2 = (const float*)d_in[3];
    const float* gb2 = (const float*)d_in[4];
    const float* Wm[4]; const float* Ue[4]; const float* Se[4]; const float* Ve[4]; const float* bi[4];
    for (int p = 0; p < 4; p++) {
        Wm[p] = (const float*)d_in[5 + p*5 + 0];
        Ue[p] = (const float*)d_in[5 + p*5 + 1];
        Se[p] = (const float*)d_in[5 + p*5 + 2];
        Ve[p] = (const float*)d_in[5 + p*5 + 3];
        bi[p] = (const float*)d_in[5 + p*5 + 4];
    }
    float* out = (float*)d_out;

    int*   idxp   = (int*)dsym(g_idx);
    float* gatesp = (float*)dsym(g_gates);
    float* pooled = (float*)dsym(g_pooled);
    float* xr     = (float*)dsym(g_xr);
    float* Wmr    = (float*)dsym(g_Wmr);
    float* bcat   = (float*)dsym(g_bcat);
    float* Vw     = (float*)dsym(g_Vw);
    float* Uw     = (float*)dsym(g_Uw);
    float* tbuf   = (float*)dsym(g_t);
    float* qkv    = (float*)dsym(g_qkv);
    float* sc     = (float*)dsym(g_scores);
    float* ctx    = (float*)dsym(g_ctx);

    const long VW_PER = (long)BATCH*32*DIM;
    const long UW_PER = (long)BATCH*DIM*32;
    const long T_PER  = (long)BATCH*SEQ*32;
    const long SCB    = (long)SEQ*SEQP;

    cudaFuncSetAttribute(tgemm_wide, cudaFuncAttributeMaxDynamicSharedMemorySize, WIDE_SMEM);

    // launch idx 0..4 (so ncu -s 5 captures tgemm_wide at idx 5)
    round_kernel<<<1184, 256>>>(x, xr, (long)MROWS*DIM);                           // 0
    round4_kernel<<<2048, 256>>>(Wm[0], Wm[1], Wm[2], Wm[3], Wmr);                 // 1
    concat_bias_kernel<<<12, 256>>>(bi[0], bi[1], bi[2], bcat);                    // 2
    pool_kernel<<<dim3(8, BATCH), 256>>>(x, pooled);                               // 3
    gating_kernel<<<BATCH, 256>>>(pooled, gw1, gb1, gw2, gb2, idxp, gatesp);       // 4

    // 5: fused main projection qkv = x @ [Wq|Wk|Wv]^T + bcat
    tgemm_wide<<<dim3(QKVD/128, (MROWS + 127)/128), 256, WIDE_SMEM>>>(
        xr, Wmr, bcat, qkv, MROWS, QKVD, QKVD);

    // 6: fused expert folding for all 4 projections
    build_uv_kernel<<<128, 256>>>(Ue[0], Ue[1], Ue[2], Ue[3],
                                  Se[0], Se[1], Se[2], Se[3],
                                  Ve[0], Ve[1], Ve[2], Ve[3],
                                  idxp, gatesp, Vw, Uw);

    // 7: fused xV for q,k,v: t[p,b] = x_b @ Vw[p,b]^T  (z = p*32+b)
    tgemm_kernel<true,false,false,true><<<tgrid(32, SEQ, 3*BATCH), 256>>>(
        xr, Vw, tbuf, nullptr,
        SEQ, 32, DIM, DIM, DIM, 32,
        0, (long)SD, VW_PER, (long)32*DIM, T_PER, (long)SEQ*32, BATCH, 1.f);

    // 8: fused expert accumulate for q,k,v: qkv[:, p*1024 + n] += t @ Uw^T
    tgemm_kernel<true,true,false,true><<<tgrid(DIM, SEQ, 3*BATCH), 256>>>(
        tbuf, Uw, qkv, nullptr,
        SEQ, DIM, 32, 32, 32, QKVD,
        T_PER, (long)SEQ*32, UW_PER, (long)DIM*32, (long)DIM, (long)SEQ*QKVD, BATCH, 1.f);

    // 9: scores = SCALE * q @ k^T  batched (b,h)
    tgemm_kernel<true,false,false,false><<<tgrid(SEQ, SEQ, BATCH*NHEAD), 256>>>(
        qkv, qkv + DIM, sc, nullptr,
        SEQ, SEQ, HDIM, QKVD, QKVD, SEQP,
        (long)SEQ*QKVD, (long)HDIM, (long)SEQ*QKVD, (long)HDIM,
        (long)NHEAD*SCB, SCB, NHEAD, ATTN_SCALE);

    // 10: softmax
    softmax_kernel<<<(unsigned)((long)BATCH*NHEAD*SEQ/4 + 1), 128>>>(sc);

    // 11: ctx = probs @ v
    tgemm_kernel<false,false,false,true><<<tgrid(HDIM, SEQ, BATCH*NHEAD), 256>>>(
        sc, qkv + 2*DIM, ctx, nullptr,
        SEQ, HDIM, SEQP, SEQP, QKVD, DIM,
        (long)NHEAD*SCB, SCB, (long)SEQ*QKVD, (long)HDIM,
        (long)SD, (long)HDIM, NHEAD, 1.f);

    // 12..14: output projection -> d_out
    {
        int p = 3;
        tgemm_kernel<true,false,false,true><<<tgrid(32, SEQ, BATCH), 256>>>(
            ctx, Vw + p*VW_PER, tbuf + p*T_PER, nullptr,
            SEQ, 32, DIM, DIM, DIM, 32,
            0, (long)SD, 0, (long)32*DIM, 0, (long)SEQ*32, BATCH, 1.f);
        tgemm_wide<<<dim3(DIM/128, (MROWS + 127)/128), 256, WIDE_SMEM>>>(
            ctx, Wmr + 3ll*DIM*DIM, bi[3], out, MROWS, DIM, DIM);
        tgemm_kernel<true,true,false,false><<<tgrid(DIM, SEQ, BATCH), 256>>>(
            tbuf + p*T_PER, Uw + p*UW_PER, out, nullptr,
            SEQ, DIM, 32, 32, 32, DIM,
            0, (long)SEQ*32, 0, (long)DIM*32, 0, (long)SD, BATCH, 1.f);
    }
}

// round 7
// speedup vs baseline: 3.1474x; 1.0708x over previous
#include <cuda_runtime.h>
#include <math.h>
#include <stdint.h>

// ---------------- problem constants ----------------
#define BATCH 32
#define SEQ   257
#define DIM   1024
#define QKVD  3072
#define NHEAD 16
#define HDIM  64
#define NEXP  8
#define TOPK  2
#define RANK  16
#define GHID  256
#define SD    (SEQ*DIM)
#define MROWS (BATCH*SEQ)        // 8224
#define ATTN_SCALE 0.125f

// ---------------- static device scratch ----------------
__device__ int   g_idx[BATCH*TOPK];
__device__ float g_gates[BATCH*TOPK];
__device__ float g_pooled[BATCH*DIM];
__device__ float g_xr [MROWS*DIM];
__device__ float g_Wmr[4ll*DIM*DIM];             // rows 0..3071 = Wq|Wk|Wv; 3072..4095 = Wo
__device__ float g_bcat[QKVD];
__device__ float g_Vw[4ll*BATCH*32*DIM];
__device__ float g_Uw[4ll*BATCH*DIM*32];
__device__ float g_t [4ll*BATCH*SEQ*32];
__device__ float g_qkv[(long)MROWS*QKVD + 32*QKVD];
__device__ float g_ctx[MROWS*DIM];

__device__ __forceinline__ uint32_t f2tf(float x) {
    uint32_t r; asm("cvt.rna.tf32.f32 %0, %1;" : "=r"(r) : "f"(x)); return r;
}
__device__ __forceinline__ float f2tff(float x) { return __uint_as_float(f2tf(x)); }

// ---------------- rounding kernels ----------------
__global__ void round_kernel(const float* __restrict__ src, float* __restrict__ dst, long n)
{
    long i = (long)blockIdx.x * blockDim.x + threadIdx.x;
    long stride = (long)gridDim.x * blockDim.x;
    for (; i < n; i += stride) dst[i] = f2tff(src[i]);
}

__global__ void round4_kernel(const float* __restrict__ w0, const float* __restrict__ w1,
                              const float* __restrict__ w2, const float* __restrict__ w3,
                              float* __restrict__ dst)
{
    const long NW = (long)DIM*DIM;
    long i = (long)blockIdx.x * blockDim.x + threadIdx.x;
    long stride = (long)gridDim.x * blockDim.x;
    for (; i < 4*NW; i += stride) {
        int p = (int)(i / NW); long j = i - (long)p*NW;
        const float* w = (p == 0) ? w0 : (p == 1) ? w1 : (p == 2) ? w2 : w3;
        dst[i] = f2tff(w[j]);
    }
}

__global__ void concat_bias_kernel(const float* __restrict__ b0, const float* __restrict__ b1,
                                   const float* __restrict__ b2, float* __restrict__ dst)
{
    int i = blockIdx.x * 256 + threadIdx.x;
    if (i < DIM) dst[i] = b0[i];
    else if (i < 2*DIM) dst[i] = b1[i - DIM];
    else if (i < 3*DIM) dst[i] = b2[i - 2*DIM];
}

// ---------------- pooling ----------------
__global__ void pool_kernel(const float* __restrict__ x, float* __restrict__ pooled)
{
    int b = blockIdx.y;
    int d = blockIdx.x * 128 + (threadIdx.x & 127);
    int half = threadIdx.x >> 7;
    const float* xb = x + (long)b*SD + d;
    int t0 = half * 129;
    int t1 = half ? SEQ : 129;
    float s = 0.f;
    for (int t = t0; t < t1; t++) s += xb[(long)t*DIM];
    __shared__ float red[256];
    red[threadIdx.x] = s;
    __syncthreads();
    if (half == 0)
        pooled[b*DIM + d] = (red[threadIdx.x] + red[threadIdx.x + 128]) * (1.0f / SEQ);
}

// ---------------- gating MLP (exact fp32) ----------------
__global__ void gating_kernel(const float* __restrict__ pooled,
                              const float* __restrict__ gw1, const float* __restrict__ gb1,
                              const float* __restrict__ gw2, const float* __restrict__ gb2,
                              int* __restrict__ idx, float* __restrict__ gates)
{
    int b = blockIdx.x;
    int tid = threadIdx.x;
    __shared__ float pl[DIM];
    __shared__ float h[GHID];
    __shared__ float logits[NEXP];

    for (int d = tid; d < DIM; d += 256) pl[d] = pooled[b*DIM + d];
    __syncthreads();
    {
        float s = gb1[tid];
        const float* w = gw1 + (long)tid * DIM;
        #pragma unroll 8
        for (int d = 0; d < DIM; d++) s += pl[d] * w[d];
        h[tid] = fmaxf(s, 0.f);
    }
    __syncthreads();
    if (tid < NEXP) {
        float s = gb2[tid];
        const float* w = gw2 + (long)tid * GHID;
        for (int g = 0; g < GHID; g++) s += h[g] * w[g];
        logits[tid] = s;
    }
    __syncthreads();
    if (tid == 0) {
        int i1 = 0; float v1 = logits[0];
        for (int e = 1; e < NEXP; e++) if (logits[e] > v1) { v1 = logits[e]; i1 = e; }
        int i2 = -1; float v2 = -3.0e38f;
        for (int e = 0; e < NEXP; e++) if (e != i1 && logits[e] > v2) { v2 = logits[e]; i2 = e; }
        float e2 = expf(v2 - v1);
        float inv = 1.f / (1.f + e2);
        idx[b*2] = i1; idx[b*2+1] = i2;
        gates[b*2] = inv; gates[b*2+1] = e2 * inv;
    }
}

// ---------------- fused fold ----------------
__global__ void build_uv_kernel(const float* __restrict__ U0, const float* __restrict__ U1,
                                const float* __restrict__ U2, const float* __restrict__ U3,
                                const float* __restrict__ S0, const float* __restrict__ S1,
                                const float* __restrict__ S2, const float* __restrict__ S3,
                                const float* __restrict__ V0, const float* __restrict__ V1,
                                const float* __restrict__ V2, const float* __restrict__ V3,
                                const int* __restrict__ idx, const float* __restrict__ gates,
                                float* __restrict__ VwAll, float* __restrict__ UwAll)
{
    int p = blockIdx.x >> 5, b = blockIdx.x & 31;
    const float* U = (p == 0) ? U0 : (p == 1) ? U1 : (p == 2) ? U2 : U3;
    const float* Sg = (p == 0) ? S0 : (p == 1) ? S1 : (p == 2) ? S2 : S3;
    const float* V = (p == 0) ? V0 : (p == 1) ? V1 : (p == 2) ? V2 : V3;
    int tid = threadIdx.x;
    int e0 = idx[b*2], e1 = idx[b*2+1];
    float g0 = gates[b*2], g1 = gates[b*2+1];
    float* vw = VwAll + ((long)p*BATCH + b) * 32 * DIM;
    float* uw = UwAll + ((long)p*BATCH + b) * DIM * 32;

    for (int i = tid; i < 32*DIM; i += 256) {
        int j = i >> 10, d = i & (DIM-1);
        int k = j >> 4, r = j & 15;
        int e = k ? e1 : e0;
        vw[i] = f2tff(Sg[e*RANK + r] * V[((long)e*RANK + r)*DIM + d]);
    }
    for (int i = tid; i < DIM*32; i += 256) {
        int n = i >> 5, j = i & 31;
        int k = j >> 4, r = j & 15;
        int e = k ? e1 : e0;
        float g = k ? g1 : g0;
        uw[i] = f2tff(g * U[((long)e*DIM + n)*RANK + r]);
    }
}

// ---------------- MMA primitive ----------------
__device__ __forceinline__ void mma_tf32(float c[4], const uint32_t a[4], const uint32_t b[2]) {
    asm volatile(
        "mma.sync.aligned.m16n8k8.row.col.f32.tf32.tf32.f32 "
        "{%0,%1,%2,%3}, {%4,%5,%6,%7}, {%8,%9}, {%0,%1,%2,%3};"
        : "+f"(c[0]), "+f"(c[1]), "+f"(c[2]), "+f"(c[3])
        : "r"(a[0]), "r"(a[1]), "r"(a[2]), "r"(a[3]), "r"(b[0]), "r"(b[1]));
}
__device__ __forceinline__ int a_off(int kk, int mt, int lane) { return ((kk*8 + mt)*32 + lane)*4; }
__device__ __forceinline__ int b_off(int kk, int nt, int lane) { return ((kk*8 + nt)*32 + lane)*2; }
__device__ __forceinline__ int bw_off(int kk, int np, int lane) { return ((kk*8 + np)*32 + lane)*4; }

// ==================== WIDE GEMM: C[M,N] = A[M,1024] @ B[N,1024]^T + bias ===========
__global__ __launch_bounds__(256)
void tgemm_wide(const float* __restrict__ A, const float* __restrict__ B,
                const float* __restrict__ bias, float* __restrict__ C,
                int M, int N, int ldc)
{
    extern __shared__ __align__(16) float sw[];
    int m0 = blockIdx.y * 128, n0 = blockIdx.x * 128;

    int tid = threadIdx.x;
    int warp = tid >> 5, lane = tid & 31;
    int mt0 = (warp & 3) * 2;
    int np0 = (warp >> 2) * 4;
    int g = lane >> 2, tg = lane & 3;

    float acc[2][8][4] = {};
    float4 ar[4], br[4];

    const int KB = DIM / 32;

    auto load_regs = [&](int kb) {
        int k0 = kb * 32;
        #pragma unroll
        for (int i = 0; i < 4; i++) {
            int f4 = i*256 + tid;
            int row = f4 >> 3, c4 = f4 & 7;
            int gm = m0 + row;
            if (gm < M) ar[i] = *(const float4*)(A + (long)gm*DIM + k0 + c4*4);
            else        ar[i] = make_float4(0.f,0.f,0.f,0.f);
        }
        #pragma unroll
        for (int i = 0; i < 4; i++) {
            int f4 = i*256 + tid;
            int row = f4 >> 3, c4 = f4 & 7;
            br[i] = *(const float4*)(B + (long)(n0 + row)*DIM + k0 + c4*4);
        }
    };

    auto sts = [&](int s) {
        float* As = sw + s*8192;
        float* Bs = sw + s*8192 + 4096;
        #pragma unroll
        for (int i = 0; i < 4; i++) {
            int f4 = i*256 + tid;
            int row = f4 >> 3, c4 = f4 & 7;
            int kk = c4 >> 1;
            int slot = ((row & 15) >> 3) + 2*(c4 & 1);
            int base = a_off(kk, row >> 4, (row & 7)*4) + slot;
            As[base +  0] = ar[i].x;
            As[base +  4] = ar[i].y;
            As[base +  8] = ar[i].z;
            As[base + 12] = ar[i].w;
        }
        #pragma unroll
        for (int i = 0; i < 4; i++) {
            int f4 = i*256 + tid;
            int row = f4 >> 3, c4 = f4 & 7;
            int nt = row >> 3, gg = row & 7;
            int kk = c4 >> 1;
            int slot = (nt & 1)*2 + (c4 & 1);
            int base = bw_off(kk, nt >> 1, gg*4) + slot;
            Bs[base +  0] = br[i].x;
            Bs[base +  4] = br[i].y;
            Bs[base +  8] = br[i].z;
            Bs[base + 12] = br[i].w;
        }
    };

    auto compute = [&](int s) {
        const float* As = sw + s*8192;
        const float* Bs = sw + s*8192 + 4096;
        #pragma unroll
        for (int kk = 0; kk < 4; kk++) {
            float4 af[2];
            af[0] = *(const float4*)&As[a_off(kk, mt0    , lane)];
            af[1] = *(const float4*)&As[a_off(kk, mt0 + 1, lane)];
            float4 bp[4];
            #pragma unroll
            for (int t = 0; t < 4; t++)
                bp[t] = *(const float4*)&Bs[bw_off(kk, np0 + t, lane)];
            #pragma unroll
            for (int i = 0; i < 2; i++) {
                uint32_t a[4] = { __float_as_uint(af[i].x), __float_as_uint(af[i].y),
                                  __float_as_uint(af[i].z), __float_as_uint(af[i].w) };
                #pragma unroll
                for (int t = 0; t < 4; t++) {
                    uint32_t b0[2] = { __float_as_uint(bp[t].x), __float_as_uint(bp[t].y) };
                    uint32_t b1[2] = { __float_as_uint(bp[t].z), __float_as_uint(bp[t].w) };
                    mma_tf32(acc[i][2*t    ], a, b0);
                    mma_tf32(acc[i][2*t + 1], a, b1);
                }
            }
        }
    };

    load_regs(0);
    sts(0);
    __syncthreads();

    for (int kb = 0; kb < KB; kb++) {
        int s = kb & 1;
        if (kb + 1 < KB) load_regs(kb + 1);
        compute(s);
        if (kb + 1 < KB) {
            sts(s ^ 1);
            __syncthreads();
        }
    }

    #pragma unroll
    for (int i = 0; i < 2; i++) {
        #pragma unroll
        for (int rs = 0; rs < 2; rs++) {
            int gm = m0 + (mt0 + i)*16 + g + rs*8;
            if (gm >= M) continue;
            #pragma unroll
            for (int j = 0; j < 8; j++) {
                int gn = n0 + (np0*2 + j)*8 + tg*2;
                long off = (long)gm*ldc + gn;
                C[off    ] = acc[i][j][rs*2+0] + bias[gn];
                C[off + 1] = acc[i][j][rs*2+1] + bias[gn+1];
            }
        }
    }
}

// ==================== general batched GEMM ====================
#define TBM 128
#define TBN 64
#define TBK 32

template<bool BT, bool ACC, bool BIAS, bool ROUND>
__global__ __launch_bounds__(256, 2)
void tgemm_kernel(const float* __restrict__ A, const float* __restrict__ B,
                  float* __restrict__ C, const float* __restrict__ bias,
                  int M, int N, int K, int lda, int ldb, int ldc,
                  long sA1, long sA2, long sB1, long sB2, long sC1, long sC2,
                  int zdiv, float alpha)
{
    int z = blockIdx.z;
    long zq = z / zdiv, zr = z % zdiv;
    A += zq*sA1 + zr*sA2;
    B += zq*sB1 + zr*sB2;
    C += zq*sC1 + zr*sC2;

    int m0 = blockIdx.y * TBM, n0 = blockIdx.x * TBN;
    __shared__ __align__(16) float As[4*8*32*4];
    __shared__ __align__(16) float Bs[4*8*32*2];

    int tid = threadIdx.x;
    int warp = tid >> 5, lane = tid & 31;
    int mt0 = (warp & 3) * 2;
    int nt0 = (warp >> 2) * 4;
    int g = lane >> 2, tg = lane & 3;

    float acc[2][4][4] = {};
    float4 ar[4];
    float4 br[2];

    const int KB = K / TBK;

    auto load_regs = [&](int kb) {
        int k0 = kb * TBK;
        #pragma unroll
        for (int i = 0; i < 4; i++) {
            int f4 = i*256 + tid;
            int m = f4 >> 3, k4 = f4 & 7;
            int gm = m0 + m;
            if (gm < M) ar[i] = *(const float4*)(A + (long)gm*lda + k0 + k4*4);
            else        ar[i] = make_float4(0.f,0.f,0.f,0.f);
        }
        if (BT) {
            #pragma unroll
            for (int i = 0; i < 2; i++) {
                int f4 = i*256 + tid;
                int n = f4 >> 3, k4 = f4 & 7;
                int gn = n0 + n;
                if (gn < N) br[i] = *(const float4*)(B + (long)gn*ldb + k0 + k4*4);
                else        br[i] = make_float4(0.f,0.f,0.f,0.f);
            }
        } else {
            #pragma unroll
            for (int i = 0; i < 2; i++) {
                int f4 = i*256 + tid;
                int k = f4 >> 4, n4 = f4 & 15;
                int gn = n0 + n4*4;
                if (gn < N) br[i] = *(const float4*)(B + (long)(k0 + k)*ldb + gn);
                else        br[i] = make_float4(0.f,0.f,0.f,0.f);
            }
        }
    };

    auto sts = [&]() {
        #pragma unroll
        for (int i = 0; i < 4; i++) {
            int f4 = i*256 + tid;
            int m = f4 >> 3, k4 = f4 & 7;
            int kk = k4 >> 1;
            int slot = ((m & 15) >> 3) + 2*(k4 & 1);
            int base = a_off(kk, m >> 4, (m & 7)*4) + slot;
            As[base +  0] = ar[i].x;
            As[base +  4] = ar[i].y;
            As[base +  8] = ar[i].z;
            As[base + 12] = ar[i].w;
        }
        if (BT) {
            #pragma unroll
            for (int i = 0; i < 2; i++) {
                int f4 = i*256 + tid;
                int n = f4 >> 3, k4 = f4 & 7;
                int kk = k4 >> 1;
                int slot = k4 & 1;
                int base = b_off(kk, n >> 3, (n & 7)*4) + slot;
                Bs[base + 0] = br[i].x;
                Bs[base + 2] = br[i].y;
                Bs[base + 4] = br[i].z;
                Bs[base + 6] = br[i].w;
            }
        } else {
            #pragma unroll
            for (int i = 0; i < 2; i++) {
                int f4 = i*256 + tid;
                int k = f4 >> 4, n4 = f4 & 15;
                int kk = k >> 3, k8 = k & 7;
                int slot = k8 >> 2;
                int nt = n4 >> 1;
                int lanebase = ((n4 & 1)*4)*4 + (k8 & 3);
                int base = b_off(kk, nt, 0) + slot;
                Bs[base + (lanebase + 0*4)*2] = br[i].x;
                Bs[base + (lanebase + 1*4)*2] = br[i].y;
                Bs[base + (lanebase + 2*4)*2] = br[i].z;
                Bs[base + (lanebase + 3*4)*2] = br[i].w;
            }
        }
    };

    load_regs(0);
    sts();
    __syncthreads();

    for (int kb = 0; kb < KB; kb++) {
        if (kb + 1 < KB) load_regs(kb + 1);

        #pragma unroll
        for (int kk = 0; kk < 4; kk++) {
            float4 af[2];
            af[0] = *(const float4*)&As[a_off(kk, mt0    , lane)];
            af[1] = *(const float4*)&As[a_off(kk, mt0 + 1, lane)];
            float2 bf[4];
            #pragma unroll
            for (int j = 0; j < 4; j++)
                bf[j] = *(const float2*)&Bs[b_off(kk, nt0 + j, lane)];
            #pragma unroll
            for (int i = 0; i < 2; i++) {
                uint32_t a[4] = { __float_as_uint(af[i].x), __float_as_uint(af[i].y),
                                  __float_as_uint(af[i].z), __float_as_uint(af[i].w) };
                #pragma unroll
                for (int j = 0; j < 4; j++) {
                    uint32_t b2[2] = { __float_as_uint(bf[j].x), __float_as_uint(bf[j].y) };
                    mma_tf32(acc[i][j], a, b2);
                }
            }
        }

        if (kb + 1 < KB) {
            __syncthreads();
            sts();
            __syncthreads();
        }
    }

    int wm = mt0 * 16, wn = nt0 * 8;
    #pragma unroll
    for (int i = 0; i < 2; i++) {
        #pragma unroll
        for (int rs = 0; rs < 2; rs++) {
            int gm = m0 + wm + i*16 + g + rs*8;
            if (gm >= M) continue;
            #pragma unroll
            for (int j = 0; j < 4; j++) {
                int gn = n0 + wn + j*8 + tg*2;
                #pragma unroll
                for (int c = 0; c < 2; c++) {
                    if (gn + c >= N) continue;
                    long off = (long)gm*ldc + gn + c;
                    float v = acc[i][j][rs*2+c] * alpha;
                    if (BIAS) v += bias[gn+c];
                    if (ACC)  v += C[off];
                    if (ROUND) v = f2tff(v);
                    C[off] = v;
                }
            }
        }
    }
}

// ==================== FLASH ATTENTION ====================
// grid (3, BATCH*NHEAD), block 256. q/k/v read from fused g_qkv (stride QKVD).
// Per CTA: 128 q rows, kv tiles of 64, online softmax, ctx written tf32-rounded.
#define FLASH_SMEM ((4096 + 4096 + 128*68) * 4)   // 67584 bytes

__global__ __launch_bounds__(256)
void flash_kernel(const float* __restrict__ qkv, float* __restrict__ ctx)
{
    extern __shared__ __align__(16) float fs[];
    float* ks = fs;            // K tile frags: 4096 floats
    float* vs = fs + 4096;     // V tile frags: 4096 floats
    float* ps = fs + 8192;     // P tile plain [128][68]

    int tid = threadIdx.x, warp = tid >> 5, lane = tid & 31;
    int g = lane >> 2, tg = lane & 3;
    int bh = blockIdx.y;
    int b = bh >> 4, h = bh & 15;
    int m0 = blockIdx.x * 128;

    const float* qb = qkv + (long)b*SEQ*QKVD + h*HDIM;
    const float* kb = qkv + (long)b*SEQ*QKVD + DIM + h*HDIM;
    const float* vb = qkv + (long)b*SEQ*QKVD + 2*DIM + h*HDIM;

    int r0 = m0 + warp*16 + g;
    int r1 = r0 + 8;

    // q fragments in registers
    uint32_t qa[8][4];
    #pragma unroll
    for (int kk = 0; kk < 8; kk++) {
        float a0 = (r0 < SEQ) ? qb[(long)r0*QKVD + kk*8 + tg]     : 0.f;
        float a1 = (r1 < SEQ) ? qb[(long)r1*QKVD + kk*8 + tg]     : 0.f;
        float a2 = (r0 < SEQ) ? qb[(long)r0*QKVD + kk*8 + tg + 4] : 0.f;
        float a3 = (r1 < SEQ) ? qb[(long)r1*QKVD + kk*8 + tg + 4] : 0.f;
        qa[kk][0] = __float_as_uint(a0); qa[kk][1] = __float_as_uint(a1);
        qa[kk][2] = __float_as_uint(a2); qa[kk][3] = __float_as_uint(a3);
    }

    float o[8][4] = {};
    float m0r = -1e30f, m1r = -1e30f, l0r = 0.f, l1r = 0.f;

    for (int j = 0; j < 5; j++) {
        int kv0 = j * 64;
        // load K tile (64 n-rows x 64 k-cols) into BT=true frag layout
        #pragma unroll
        for (int i = 0; i < 4; i++) {
            int f4 = i*256 + tid;
            int n = f4 >> 4, c4 = f4 & 15;
            int gr = kv0 + n;
            float4 v = make_float4(0.f,0.f,0.f,0.f);
            if (gr < SEQ) v = *(const float4*)(kb + (long)gr*QKVD + c4*4);
            int kk = c4 >> 1, slot = c4 & 1;
            int base = ((kk*8 + (n >> 3))*32 + (n & 7)*4)*2 + slot;
            ks[base + 0] = v.x; ks[base + 2] = v.y;
            ks[base + 4] = v.z; ks[base + 6] = v.w;
        }
        // load V tile (64 k-rows x 64 n-cols) into BT=false frag layout
        #pragma unroll
        for (int i = 0; i < 4; i++) {
            int f4 = i*256 + tid;
            int k = f4 >> 4, n4 = f4 & 15;
            int gr = kv0 + k;
            float4 v = make_float4(0.f,0.f,0.f,0.f);
            if (gr < SEQ) v = *(const float4*)(vb + (long)gr*QKVD + n4*4);
            int kk = k >> 3, k8 = k & 7;
            int slot = k8 >> 2;
            int nt = n4 >> 1;
            int lanebase = ((n4 & 1)*4)*4 + (k8 & 3);
            int base = ((kk*8 + nt)*32)*2 + slot;
            vs[base + (lanebase + 0*4)*2] = v.x;
            vs[base + (lanebase + 1*4)*2] = v.y;
            vs[base + (lanebase + 2*4)*2] = v.z;
            vs[base + (lanebase + 3*4)*2] = v.w;
        }
        __syncthreads();

        // s = q @ k^T
        float s[8][4] = {};
        #pragma unroll
        for (int kk = 0; kk < 8; kk++) {
            #pragma unroll
            for (int nt = 0; nt < 8; nt++) {
                const float2 bf = *(const float2*)&ks[((kk*8 + nt)*32 + lane)*2];
                uint32_t b2[2] = { __float_as_uint(bf.x), __float_as_uint(bf.y) };
                mma_tf32(s[nt], qa[kk], b2);
            }
        }

        // scale + mask + online softmax
        float tmax0 = -1e30f, tmax1 = -1e30f;
        #pragma unroll
        for (int nt = 0; nt < 8; nt++) {
            int c0 = kv0 + nt*8 + 2*tg;
            s[nt][0] = (c0     < SEQ) ? s[nt][0]*ATTN_SCALE : -1e30f;
            s[nt][1] = (c0 + 1 < SEQ) ? s[nt][1]*ATTN_SCALE : -1e30f;
            s[nt][2] = (c0     < SEQ) ? s[nt][2]*ATTN_SCALE : -1e30f;
            s[nt][3] = (c0 + 1 < SEQ) ? s[nt][3]*ATTN_SCALE : -1e30f;
            tmax0 = fmaxf(tmax0, fmaxf(s[nt][0], s[nt][1]));
            tmax1 = fmaxf(tmax1, fmaxf(s[nt][2], s[nt][3]));
        }
        tmax0 = fmaxf(tmax0, __shfl_xor_sync(0xffffffffu, tmax0, 1));
        tmax0 = fmaxf(tmax0, __shfl_xor_sync(0xffffffffu, tmax0, 2));
        tmax1 = fmaxf(tmax1, __shfl_xor_sync(0xffffffffu, tmax1, 1));
        tmax1 = fmaxf(tmax1, __shfl_xor_sync(0xffffffffu, tmax1, 2));
        float nm0 = fmaxf(m0r, tmax0), nm1 = fmaxf(m1r, tmax1);
        float f0 = __expf(m0r - nm0), f1 = __expf(m1r - nm1);

        float sum0 = 0.f, sum1 = 0.f;
        int prow0 = (warp*16 + g)*68 + 2*tg;
        int prow1 = (warp*16 + g + 8)*68 + 2*tg;
        #pragma unroll
        for (int nt = 0; nt < 8; nt++) {
            float p0 = __expf(s[nt][0] - nm0);
            float p1 = __expf(s[nt][1] - nm0);
            float p2 = __expf(s[nt][2] - nm1);
            float p3 = __expf(s[nt][3] - nm1);
            sum0 += p0 + p1;
            sum1 += p2 + p3;
            *(float2*)&ps[prow0 + nt*8] = make_float2(f2tff(p0), f2tff(p1));
            *(float2*)&ps[prow1 + nt*8] = make_float2(f2tff(p2), f2tff(p3));
        }
        sum0 += __shfl_xor_sync(0xffffffffu, sum0, 1);
        sum0 += __shfl_xor_sync(0xffffffffu, sum0, 2);
        sum1 += __shfl_xor_sync(0xffffffffu, sum1, 1);
        sum1 += __shfl_xor_sync(0xffffffffu, sum1, 2);
        l0r = l0r*f0 + sum0;
        l1r = l1r*f1 + sum1;
        m0r = nm0; m1r = nm1;
        #pragma unroll
        for (int nt = 0; nt < 8; nt++) {
            o[nt][0] *= f0; o[nt][1] *= f0;
            o[nt][2] *= f1; o[nt][3] *= f1;
        }
        __syncthreads();

        // o += p @ v
        #pragma unroll
        for (int kk = 0; kk < 8; kk++) {
            uint32_t pa[4];
            pa[0] = __float_as_uint(ps[(warp*16 + g    )*68 + kk*8 + tg    ]);
            pa[1] = __float_as_uint(ps[(warp*16 + g + 8)*68 + kk*8 + tg    ]);
            pa[2] = __float_as_uint(ps[(warp*16 + g    )*68 + kk*8 + tg + 4]);
            pa[3] = __float_as_uint(ps[(warp*16 + g + 8)*68 + kk*8 + tg + 4]);
            #pragma unroll
            for (int nt = 0; nt < 8; nt++) {
                const float2 bf = *(const float2*)&vs[((kk*8 + nt)*32 + lane)*2];
                uint32_t b2[2] = { __float_as_uint(bf.x), __float_as_uint(bf.y) };
                mma_tf32(o[nt], pa, b2);
            }
        }
        __syncthreads();
    }

    // write ctx = o / l (tf32-rounded)
    float inv0 = 1.f / l0r, inv1 = 1.f / l1r;
    float* cb = ctx + (long)b*SEQ*DIM + h*HDIM;
    #pragma unroll
    for (int nt = 0; nt < 8; nt++) {
        int col = nt*8 + 2*tg;
        if (r0 < SEQ)
            *(float2*)&cb[(long)r0*DIM + col] =
                make_float2(f2tff(o[nt][0]*inv0), f2tff(o[nt][1]*inv0));
        if (r1 < SEQ)
            *(float2*)&cb[(long)r1*DIM + col] =
                make_float2(f2tff(o[nt][2]*inv1), f2tff(o[nt][3]*inv1));
    }
}

// ---------------- host launch ----------------
static void* dsym(const void* symbol) { void* p = nullptr; cudaGetSymbolAddress(&p, symbol); return p; }
static inline dim3 tgrid(int N, int M, int Z) { return dim3((N+TBN-1)/TBN, (M+TBM-1)/TBM, Z); }
#define WIDE_SMEM 65536

extern "C" void kernel_launch(void* const* d_in, const int* in_sizes, int n_in,
                              void* d_out, int out_size)
{
    const float* x   = (const float*)d_in[0];
    const float* gw1 = (const float*)d_in[1];
    const float* gb1 = (const float*)d_in[2];
    const float* gw2 = (const float*)d_in[3];
    const float* gb2 = (const float*)d_in[4];
    const float* Wm[4]; const float* Ue[4]; const float* Se[4]; const float* Ve[4]; const float* bi[4];
    for (int p = 0; p < 4; p++) {
        Wm[p] = (const float*)d_in[5 + p*5 + 0];
        Ue[p] = (const float*)d_in[5 + p*5 + 1];
        Se[p] = (const float*)d_in[5 + p*5 + 2];
        Ve[p] = (const float*)d_in[5 + p*5 + 3];
        bi[p] = (const float*)d_in[5 + p*5 + 4];
    }
    float* out = (float*)d_out;

    int*   idxp   = (int*)dsym(g_idx);
    float* gatesp = (float*)dsym(g_gates);
    float* pooled = (float*)dsym(g_pooled);
    float* xr     = (float*)dsym(g_xr);
    float* Wmr    = (float*)dsym(g_Wmr);
    float* bcat   = (float*)dsym(g_bcat);
    float* Vw     = (float*)dsym(g_Vw);
    float* Uw     = (float*)dsym(g_Uw);
    float* tbuf   = (float*)dsym(g_t);
    float* qkv    = (float*)dsym(g_qkv);
    float* ctx    = (float*)dsym(g_ctx);

    const long VW_PER = (long)BATCH*32*DIM;
    const long UW_PER = (long)BATCH*DIM*32;
    const long T_PER  = (long)BATCH*SEQ*32;

    cudaFuncSetAttribute(tgemm_wide, cudaFuncAttributeMaxDynamicSharedMemorySize, WIDE_SMEM);
    cudaFuncSetAttribute(flash_kernel, cudaFuncAttributeMaxDynamicSharedMemorySize, FLASH_SMEM);

    round_kernel<<<1184, 256>>>(x, xr, (long)MROWS*DIM);                           // 0
    round4_kernel<<<2048, 256>>>(Wm[0], Wm[1], Wm[2], Wm[3], Wmr);                 // 1
    concat_bias_kernel<<<12, 256>>>(bi[0], bi[1], bi[2], bcat);                    // 2
    pool_kernel<<<dim3(8, BATCH), 256>>>(x, pooled);                               // 3
    gating_kernel<<<BATCH, 256>>>(pooled, gw1, gb1, gw2, gb2, idxp, gatesp);       // 4

    // 5: fused main projection qkv = x @ [Wq|Wk|Wv]^T + bcat
    tgemm_wide<<<dim3(QKVD/128, (MROWS + 127)/128), 256, WIDE_SMEM>>>(
        xr, Wmr, bcat, qkv, MROWS, QKVD, QKVD);

    // 6: fused expert folding
    build_uv_kernel<<<128, 256>>>(Ue[0], Ue[1], Ue[2], Ue[3],
                                  Se[0], Se[1], Se[2], Se[3],
                                  Ve[0], Ve[1], Ve[2], Ve[3],
                                  idxp, gatesp, Vw, Uw);

    // 7: fused xV for q,k,v
    tgemm_kernel<true,false,false,true><<<tgrid(32, SEQ, 3*BATCH), 256>>>(
        xr, Vw, tbuf, nullptr,
        SEQ, 32, DIM, DIM, DIM, 32,
        0, (long)SD, VW_PER, (long)32*DIM, T_PER, (long)SEQ*32, BATCH, 1.f);

    // 8: fused expert accumulate for q,k,v (rounds qkv)
    tgemm_kernel<true,true,false,true><<<tgrid(DIM, SEQ, 3*BATCH), 256>>>(
        tbuf, Uw, qkv, nullptr,
        SEQ, DIM, 32, 32, 32, QKVD,
        T_PER, (long)SEQ*32, UW_PER, (long)DIM*32, (long)DIM, (long)SEQ*QKVD, BATCH, 1.f);

    // 9: flash attention (scores + softmax + pv fused)
    flash_kernel<<<dim3(3, BATCH*NHEAD), 256, FLASH_SMEM>>>(qkv, ctx);

    // 10..12: output projection -> d_out
    {
        int p = 3;
        tgemm_kernel<true,false,false,true><<<tgrid(32, SEQ, BATCH), 256>>>(
            ctx, Vw + p*VW_PER, tbuf + p*T_PER, nullptr,
            SEQ, 32, DIM, DIM, DIM, 32,
            0, (long)SD, 0, (long)32*DIM, 0, (long)SEQ*32, BATCH, 1.f);
        tgemm_wide<<<dim3(DIM/128, (MROWS + 127)/128), 256, WIDE_SMEM>>>(
            ctx, Wmr + 3ll*DIM*DIM, bi[3], out, MROWS, DIM, DIM);
        tgemm_kernel<true,true,false,false><<<tgrid(DIM, SEQ, BATCH), 256>>>(
            tbuf + p*T_PER, Uw + p*UW_PER, out, nullptr,
            SEQ, DIM, 32, 32, 32, DIM,
            0, (long)SEQ*32, 0, (long)DIM*32, 0, (long)SD, BATCH, 1.f);
    }
}

// round 8
// speedup vs baseline: 3.7268x; 1.1841x over previous
#include <cuda_runtime.h>
#include <cuda_fp16.h>
#include <math.h>
#include <stdint.h>

// ---------------- problem constants ----------------
#define BATCH 32
#define SEQ   257
#define DIM   1024
#define QKVD  3072
#define NHEAD 16
#define HDIM  64
#define NEXP  8
#define TOPK  2
#define RANK  16
#define GHID  256
#define SD    (SEQ*DIM)
#define MROWS (BATCH*SEQ)        // 8224
#define ATTN_SCALE 0.125f

// ---------------- static device scratch ----------------
__device__ int   g_idx[BATCH*TOPK];
__device__ float g_gates[BATCH*TOPK];
__device__ float g_pooled[BATCH*DIM];
__device__ float g_bcat[QKVD];
__device__ __align__(16) __half g_xh [MROWS*DIM];
__device__ __align__(16) __half g_Wmh[4ll*DIM*DIM];     // rows 0..3071 = Wq|Wk|Wv; 3072..4095 = Wo
__device__ __align__(16) __half g_Vw[4ll*BATCH*32*DIM];
__device__ __align__(16) __half g_Uw[4ll*BATCH*DIM*32];
__device__ __align__(16) __half g_t [4ll*BATCH*SEQ*32];
__device__ __align__(16) __half g_qkv[(long)(MROWS+32)*QKVD];
__device__ __align__(16) __half g_ctx[MROWS*DIM];

// ---------------- conversion kernels ----------------
__global__ void cvt_kernel(const float* __restrict__ src, __half* __restrict__ dst, long n)
{
    long i = (long)blockIdx.x * blockDim.x + threadIdx.x;
    long stride = (long)gridDim.x * blockDim.x;
    for (; i < n; i += stride) dst[i] = __float2half_rn(src[i]);
}

__global__ void cvt4_kernel(const float* __restrict__ w0, const float* __restrict__ w1,
                            const float* __restrict__ w2, const float* __restrict__ w3,
                            __half* __restrict__ dst)
{
    const long NW = (long)DIM*DIM;
    long i = (long)blockIdx.x * blockDim.x + threadIdx.x;
    long stride = (long)gridDim.x * blockDim.x;
    for (; i < 4*NW; i += stride) {
        int p = (int)(i / NW); long j = i - (long)p*NW;
        const float* w = (p == 0) ? w0 : (p == 1) ? w1 : (p == 2) ? w2 : w3;
        dst[i] = __float2half_rn(w[j]);
    }
}

__global__ void concat_bias_kernel(const float* __restrict__ b0, const float* __restrict__ b1,
                                   const float* __restrict__ b2, float* __restrict__ dst)
{
    int i = blockIdx.x * 256 + threadIdx.x;
    if (i < DIM) dst[i] = b0[i];
    else if (i < 2*DIM) dst[i] = b1[i - DIM];
    else if (i < 3*DIM) dst[i] = b2[i - 2*DIM];
}

// ---------------- pooling (fp32, exact) ----------------
__global__ void pool_kernel(const float* __restrict__ x, float* __restrict__ pooled)
{
    int b = blockIdx.y;
    int d = blockIdx.x * 128 + (threadIdx.x & 127);
    int half = threadIdx.x >> 7;
    const float* xb = x + (long)b*SD + d;
    int t0 = half * 129;
    int t1 = half ? SEQ : 129;
    float s = 0.f;
    for (int t = t0; t < t1; t++) s += xb[(long)t*DIM];
    __shared__ float red[256];
    red[threadIdx.x] = s;
    __syncthreads();
    if (half == 0)
        pooled[b*DIM + d] = (red[threadIdx.x] + red[threadIdx.x + 128]) * (1.0f / SEQ);
}

// ---------------- gating MLP (exact fp32) ----------------
__global__ void gating_kernel(const float* __restrict__ pooled,
                              const float* __restrict__ gw1, const float* __restrict__ gb1,
                              const float* __restrict__ gw2, const float* __restrict__ gb2,
                              int* __restrict__ idx, float* __restrict__ gates)
{
    int b = blockIdx.x;
    int tid = threadIdx.x;
    __shared__ float pl[DIM];
    __shared__ float h[GHID];
    __shared__ float logits[NEXP];

    for (int d = tid; d < DIM; d += 256) pl[d] = pooled[b*DIM + d];
    __syncthreads();
    {
        float s = gb1[tid];
        const float* w = gw1 + (long)tid * DIM;
        #pragma unroll 8
        for (int d = 0; d < DIM; d++) s += pl[d] * w[d];
        h[tid] = fmaxf(s, 0.f);
    }
    __syncthreads();
    if (tid < NEXP) {
        float s = gb2[tid];
        const float* w = gw2 + (long)tid * GHID;
        for (int g = 0; g < GHID; g++) s += h[g] * w[g];
        logits[tid] = s;
    }
    __syncthreads();
    if (tid == 0) {
        int i1 = 0; float v1 = logits[0];
        for (int e = 1; e < NEXP; e++) if (logits[e] > v1) { v1 = logits[e]; i1 = e; }
        int i2 = -1; float v2 = -3.0e38f;
        for (int e = 0; e < NEXP; e++) if (e != i1 && logits[e] > v2) { v2 = logits[e]; i2 = e; }
        float e2 = expf(v2 - v1);
        float inv = 1.f / (1.f + e2);
        idx[b*2] = i1; idx[b*2+1] = i2;
        gates[b*2] = inv; gates[b*2+1] = e2 * inv;
    }
}

// ---------------- fused fold (fp16 outputs) ----------------
__global__ void build_uv_kernel(const float* __restrict__ U0, const float* __restrict__ U1,
                                const float* __restrict__ U2, const float* __restrict__ U3,
                                const float* __restrict__ S0, const float* __restrict__ S1,
                                const float* __restrict__ S2, const float* __restrict__ S3,
                                const float* __restrict__ V0, const float* __restrict__ V1,
                                const float* __restrict__ V2, const float* __restrict__ V3,
                                const int* __restrict__ idx, const float* __restrict__ gates,
                                __half* __restrict__ VwAll, __half* __restrict__ UwAll)
{
    int p = blockIdx.x >> 5, b = blockIdx.x & 31;
    const float* U = (p == 0) ? U0 : (p == 1) ? U1 : (p == 2) ? U2 : U3;
    const float* Sg = (p == 0) ? S0 : (p == 1) ? S1 : (p == 2) ? S2 : S3;
    const float* V = (p == 0) ? V0 : (p == 1) ? V1 : (p == 2) ? V2 : V3;
    int tid = threadIdx.x;
    int e0 = idx[b*2], e1 = idx[b*2+1];
    float g0 = gates[b*2], g1 = gates[b*2+1];
    __half* vw = VwAll + ((long)p*BATCH + b) * 32 * DIM;
    __half* uw = UwAll + ((long)p*BATCH + b) * DIM * 32;

    for (int i = tid; i < 32*DIM; i += 256) {
        int j = i >> 10, d = i & (DIM-1);
        int k = j >> 4, r = j & 15;
        int e = k ? e1 : e0;
        vw[i] = __float2half_rn(Sg[e*RANK + r] * V[((long)e*RANK + r)*DIM + d]);
    }
    for (int i = tid; i < DIM*32; i += 256) {
        int n = i >> 5, j = i & 31;
        int k = j >> 4, r = j & 15;
        int e = k ? e1 : e0;
        float g = k ? g1 : g0;
        uw[i] = __float2half_rn(g * U[((long)e*DIM + n)*RANK + r]);
    }
}

// ---------------- FP16 MMA primitive ----------------
__device__ __forceinline__ void mma_f16(float c[4], const uint32_t a[4], const uint32_t b0, const uint32_t b1) {
    asm volatile(
        "mma.sync.aligned.m16n8k16.row.col.f32.f16.f16.f32 "
        "{%0,%1,%2,%3}, {%4,%5,%6,%7}, {%8,%9}, {%0,%1,%2,%3};"
        : "+f"(c[0]), "+f"(c[1]), "+f"(c[2]), "+f"(c[3])
        : "r"(a[0]), "r"(a[1]), "r"(a[2]), "r"(a[3]), "r"(b0), "r"(b1));
}

__device__ __forceinline__ float ld_c(const float* p) { return *p; }
__device__ __forceinline__ float ld_c(const __half* p) { return __half2float(*p); }
__device__ __forceinline__ void st_c(float* p, float v) { *p = v; }
__device__ __forceinline__ void st_c(__half* p, float v) { *p = __float2half_rn(v); }

// ==================== WIDE FP16 GEMM: C[M,N] = A[M,1024] @ B[N,1024]^T + bias ======
// TBM=128, TBN=128, TBK=32 (halves). 8 warps, warp tile 32x64, double buffer, 1 sync/iter.
template<typename CT>
__global__ __launch_bounds__(256, 2)
void hgemm_wide(const __half* __restrict__ A, const __half* __restrict__ B,
                const float* __restrict__ bias, CT* __restrict__ C, int M, int ldc)
{
    __shared__ uint32_t As[2][2048];   // [kk(2)][mt(8)][lane(32)][4 regs]
    __shared__ uint32_t Bs[2][2048];   // [kk(2)][np(8)][lane(32)][4 = ntEven.R0,R1, ntOdd.R0,R1]
    int m0 = blockIdx.y * 128, n0 = blockIdx.x * 128;

    int tid = threadIdx.x;
    int warp = tid >> 5, lane = tid & 31;
    int mt0 = (warp & 3) * 2;
    int np0 = (warp >> 2) * 4;
    int g = lane >> 2, tg = lane & 3;

    float acc[2][8][4] = {};
    uint4 ar[2], br[2];

    const int KB = DIM / 32;   // 32

    auto load_regs = [&](int kb) {
        int k0 = kb * 32;
        #pragma unroll
        for (int i = 0; i < 2; i++) {
            int f4 = i*256 + tid;
            int row = f4 >> 2, c8 = f4 & 3;
            int gm = m0 + row;
            ar[i] = (gm < M) ? *(const uint4*)(A + (long)gm*DIM + k0 + c8*8)
                             : make_uint4(0u,0u,0u,0u);
        }
        #pragma unroll
        for (int i = 0; i < 2; i++) {
            int f4 = i*256 + tid;
            int row = f4 >> 2, c8 = f4 & 3;
            br[i] = *(const uint4*)(B + (long)(n0 + row)*DIM + k0 + c8*8);
        }
    };

    auto sts = [&](int s) {
        #pragma unroll
        for (int i = 0; i < 2; i++) {
            int f4 = i*256 + tid;
            int row = f4 >> 2, c8 = f4 & 3;
            int kk = c8 >> 1, kh = c8 & 1;
            int mt = row >> 4, w = row & 15, gg = w & 7, rh = w >> 3;
            int base = ((kk*8 + mt)*32 + gg*4)*4 + kh*2 + rh;
            As[s][base +  0] = ar[i].x;
            As[s][base +  4] = ar[i].y;
            As[s][base +  8] = ar[i].z;
            As[s][base + 12] = ar[i].w;
        }
        #pragma unroll
        for (int i = 0; i < 2; i++) {
            int f4 = i*256 + tid;
            int n = f4 >> 2, c8 = f4 & 3;
            int kk = c8 >> 1, kh = c8 & 1;
            int nt = n >> 3, gc = n & 7, np = nt >> 1, sub = nt & 1;
            int base = ((kk*8 + np)*32 + gc*4)*4 + sub*2 + kh;
            Bs[s][base +  0] = br[i].x;
            Bs[s][base +  4] = br[i].y;
            Bs[s][base +  8] = br[i].z;
            Bs[s][base + 12] = br[i].w;
        }
    };

    auto compute = [&](int s) {
        #pragma unroll
        for (int kk = 0; kk < 2; kk++) {
            uint4 a4[2];
            a4[0] = *(const uint4*)&As[s][((kk*8 + mt0    )*32 + lane)*4];
            a4[1] = *(const uint4*)&As[s][((kk*8 + mt0 + 1)*32 + lane)*4];
            uint4 bp[4];
            #pragma unroll
            for (int p = 0; p < 4; p++)
                bp[p] = *(const uint4*)&Bs[s][((kk*8 + np0 + p)*32 + lane)*4];
            #pragma unroll
            for (int i = 0; i < 2; i++) {
                uint32_t a[4] = { a4[i].x, a4[i].y, a4[i].z, a4[i].w };
                #pragma unroll
                for (int p = 0; p < 4; p++) {
                    mma_f16(acc[i][2*p    ], a, bp[p].x, bp[p].y);
                    mma_f16(acc[i][2*p + 1], a, bp[p].z, bp[p].w);
                }
            }
        }
    };

    load_regs(0);
    sts(0);
    __syncthreads();

    for (int kb = 0; kb < KB; kb++) {
        int s = kb & 1;
        if (kb + 1 < KB) load_regs(kb + 1);
        compute(s);
        if (kb + 1 < KB) {
            sts(s ^ 1);
            __syncthreads();
        }
    }

    #pragma unroll
    for (int i = 0; i < 2; i++) {
        #pragma unroll
        for (int rs = 0; rs < 2; rs++) {
            int gm = m0 + (mt0 + i)*16 + g + rs*8;
            if (gm >= M) continue;
            #pragma unroll
            for (int j = 0; j < 8; j++) {
                int gn = n0 + (np0*2 + j)*8 + tg*2;
                long off = (long)gm*ldc + gn;
                st_c(&C[off    ], acc[i][j][rs*2+0] + bias[gn]);
                st_c(&C[off + 1], acc[i][j][rs*2+1] + bias[gn+1]);
            }
        }
    }
}

// ==================== general batched FP16 GEMM (B transposed (N,K)) ====================
// TBM=128, TBN=64, TBK=32. Requires K%32==0, 16B-aligned rows.
#define TBN 64
template<bool ACC, typename CT>
__global__ __launch_bounds__(256, 2)
void hgemm(const __half* __restrict__ A, const __half* __restrict__ B,
           CT* __restrict__ C,
           int M, int N, int K, int lda, int ldb, int ldc,
           long sA1, long sA2, long sB1, long sB2, long sC1, long sC2, int zdiv)
{
    int z = blockIdx.z;
    long zq = z / zdiv, zr = z % zdiv;
    A += zq*sA1 + zr*sA2;
    B += zq*sB1 + zr*sB2;
    C += zq*sC1 + zr*sC2;

    int m0 = blockIdx.y * 128, n0 = blockIdx.x * TBN;
    __shared__ uint32_t As[2048];   // [kk(2)][mt(8)][lane][4]
    __shared__ uint32_t Bs[1024];   // [kk(2)][np(4)][lane][4]

    int tid = threadIdx.x;
    int warp = tid >> 5, lane = tid & 31;
    int mt0 = (warp & 3) * 2;
    int np0 = (warp >> 2) * 2;   // 2 n-pairs = 4 ntiles = 32 cols
    int g = lane >> 2, tg = lane & 3;

    float acc[2][4][4] = {};
    uint4 ar[2], br;

    const int KB = K / 32;

    auto load_regs = [&](int kb) {
        int k0 = kb * 32;
        #pragma unroll
        for (int i = 0; i < 2; i++) {
            int f4 = i*256 + tid;
            int row = f4 >> 2, c8 = f4 & 3;
            int gm = m0 + row;
            ar[i] = (gm < M) ? *(const uint4*)(A + (long)gm*lda + k0 + c8*8)
                             : make_uint4(0u,0u,0u,0u);
        }
        {
            int n = tid >> 2, c8 = tid & 3;
            int gn = n0 + n;
            br = (gn < N) ? *(const uint4*)(B + (long)gn*ldb + k0 + c8*8)
                          : make_uint4(0u,0u,0u,0u);
        }
    };

    auto sts = [&]() {
        #pragma unroll
        for (int i = 0; i < 2; i++) {
            int f4 = i*256 + tid;
            int row = f4 >> 2, c8 = f4 & 3;
            int kk = c8 >> 1, kh = c8 & 1;
            int mt = row >> 4, w = row & 15, gg = w & 7, rh = w >> 3;
            int base = ((kk*8 + mt)*32 + gg*4)*4 + kh*2 + rh;
            As[base +  0] = ar[i].x;
            As[base +  4] = ar[i].y;
            As[base +  8] = ar[i].z;
            As[base + 12] = ar[i].w;
        }
        {
            int n = tid >> 2, c8 = tid & 3;
            int kk = c8 >> 1, kh = c8 & 1;
            int nt = n >> 3, gc = n & 7, np = nt >> 1, sub = nt & 1;
            int base = ((kk*4 + np)*32 + gc*4)*4 + sub*2 + kh;
            Bs[base +  0] = br.x;
            Bs[base +  4] = br.y;
            Bs[base +  8] = br.z;
            Bs[base + 12] = br.w;
        }
    };

    load_regs(0);
    sts();
    __syncthreads();

    for (int kb = 0; kb < KB; kb++) {
        if (kb + 1 < KB) load_regs(kb + 1);

        #pragma unroll
        for (int kk = 0; kk < 2; kk++) {
            uint4 a4[2];
            a4[0] = *(const uint4*)&As[((kk*8 + mt0    )*32 + lane)*4];
            a4[1] = *(const uint4*)&As[((kk*8 + mt0 + 1)*32 + lane)*4];
            uint4 bp[2];
            bp[0] = *(const uint4*)&Bs[((kk*4 + np0    )*32 + lane)*4];
            bp[1] = *(const uint4*)&Bs[((kk*4 + np0 + 1)*32 + lane)*4];
            #pragma unroll
            for (int i = 0; i < 2; i++) {
                uint32_t a[4] = { a4[i].x, a4[i].y, a4[i].z, a4[i].w };
                #pragma unroll
                for (int p = 0; p < 2; p++) {
                    mma_f16(acc[i][2*p    ], a, bp[p].x, bp[p].y);
                    mma_f16(acc[i][2*p + 1], a, bp[p].z, bp[p].w);
                }
            }
        }

        if (kb + 1 < KB) {
            __syncthreads();
            sts();
            __syncthreads();
        }
    }

    #pragma unroll
    for (int i = 0; i < 2; i++) {
        #pragma unroll
        for (int rs = 0; rs < 2; rs++) {
            int gm = m0 + (mt0 + i)*16 + g + rs*8;
            if (gm >= M) continue;
            #pragma unroll
            for (int j = 0; j < 4; j++) {
                int gn = n0 + (np0*2 + j)*8 + tg*2;
                if (gn >= N) continue;
                long off = (long)gm*ldc + gn;
                float v0 = acc[i][j][rs*2+0];
                float v1 = acc[i][j][rs*2+1];
                if (ACC) { v0 += ld_c(&C[off]); v1 += ld_c(&C[off+1]); }
                st_c(&C[off    ], v0);
                st_c(&C[off + 1], v1);
            }
        }
    }
}

// ==================== FLASH ATTENTION (fp16 in, fp32 accum) ====================
// grid (3, BATCH*NHEAD), block 256. Per CTA: 128 q rows, kv tiles of 64.
__global__ __launch_bounds__(256)
void flash_kernel(const __half* __restrict__ qkv, __half* __restrict__ ctx)
{
    __shared__ uint32_t ks[2048];   // K frags: [kk(4)][nt(8)][lane][2]
    __shared__ uint32_t vs[2048];   // V frags (B non-transposed): same shape
    __shared__ uint32_t ps[4096];   // P A-frags: [kk(4)][mt=warp(8)][lane][4]

    int tid = threadIdx.x, warp = tid >> 5, lane = tid & 31;
    int g = lane >> 2, tg = lane & 3;
    int bh = blockIdx.y;
    int b = bh >> 4, h = bh & 15;
    int m0 = blockIdx.x * 128;

    const __half* qb = qkv + (long)b*SEQ*QKVD + h*HDIM;
    const __half* kb = qkv + (long)b*SEQ*QKVD + DIM + h*HDIM;
    const __half* vb = qkv + (long)b*SEQ*QKVD + 2*DIM + h*HDIM;

    int r0 = m0 + warp*16 + g;
    int r1 = r0 + 8;

    // q A-fragments in registers (4 kk-steps of k16)
    uint32_t qa[4][4];
    #pragma unroll
    for (int kk = 0; kk < 4; kk++) {
        qa[kk][0] = (r0 < SEQ) ? *(const uint32_t*)(qb + (long)r0*QKVD + kk*16 + 2*tg)     : 0u;
        qa[kk][1] = (r1 < SEQ) ? *(const uint32_t*)(qb + (long)r1*QKVD + kk*16 + 2*tg)     : 0u;
        qa[kk][2] = (r0 < SEQ) ? *(const uint32_t*)(qb + (long)r0*QKVD + kk*16 + 8 + 2*tg) : 0u;
        qa[kk][3] = (r1 < SEQ) ? *(const uint32_t*)(qb + (long)r1*QKVD + kk*16 + 8 + 2*tg) : 0u;
    }

    float o[8][4] = {};
    float m0r = -1e30f, m1r = -1e30f, l0r = 0.f, l1r = 0.f;

    for (int j = 0; j < 5; j++) {
        int kv0 = j * 64;
        // K tile: 64 rows x 64 halves -> BT frag layout
        #pragma unroll
        for (int i = 0; i < 2; i++) {
            int f4 = i*256 + tid;
            int n = f4 >> 3, c8 = f4 & 7;
            int gr = kv0 + n;
            uint4 v = (gr < SEQ) ? *(const uint4*)(kb + (long)gr*QKVD + c8*8)
                                 : make_uint4(0u,0u,0u,0u);
            int kk = c8 >> 1, kh = c8 & 1;
            int nt = n >> 3, gc = n & 7;
            int base = ((kk*8 + nt)*32 + gc*4)*2 + kh;
            ks[base + 0] = v.x;
            ks[base + 2] = v.y;
            ks[base + 4] = v.z;
            ks[base + 6] = v.w;
        }
        // V tile: pair k-rows to build half2 along k
        {
            int kvpair = tid >> 3, nt = tid & 7;
            int rA = kv0 + kvpair*2, rB = rA + 1;
            union { uint4 u; __half hx[8]; } ua, ub;
            ua.u = (rA < SEQ) ? *(const uint4*)(vb + (long)rA*QKVD + nt*8) : make_uint4(0u,0u,0u,0u);
            ub.u = (rB < SEQ) ? *(const uint4*)(vb + (long)rB*QKVD + nt*8) : make_uint4(0u,0u,0u,0u);
            int klocal = kvpair*2;
            int kk = klocal >> 4, kin = klocal & 15;
            int kh = kin >> 3, t = (kin & 7) >> 1;
            #pragma unroll
            for (int jj = 0; jj < 8; jj++) {
                half2 h2 = __halves2half2(ua.hx[jj], ub.hx[jj]);
                vs[((kk*8 + nt)*32 + jj*4 + t)*2 + kh] = *reinterpret_cast<uint32_t*>(&h2);
            }
        }
        __syncthreads();

        // s = q @ k^T
        float s[8][4] = {};
        #pragma unroll
        for (int kk = 0; kk < 4; kk++) {
            #pragma unroll
            for (int nt = 0; nt < 8; nt++) {
                uint2 bb = *(const uint2*)&ks[((kk*8 + nt)*32 + lane)*2];
                mma_f16(s[nt], qa[kk], bb.x, bb.y);
            }
        }

        // scale + mask + online softmax
        float tmax0 = -1e30f, tmax1 = -1e30f;
        #pragma unroll
        for (int nt = 0; nt < 8; nt++) {
            int c0 = kv0 + nt*8 + 2*tg;
            s[nt][0] = (c0     < SEQ) ? s[nt][0]*ATTN_SCALE : -1e30f;
            s[nt][1] = (c0 + 1 < SEQ) ? s[nt][1]*ATTN_SCALE : -1e30f;
            s[nt][2] = (c0     < SEQ) ? s[nt][2]*ATTN_SCALE : -1e30f;
            s[nt][3] = (c0 + 1 < SEQ) ? s[nt][3]*ATTN_SCALE : -1e30f;
            tmax0 = fmaxf(tmax0, fmaxf(s[nt][0], s[nt][1]));
            tmax1 = fmaxf(tmax1, fmaxf(s[nt][2], s[nt][3]));
        }
        tmax0 = fmaxf(tmax0, __shfl_xor_sync(0xffffffffu, tmax0, 1));
        tmax0 = fmaxf(tmax0, __shfl_xor_sync(0xffffffffu, tmax0, 2));
        tmax1 = fmaxf(tmax1, __shfl_xor_sync(0xffffffffu, tmax1, 1));
        tmax1 = fmaxf(tmax1, __shfl_xor_sync(0xffffffffu, tmax1, 2));
        float nm0 = fmaxf(m0r, tmax0), nm1 = fmaxf(m1r, tmax1);
        float f0 = __expf(m0r - nm0), f1 = __expf(m1r - nm1);

        float sum0 = 0.f, sum1 = 0.f;
        #pragma unroll
        for (int nt = 0; nt < 8; nt++) {
            float p0 = __expf(s[nt][0] - nm0);
            float p1 = __expf(s[nt][1] - nm0);
            float p2 = __expf(s[nt][2] - nm1);
            float p3 = __expf(s[nt][3] - nm1);
            sum0 += p0 + p1;
            sum1 += p2 + p3;
            // write P directly into this thread's own A-frag slots (no sync needed)
            int kkp = nt >> 1, kh = nt & 1;
            int base = ((kkp*8 + warp)*32 + lane)*4 + kh*2;
            half2 h01 = __floats2half2_rn(p0, p1);
            half2 h23 = __floats2half2_rn(p2, p3);
            ps[base + 0] = *reinterpret_cast<uint32_t*>(&h01);
            ps[base + 1] = *reinterpret_cast<uint32_t*>(&h23);
        }
        sum0 += __shfl_xor_sync(0xffffffffu, sum0, 1);
        sum0 += __shfl_xor_sync(0xffffffffu, sum0, 2);
        sum1 += __shfl_xor_sync(0xffffffffu, sum1, 1);
        sum1 += __shfl_xor_sync(0xffffffffu, sum1, 2);
        l0r = l0r*f0 + sum0;
        l1r = l1r*f1 + sum1;
        m0r = nm0; m1r = nm1;
        #pragma unroll
        for (int nt = 0; nt < 8; nt++) {
            o[nt][0] *= f0; o[nt][1] *= f0;
            o[nt][2] *= f1; o[nt][3] *= f1;
        }

        // o += p @ v
        #pragma unroll
        for (int kk = 0; kk < 4; kk++) {
            uint4 p4 = *(const uint4*)&ps[((kk*8 + warp)*32 + lane)*4];
            uint32_t pa[4] = { p4.x, p4.y, p4.z, p4.w };
            #pragma unroll
            for (int nt = 0; nt < 8; nt++) {
                uint2 vv = *(const uint2*)&vs[((kk*8 + nt)*32 + lane)*2];
                mma_f16(o[nt], pa, vv.x, vv.y);
            }
        }
        __syncthreads();
    }

    // write ctx = o / l (fp16)
    float inv0 = 1.f / l0r, inv1 = 1.f / l1r;
    __half* cb = ctx + (long)b*SEQ*DIM + h*HDIM;
    #pragma unroll
    for (int nt = 0; nt < 8; nt++) {
        int col = nt*8 + 2*tg;
        if (r0 < SEQ) {
            half2 h2 = __floats2half2_rn(o[nt][0]*inv0, o[nt][1]*inv0);
            *reinterpret_cast<half2*>(cb + (long)r0*DIM + col) = h2;
        }
        if (r1 < SEQ) {
            half2 h2 = __floats2half2_rn(o[nt][2]*inv1, o[nt][3]*inv1);
            *reinterpret_cast<half2*>(cb + (long)r1*DIM + col) = h2;
        }
    }
}

// ---------------- host launch ----------------
static void* dsym(const void* symbol) { void* p = nullptr; cudaGetSymbolAddress(&p, symbol); return p; }
static inline dim3 hgrid(int N, int M, int Z) { return dim3((N+TBN-1)/TBN, (M+127)/128, Z); }

extern "C" void kernel_launch(void* const* d_in, const int* in_sizes, int n_in,
                              void* d_out, int out_size)
{
    const float* x   = (const float*)d_in[0];
    const float* gw1 = (const float*)d_in[1];
    const float* gb1 = (const float*)d_in[2];
    const float* gw2 = (const float*)d_in[3];
    const float* gb2 = (const float*)d_in[4];
    const float* Wm[4]; const float* Ue[4]; const float* Se[4]; const float* Ve[4]; const float* bi[4];
    for (int p = 0; p < 4; p++) {
        Wm[p] = (const float*)d_in[5 + p*5 + 0];
        Ue[p] = (const float*)d_in[5 + p*5 + 1];
        Se[p] = (const float*)d_in[5 + p*5 + 2];
        Ve[p] = (const float*)d_in[5 + p*5 + 3];
        bi[p] = (const float*)d_in[5 + p*5 + 4];
    }
    float* out = (float*)d_out;

    int*    idxp   = (int*)dsym(g_idx);
    float*  gatesp = (float*)dsym(g_gates);
    float*  pooled = (float*)dsym(g_pooled);
    float*  bcat   = (float*)dsym(g_bcat);
    __half* xh     = (__half*)dsym(g_xh);
    __half* Wmh    = (__half*)dsym(g_Wmh);
    __half* Vw     = (__half*)dsym(g_Vw);
    __half* Uw     = (__half*)dsym(g_Uw);
    __half* tbuf   = (__half*)dsym(g_t);
    __half* qkv    = (__half*)dsym(g_qkv);
    __half* ctx    = (__half*)dsym(g_ctx);

    const long VW_PER = (long)BATCH*32*DIM;
    const long UW_PER = (long)BATCH*DIM*32;
    const long T_PER  = (long)BATCH*SEQ*32;

    cvt_kernel<<<1184, 256>>>(x, xh, (long)MROWS*DIM);                             // 0
    cvt4_kernel<<<2048, 256>>>(Wm[0], Wm[1], Wm[2], Wm[3], Wmh);                   // 1
    concat_bias_kernel<<<12, 256>>>(bi[0], bi[1], bi[2], bcat);                    // 2
    pool_kernel<<<dim3(8, BATCH), 256>>>(x, pooled);                               // 3
    gating_kernel<<<BATCH, 256>>>(pooled, gw1, gb1, gw2, gb2, idxp, gatesp);       // 4

    // 5: fused main projection qkv = x @ [Wq|Wk|Wv]^T + bcat (fp16 out)
    hgemm_wide<__half><<<dim3(QKVD/128, (MROWS + 127)/128), 256>>>(
        xh, Wmh, bcat, qkv, MROWS, QKVD);

    // 6: fused expert folding
    build_uv_kernel<<<128, 256>>>(Ue[0], Ue[1], Ue[2], Ue[3],
                                  Se[0], Se[1], Se[2], Se[3],
                                  Ve[0], Ve[1], Ve[2], Ve[3],
                                  idxp, gatesp, Vw, Uw);

    // 7: fused xV for q,k,v: t[p,b] = x_b @ Vw[p,b]^T  (z = p*32+b)
    hgemm<false,__half><<<hgrid(32, SEQ, 3*BATCH), 256>>>(
        xh, Vw, tbuf,
        SEQ, 32, DIM, DIM, DIM, 32,
        0, (long)SD, VW_PER, (long)32*DIM, T_PER, (long)SEQ*32, BATCH);

    // 8: fused expert accumulate: qkv[:, p*1024 + n] += t @ Uw^T
    hgemm<true,__half><<<hgrid(DIM, SEQ, 3*BATCH), 256>>>(
        tbuf, Uw, qkv,
        SEQ, DIM, 32, 32, 32, QKVD,
        T_PER, (long)SEQ*32, UW_PER, (long)DIM*32, (long)DIM, (long)SEQ*QKVD, BATCH);

    // 9: flash attention
    flash_kernel<<<dim3(3, BATCH*NHEAD), 256>>>(qkv, ctx);

    // 10: ctx low-rank projection t3 = ctx @ Vw3^T
    hgemm<false,__half><<<hgrid(32, SEQ, BATCH), 256>>>(
        ctx, Vw + 3*VW_PER, tbuf + 3*T_PER,
        SEQ, 32, DIM, DIM, DIM, 32,
        0, (long)SD, 0, (long)32*DIM, 0, (long)SEQ*32, BATCH);

    // 11: out = ctx @ Wo^T + bo (fp32 out)
    hgemm_wide<float><<<dim3(DIM/128, (MROWS + 127)/128), 256>>>(
        ctx, Wmh + 3ll*DIM*DIM, bi[3], out, MROWS, DIM);

    // 12: out += t3 @ Uw3^T (fp32 accumulate)
    hgemm<true,float><<<hgrid(DIM, SEQ, BATCH), 256>>>(
        tbuf + 3*T_PER, Uw + 3*UW_PER, out,
        SEQ, DIM, 32, 32, 32, DIM,
        0, (long)SEQ*32, 0, (long)DIM*32, 0, (long)SD, BATCH);
}

// round 9
// speedup vs baseline: 4.2741x; 1.1468x over previous
#include <cuda_runtime.h>
#include <cuda_fp16.h>
#include <math.h>
#include <stdint.h>

// ---------------- problem constants ----------------
#define BATCH 32
#define SEQ   257
#define DIM   1024
#define QKVD  3072
#define NHEAD 16
#define HDIM  64
#define NEXP  8
#define TOPK  2
#define RANK  16
#define GHID  256
#define SD    (SEQ*DIM)
#define MROWS (BATCH*SEQ)        // 8224
#define MBLK  65                 // ceil(8224/128)
#define ATTN_SCALE 0.125f

// ---------------- static device scratch ----------------
__device__ int   g_idx[BATCH*TOPK];
__device__ float g_gates[BATCH*TOPK];
__device__ float g_pooled[BATCH*DIM];
__device__ float g_bcat[QKVD];
__device__ __align__(16) __half   g_xh [MROWS*DIM];
__device__ __align__(16) uint32_t g_xhp[(long)MBLK*32*2048];    // permuted x (A frag order)
__device__ __align__(16) uint32_t g_Wmp[(long)32*32*2048];      // permuted weights (B frag order)
__device__ __align__(16) uint32_t g_ctxp[(long)MBLK*32*2048];   // permuted ctx
__device__ __align__(16) __half g_Vw[4ll*BATCH*32*DIM];
__device__ __align__(16) __half g_Uw[4ll*BATCH*DIM*32];
__device__ __align__(16) __half g_t [4ll*BATCH*SEQ*32];
__device__ __align__(16) __half g_qkv[(long)(MROWS+32)*QKVD];
__device__ __align__(16) __half g_ctx[MROWS*DIM];

__device__ __forceinline__ uint32_t smem_u32(const void* p) {
    uint32_t a;
    asm("{ .reg .u64 t; cvta.to.shared.u64 t, %1; cvt.u32.u64 %0, t; }" : "=r"(a) : "l"(p));
    return a;
}
__device__ __forceinline__ void cp16(uint32_t saddr, const void* g) {
    asm volatile("cp.async.cg.shared.global [%0], [%1], 16;" :: "r"(saddr), "l"(g));
}

// ---------------- conversion / permutation kernels ----------------
__global__ void cvt_kernel(const float* __restrict__ src, __half* __restrict__ dst, long n)
{
    long i = (long)blockIdx.x * blockDim.x + threadIdx.x;
    long stride = (long)gridDim.x * blockDim.x;
    for (; i < n; i += stride) dst[i] = __float2half_rn(src[i]);
}

// x (fp32 row-major) -> permuted fp16 A-frag layout. one uint4 per thread.
__global__ void cvt_xp_kernel(const float* __restrict__ x, uint32_t* __restrict__ xp)
{
    long idx = (long)blockIdx.x * 256 + threadIdx.x;
    if (idx >= (long)MBLK*32*512) return;
    int q  = (int)(idx & 511);
    long r = idx >> 9;
    int kc = (int)(r & 31);
    int mb = (int)(r >> 5);
    int kk = q >> 8, mt = (q >> 5) & 7, lane = q & 31;
    int g = lane >> 2, tg = lane & 3;
    int mbase = mb*128 + mt*16 + g;
    int kbase = kc*32 + kk*16 + tg*2;
    uint32_t v[4];
    #pragma unroll
    for (int j = 0; j < 4; j++) {
        int kh = j >> 1, rh = j & 1;
        int m = mbase + rh*8;
        int kz = kbase + kh*8;
        half2 h2 = (m < MROWS)
            ? __floats2half2_rn(x[(long)m*DIM + kz], x[(long)m*DIM + kz + 1])
            : __floats2half2_rn(0.f, 0.f);
        v[j] = *reinterpret_cast<uint32_t*>(&h2);
    }
    *(uint4*)(xp + idx*4) = make_uint4(v[0], v[1], v[2], v[3]);
}

// ctx (fp16 row-major) -> permuted A-frag layout
__global__ void ctxp_kernel(const __half* __restrict__ ctx, uint32_t* __restrict__ cp)
{
    long idx = (long)blockIdx.x * 256 + threadIdx.x;
    if (idx >= (long)MBLK*32*512) return;
    int q  = (int)(idx & 511);
    long r = idx >> 9;
    int kc = (int)(r & 31);
    int mb = (int)(r >> 5);
    int kk = q >> 8, mt = (q >> 5) & 7, lane = q & 31;
    int g = lane >> 2, tg = lane & 3;
    int mbase = mb*128 + mt*16 + g;
    int kbase = kc*32 + kk*16 + tg*2;
    uint32_t v[4];
    #pragma unroll
    for (int j = 0; j < 4; j++) {
        int kh = j >> 1, rh = j & 1;
        int m = mbase + rh*8;
        int kz = kbase + kh*8;
        v[j] = (m < MROWS) ? *(const uint32_t*)(ctx + (long)m*DIM + kz) : 0u;
    }
    *(uint4*)(cp + idx*4) = make_uint4(v[0], v[1], v[2], v[3]);
}

// 4 weight matrices (fp32 (N,K) row-major) -> permuted fp16 B-frag layout (4096 n-rows)
__global__ void cvt4p_kernel(const float* __restrict__ w0, const float* __restrict__ w1,
                             const float* __restrict__ w2, const float* __restrict__ w3,
                             uint32_t* __restrict__ wp)
{
    long idx = (long)blockIdx.x * 256 + threadIdx.x;
    if (idx >= (long)32*32*512) return;
    int q  = (int)(idx & 511);
    long r = idx >> 9;
    int kc = (int)(r & 31);
    int nb = (int)(r >> 5);
    int kk = q >> 8, np = (q >> 5) & 7, lane = q & 31;
    int gc = lane >> 2, tg = lane & 3;
    int kbase = kc*32 + kk*16 + tg*2;
    uint32_t v[4];
    #pragma unroll
    for (int j = 0; j < 4; j++) {
        int sub = j >> 1, kh = j & 1;
        int n = nb*128 + np*16 + sub*8 + gc;
        int p = n >> 10, row = n & 1023;
        const float* w = (p == 0) ? w0 : (p == 1) ? w1 : (p == 2) ? w2 : w3;
        int kz = kbase + kh*8;
        half2 h2 = __floats2half2_rn(w[(long)row*DIM + kz], w[(long)row*DIM + kz + 1]);
        v[j] = *reinterpret_cast<uint32_t*>(&h2);
    }
    *(uint4*)(wp + idx*4) = make_uint4(v[0], v[1], v[2], v[3]);
}

__global__ void concat_bias_kernel(const float* __restrict__ b0, const float* __restrict__ b1,
                                   const float* __restrict__ b2, float* __restrict__ dst)
{
    int i = blockIdx.x * 256 + threadIdx.x;
    if (i < DIM) dst[i] = b0[i];
    else if (i < 2*DIM) dst[i] = b1[i - DIM];
    else if (i < 3*DIM) dst[i] = b2[i - 2*DIM];
}

// ---------------- pooling (fp32, exact) ----------------
__global__ void pool_kernel(const float* __restrict__ x, float* __restrict__ pooled)
{
    int b = blockIdx.y;
    int d = blockIdx.x * 128 + (threadIdx.x & 127);
    int half = threadIdx.x >> 7;
    const float* xb = x + (long)b*SD + d;
    int t0 = half * 129;
    int t1 = half ? SEQ : 129;
    float s = 0.f;
    for (int t = t0; t < t1; t++) s += xb[(long)t*DIM];
    __shared__ float red[256];
    red[threadIdx.x] = s;
    __syncthreads();
    if (half == 0)
        pooled[b*DIM + d] = (red[threadIdx.x] + red[threadIdx.x + 128]) * (1.0f / SEQ);
}

// ---------------- gating MLP (exact fp32) ----------------
__global__ void gating_kernel(const float* __restrict__ pooled,
                              const float* __restrict__ gw1, const float* __restrict__ gb1,
                              const float* __restrict__ gw2, const float* __restrict__ gb2,
                              int* __restrict__ idx, float* __restrict__ gates)
{
    int b = blockIdx.x;
    int tid = threadIdx.x;
    __shared__ float pl[DIM];
    __shared__ float h[GHID];
    __shared__ float logits[NEXP];

    for (int d = tid; d < DIM; d += 256) pl[d] = pooled[b*DIM + d];
    __syncthreads();
    {
        float s = gb1[tid];
        const float* w = gw1 + (long)tid * DIM;
        #pragma unroll 8
        for (int d = 0; d < DIM; d++) s += pl[d] * w[d];
        h[tid] = fmaxf(s, 0.f);
    }
    __syncthreads();
    if (tid < NEXP) {
        float s = gb2[tid];
        const float* w = gw2 + (long)tid * GHID;
        for (int g = 0; g < GHID; g++) s += h[g] * w[g];
        logits[tid] = s;
    }
    __syncthreads();
    if (tid == 0) {
        int i1 = 0; float v1 = logits[0];
        for (int e = 1; e < NEXP; e++) if (logits[e] > v1) { v1 = logits[e]; i1 = e; }
        int i2 = -1; float v2 = -3.0e38f;
        for (int e = 0; e < NEXP; e++) if (e != i1 && logits[e] > v2) { v2 = logits[e]; i2 = e; }
        float e2 = expf(v2 - v1);
        float inv = 1.f / (1.f + e2);
        idx[b*2] = i1; idx[b*2+1] = i2;
        gates[b*2] = inv; gates[b*2+1] = e2 * inv;
    }
}

// ---------------- fused fold (fp16 outputs) ----------------
__global__ void build_uv_kernel(const float* __restrict__ U0, const float* __restrict__ U1,
                                const float* __restrict__ U2, const float* __restrict__ U3,
                                const float* __restrict__ S0, const float* __restrict__ S1,
                                const float* __restrict__ S2, const float* __restrict__ S3,
                                const float* __restrict__ V0, const float* __restrict__ V1,
                                const float* __restrict__ V2, const float* __restrict__ V3,
                                const int* __restrict__ idx, const float* __restrict__ gates,
                                __half* __restrict__ VwAll, __half* __restrict__ UwAll)
{
    int p = blockIdx.x >> 5, b = blockIdx.x & 31;
    const float* U = (p == 0) ? U0 : (p == 1) ? U1 : (p == 2) ? U2 : U3;
    const float* Sg = (p == 0) ? S0 : (p == 1) ? S1 : (p == 2) ? S2 : S3;
    const float* V = (p == 0) ? V0 : (p == 1) ? V1 : (p == 2) ? V2 : V3;
    int tid = threadIdx.x;
    int e0 = idx[b*2], e1 = idx[b*2+1];
    float g0 = gates[b*2], g1 = gates[b*2+1];
    __half* vw = VwAll + ((long)p*BATCH + b) * 32 * DIM;
    __half* uw = UwAll + ((long)p*BATCH + b) * DIM * 32;

    for (int i = tid; i < 32*DIM; i += 256) {
        int j = i >> 10, d = i & (DIM-1);
        int k = j >> 4, r = j & 15;
        int e = k ? e1 : e0;
        vw[i] = __float2half_rn(Sg[e*RANK + r] * V[((long)e*RANK + r)*DIM + d]);
    }
    for (int i = tid; i < DIM*32; i += 256) {
        int n = i >> 5, j = i & 31;
        int k = j >> 4, r = j & 15;
        int e = k ? e1 : e0;
        float g = k ? g1 : g0;
        uw[i] = __float2half_rn(g * U[((long)e*DIM + n)*RANK + r]);
    }
}

// ---------------- FP16 MMA primitive ----------------
__device__ __forceinline__ void mma_f16(float c[4], const uint32_t a[4], const uint32_t b0, const uint32_t b1) {
    asm volatile(
        "mma.sync.aligned.m16n8k16.row.col.f32.f16.f16.f32 "
        "{%0,%1,%2,%3}, {%4,%5,%6,%7}, {%8,%9}, {%0,%1,%2,%3};"
        : "+f"(c[0]), "+f"(c[1]), "+f"(c[2]), "+f"(c[3])
        : "r"(a[0]), "r"(a[1]), "r"(a[2]), "r"(a[3]), "r"(b0), "r"(b1));
}

__device__ __forceinline__ float ld_c(const float* p) { return *p; }
__device__ __forceinline__ float ld_c(const __half* p) { return __half2float(*p); }
__device__ __forceinline__ void st_c(float* p, float v) { *p = v; }
__device__ __forceinline__ void st_c(__half* p, float v) { *p = __float2half_rn(v); }

// ==================== WIDE FP16 GEMM v2: permuted operands + cp.async 4-stage ======
// C[M,N] = A @ B^T + bias. Ap: [mblock][kchunk][2048 u32] frag order;
// Bp: [nblock][kchunk][2048 u32] frag order. K=1024 fixed.
template<typename CT>
__global__ __launch_bounds__(256, 2)
void hgemm_wide2(const uint32_t* __restrict__ Ap, const uint32_t* __restrict__ Bp,
                 const float* __restrict__ bias, CT* __restrict__ C, int M, int ldc)
{
    extern __shared__ uint32_t sh[];   // 4 stages x (A 2048 + B 2048) u32 = 64KB
    uint32_t shb = smem_u32(sh);
    int tid = threadIdx.x;
    int warp = tid >> 5, lane = tid & 31;
    int mt0 = (warp & 3) * 2;
    int np0 = (warp >> 2) * 4;
    int g = lane >> 2, tg = lane & 3;
    int m0 = blockIdx.y * 128, n0 = blockIdx.x * 128;

    const uint32_t* Ar = Ap + (long)blockIdx.y * 32 * 2048;
    const uint32_t* Br = Bp + (long)blockIdx.x * 32 * 2048;

    float acc[2][8][4] = {};

    auto issue = [&](int kc) {
        uint32_t d = shb + (uint32_t)(kc & 3) * 16384;
        const uint32_t* a = Ar + kc * 2048;
        const uint32_t* b = Br + kc * 2048;
        cp16(d +             tid*16, a + tid*4);
        cp16(d +  4096u +    tid*16, a + 1024 + tid*4);
        cp16(d +  8192u +    tid*16, b + tid*4);
        cp16(d + 12288u +    tid*16, b + 1024 + tid*4);
        asm volatile("cp.async.commit_group;");
    };

    issue(0);
    issue(1);

    for (int kc = 0; kc < 32; kc++) {
        if (kc + 2 < 32) {
            issue(kc + 2);
            asm volatile("cp.async.wait_group 2;");
        } else {
            asm volatile("cp.async.wait_group 0;");
        }
        __syncthreads();

        const uint32_t* As = sh + (kc & 3) * 4096;
        const uint32_t* Bs = As + 2048;
        #pragma unroll
        for (int kk = 0; kk < 2; kk++) {
            uint4 a4[2];
            a4[0] = *(const uint4*)&As[((kk*8 + mt0    )*32 + lane)*4];
            a4[1] = *(const uint4*)&As[((kk*8 + mt0 + 1)*32 + lane)*4];
            uint4 bp[4];
            #pragma unroll
            for (int p = 0; p < 4; p++)
                bp[p] = *(const uint4*)&Bs[((kk*8 + np0 + p)*32 + lane)*4];
            #pragma unroll
            for (int i = 0; i < 2; i++) {
                uint32_t a[4] = { a4[i].x, a4[i].y, a4[i].z, a4[i].w };
                #pragma unroll
                for (int p = 0; p < 4; p++) {
                    mma_f16(acc[i][2*p    ], a, bp[p].x, bp[p].y);
                    mma_f16(acc[i][2*p + 1], a, bp[p].z, bp[p].w);
                }
            }
        }
    }

    #pragma unroll
    for (int i = 0; i < 2; i++) {
        #pragma unroll
        for (int rs = 0; rs < 2; rs++) {
            int gm = m0 + (mt0 + i)*16 + g + rs*8;
            if (gm >= M) continue;
            #pragma unroll
            for (int j = 0; j < 8; j++) {
                int gn = n0 + (np0*2 + j)*8 + tg*2;
                long off = (long)gm*ldc + gn;
                st_c(&C[off    ], acc[i][j][rs*2+0] + bias[gn]);
                st_c(&C[off + 1], acc[i][j][rs*2+1] + bias[gn+1]);
            }
        }
    }
}

// ==================== general batched FP16 GEMM (B transposed (N,K)) ====================
#define TBN 64
template<bool ACC, typename CT>
__global__ __launch_bounds__(256, 2)
void hgemm(const __half* __restrict__ A, const __half* __restrict__ B,
           CT* __restrict__ C,
           int M, int N, int K, int lda, int ldb, int ldc,
           long sA1, long sA2, long sB1, long sB2, long sC1, long sC2, int zdiv)
{
    int z = blockIdx.z;
    long zq = z / zdiv, zr = z % zdiv;
    A += zq*sA1 + zr*sA2;
    B += zq*sB1 + zr*sB2;
    C += zq*sC1 + zr*sC2;

    int m0 = blockIdx.y * 128, n0 = blockIdx.x * TBN;
    __shared__ uint32_t As[2048];
    __shared__ uint32_t Bs[1024];

    int tid = threadIdx.x;
    int warp = tid >> 5, lane = tid & 31;
    int mt0 = (warp & 3) * 2;
    int np0 = (warp >> 2) * 2;
    int g = lane >> 2, tg = lane & 3;

    float acc[2][4][4] = {};
    uint4 ar[2], br;

    const int KB = K / 32;

    auto load_regs = [&](int kb) {
        int k0 = kb * 32;
        #pragma unroll
        for (int i = 0; i < 2; i++) {
            int f4 = i*256 + tid;
            int row = f4 >> 2, c8 = f4 & 3;
            int gm = m0 + row;
            ar[i] = (gm < M) ? *(const uint4*)(A + (long)gm*lda + k0 + c8*8)
                             : make_uint4(0u,0u,0u,0u);
        }
        {
            int n = tid >> 2, c8 = tid & 3;
            int gn = n0 + n;
            br = (gn < N) ? *(const uint4*)(B + (long)gn*ldb + k0 + c8*8)
                          : make_uint4(0u,0u,0u,0u);
        }
    };

    auto sts = [&]() {
        #pragma unroll
        for (int i = 0; i < 2; i++) {
            int f4 = i*256 + tid;
            int row = f4 >> 2, c8 = f4 & 3;
            int kk = c8 >> 1, kh = c8 & 1;
            int mt = row >> 4, w = row & 15, gg = w & 7, rh = w >> 3;
            int base = ((kk*8 + mt)*32 + gg*4)*4 + kh*2 + rh;
            As[base +  0] = ar[i].x;
            As[base +  4] = ar[i].y;
            As[base +  8] = ar[i].z;
            As[base + 12] = ar[i].w;
        }
        {
            int n = tid >> 2, c8 = tid & 3;
            int kk = c8 >> 1, kh = c8 & 1;
            int nt = n >> 3, gc = n & 7, np = nt >> 1, sub = nt & 1;
            int base = ((kk*4 + np)*32 + gc*4)*4 + sub*2 + kh;
            Bs[base +  0] = br.x;
            Bs[base +  4] = br.y;
            Bs[base +  8] = br.z;
            Bs[base + 12] = br.w;
        }
    };

    load_regs(0);
    sts();
    __syncthreads();

    for (int kb = 0; kb < KB; kb++) {
        if (kb + 1 < KB) load_regs(kb + 1);

        #pragma unroll
        for (int kk = 0; kk < 2; kk++) {
            uint4 a4[2];
            a4[0] = *(const uint4*)&As[((kk*8 + mt0    )*32 + lane)*4];
            a4[1] = *(const uint4*)&As[((kk*8 + mt0 + 1)*32 + lane)*4];
            uint4 bp[2];
            bp[0] = *(const uint4*)&Bs[((kk*4 + np0    )*32 + lane)*4];
            bp[1] = *(const uint4*)&Bs[((kk*4 + np0 + 1)*32 + lane)*4];
            #pragma unroll
            for (int i = 0; i < 2; i++) {
                uint32_t a[4] = { a4[i].x, a4[i].y, a4[i].z, a4[i].w };
                #pragma unroll
                for (int p = 0; p < 2; p++) {
                    mma_f16(acc[i][2*p    ], a, bp[p].x, bp[p].y);
                    mma_f16(acc[i][2*p + 1], a, bp[p].z, bp[p].w);
                }
            }
        }

        if (kb + 1 < KB) {
            __syncthreads();
            sts();
            __syncthreads();
        }
    }

    #pragma unroll
    for (int i = 0; i < 2; i++) {
        #pragma unroll
        for (int rs = 0; rs < 2; rs++) {
            int gm = m0 + (mt0 + i)*16 + g + rs*8;
            if (gm >= M) continue;
            #pragma unroll
            for (int j = 0; j < 4; j++) {
                int gn = n0 + (np0*2 + j)*8 + tg*2;
                if (gn >= N) continue;
                long off = (long)gm*ldc + gn;
                float v0 = acc[i][j][rs*2+0];
                float v1 = acc[i][j][rs*2+1];
                if (ACC) { v0 += ld_c(&C[off]); v1 += ld_c(&C[off+1]); }
                st_c(&C[off    ], v0);
                st_c(&C[off + 1], v1);
            }
        }
    }
}

// ==================== FLASH ATTENTION (fp16 in, fp32 accum) ====================
__global__ __launch_bounds__(256)
void flash_kernel(const __half* __restrict__ qkv, __half* __restrict__ ctx)
{
    __shared__ uint32_t ks[2048];
    __shared__ uint32_t vs[2048];
    __shared__ uint32_t ps[4096];

    int tid = threadIdx.x, warp = tid >> 5, lane = tid & 31;
    int g = lane >> 2, tg = lane & 3;
    int bh = blockIdx.y;
    int b = bh >> 4, h = bh & 15;
    int m0 = blockIdx.x * 128;

    const __half* qb = qkv + (long)b*SEQ*QKVD + h*HDIM;
    const __half* kb = qkv + (long)b*SEQ*QKVD + DIM + h*HDIM;
    const __half* vb = qkv + (long)b*SEQ*QKVD + 2*DIM + h*HDIM;

    int r0 = m0 + warp*16 + g;
    int r1 = r0 + 8;

    uint32_t qa[4][4];
    #pragma unroll
    for (int kk = 0; kk < 4; kk++) {
        qa[kk][0] = (r0 < SEQ) ? *(const uint32_t*)(qb + (long)r0*QKVD + kk*16 + 2*tg)     : 0u;
        qa[kk][1] = (r1 < SEQ) ? *(const uint32_t*)(qb + (long)r1*QKVD + kk*16 + 2*tg)     : 0u;
        qa[kk][2] = (r0 < SEQ) ? *(const uint32_t*)(qb + (long)r0*QKVD + kk*16 + 8 + 2*tg) : 0u;
        qa[kk][3] = (r1 < SEQ) ? *(const uint32_t*)(qb + (long)r1*QKVD + kk*16 + 8 + 2*tg) : 0u;
    }

    float o[8][4] = {};
    float m0r = -1e30f, m1r = -1e30f, l0r = 0.f, l1r = 0.f;

    for (int j = 0; j < 5; j++) {
        int kv0 = j * 64;
        #pragma unroll
        for (int i = 0; i < 2; i++) {
            int f4 = i*256 + tid;
            int n = f4 >> 3, c8 = f4 & 7;
            int gr = kv0 + n;
            uint4 v = (gr < SEQ) ? *(const uint4*)(kb + (long)gr*QKVD + c8*8)
                                 : make_uint4(0u,0u,0u,0u);
            int kk = c8 >> 1, kh = c8 & 1;
            int nt = n >> 3, gc = n & 7;
            int base = ((kk*8 + nt)*32 + gc*4)*2 + kh;
            ks[base + 0] = v.x;
            ks[base + 2] = v.y;
            ks[base + 4] = v.z;
            ks[base + 6] = v.w;
        }
        {
            int kvpair = tid >> 3, nt = tid & 7;
            int rA = kv0 + kvpair*2, rB = rA + 1;
            union { uint4 u; __half hx[8]; } ua, ub;
            ua.u = (rA < SEQ) ? *(const uint4*)(vb + (long)rA*QKVD + nt*8) : make_uint4(0u,0u,0u,0u);
            ub.u = (rB < SEQ) ? *(const uint4*)(vb + (long)rB*QKVD + nt*8) : make_uint4(0u,0u,0u,0u);
            int klocal = kvpair*2;
            int kk = klocal >> 4, kin = klocal & 15;
            int kh = kin >> 3, t = (kin & 7) >> 1;
            #pragma unroll
            for (int jj = 0; jj < 8; jj++) {
                half2 h2 = __halves2half2(ua.hx[jj], ub.hx[jj]);
                vs[((kk*8 + nt)*32 + jj*4 + t)*2 + kh] = *reinterpret_cast<uint32_t*>(&h2);
            }
        }
        __syncthreads();

        float s[8][4] = {};
        #pragma unroll
        for (int kk = 0; kk < 4; kk++) {
            #pragma unroll
            for (int nt = 0; nt < 8; nt++) {
                uint2 bb = *(const uint2*)&ks[((kk*8 + nt)*32 + lane)*2];
                mma_f16(s[nt], qa[kk], bb.x, bb.y);
            }
        }

        float tmax0 = -1e30f, tmax1 = -1e30f;
        #pragma unroll
        for (int nt = 0; nt < 8; nt++) {
            int c0 = kv0 + nt*8 + 2*tg;
            s[nt][0] = (c0     < SEQ) ? s[nt][0]*ATTN_SCALE : -1e30f;
            s[nt][1] = (c0 + 1 < SEQ) ? s[nt][1]*ATTN_SCALE : -1e30f;
            s[nt][2] = (c0     < SEQ) ? s[nt][2]*ATTN_SCALE : -1e30f;
            s[nt][3] = (c0 + 1 < SEQ) ? s[nt][3]*ATTN_SCALE : -1e30f;
            tmax0 = fmaxf(tmax0, fmaxf(s[nt][0], s[nt][1]));
            tmax1 = fmaxf(tmax1, fmaxf(s[nt][2], s[nt][3]));
        }
        tmax0 = fmaxf(tmax0, __shfl_xor_sync(0xffffffffu, tmax0, 1));
        tmax0 = fmaxf(tmax0, __shfl_xor_sync(0xffffffffu, tmax0, 2));
        tmax1 = fmaxf(tmax1, __shfl_xor_sync(0xffffffffu, tmax1, 1));
        tmax1 = fmaxf(tmax1, __shfl_xor_sync(0xffffffffu, tmax1, 2));
        float nm0 = fmaxf(m0r, tmax0), nm1 = fmaxf(m1r, tmax1);
        float f0 = __expf(m0r - nm0), f1 = __expf(m1r - nm1);

        float sum0 = 0.f, sum1 = 0.f;
        #pragma unroll
        for (int nt = 0; nt < 8; nt++) {
            float p0 = __expf(s[nt][0] - nm0);
            float p1 = __expf(s[nt][1] - nm0);
            float p2 = __expf(s[nt][2] - nm1);
            float p3 = __expf(s[nt][3] - nm1);
            sum0 += p0 + p1;
            sum1 += p2 + p3;
            int kkp = nt >> 1, kh = nt & 1;
            int base = ((kkp*8 + warp)*32 + lane)*4 + kh*2;
            half2 h01 = __floats2half2_rn(p0, p1);
            half2 h23 = __floats2half2_rn(p2, p3);
            ps[base + 0] = *reinterpret_cast<uint32_t*>(&h01);
            ps[base + 1] = *reinterpret_cast<uint32_t*>(&h23);
        }
        sum0 += __shfl_xor_sync(0xffffffffu, sum0, 1);
        sum0 += __shfl_xor_sync(0xffffffffu, sum0, 2);
        sum1 += __shfl_xor_sync(0xffffffffu, sum1, 1);
        sum1 += __shfl_xor_sync(0xffffffffu, sum1, 2);
        l0r = l0r*f0 + sum0;
        l1r = l1r*f1 + sum1;
        m0r = nm0; m1r = nm1;
        #pragma unroll
        for (int nt = 0; nt < 8; nt++) {
            o[nt][0] *= f0; o[nt][1] *= f0;
            o[nt][2] *= f1; o[nt][3] *= f1;
        }

        #pragma unroll
        for (int kk = 0; kk < 4; kk++) {
            uint4 p4 = *(const uint4*)&ps[((kk*8 + warp)*32 + lane)*4];
            uint32_t pa[4] = { p4.x, p4.y, p4.z, p4.w };
            #pragma unroll
            for (int nt = 0; nt < 8; nt++) {
                uint2 vv = *(const uint2*)&vs[((kk*8 + nt)*32 + lane)*2];
                mma_f16(o[nt], pa, vv.x, vv.y);
            }
        }
        __syncthreads();
    }

    float inv0 = 1.f / l0r, inv1 = 1.f / l1r;
    __half* cb = ctx + (long)b*SEQ*DIM + h*HDIM;
    #pragma unroll
    for (int nt = 0; nt < 8; nt++) {
        int col = nt*8 + 2*tg;
        if (r0 < SEQ) {
            half2 h2 = __floats2half2_rn(o[nt][0]*inv0, o[nt][1]*inv0);
            *reinterpret_cast<half2*>(cb + (long)r0*DIM + col) = h2;
        }
        if (r1 < SEQ) {
            half2 h2 = __floats2half2_rn(o[nt][2]*inv1, o[nt][3]*inv1);
            *reinterpret_cast<half2*>(cb + (long)r1*DIM + col) = h2;
        }
    }
}

// ---------------- host launch ----------------
static void* dsym(const void* symbol) { void* p = nullptr; cudaGetSymbolAddress(&p, symbol); return p; }
static inline dim3 hgrid(int N, int M, int Z) { return dim3((N+TBN-1)/TBN, (M+127)/128, Z); }
#define WIDE2_SMEM 65536

extern "C" void kernel_launch(void* const* d_in, const int* in_sizes, int n_in,
                              void* d_out, int out_size)
{
    const float* x   = (const float*)d_in[0];
    const float* gw1 = (const float*)d_in[1];
    const float* gb1 = (const float*)d_in[2];
    const float* gw2 = (const float*)d_in[3];
    const float* gb2 = (const float*)d_in[4];
    const float* Wm[4]; const float* Ue[4]; const float* Se[4]; const float* Ve[4]; const float* bi[4];
    for (int p = 0; p < 4; p++) {
        Wm[p] = (const float*)d_in[5 + p*5 + 0];
        Ue[p] = (const float*)d_in[5 + p*5 + 1];
        Se[p] = (const float*)d_in[5 + p*5 + 2];
        Ve[p] = (const float*)d_in[5 + p*5 + 3];
        bi[p] = (const float*)d_in[5 + p*5 + 4];
    }
    float* out = (float*)d_out;

    int*      idxp   = (int*)dsym(g_idx);
    float*    gatesp = (float*)dsym(g_gates);
    float*    pooled = (float*)dsym(g_pooled);
    float*    bcat   = (float*)dsym(g_bcat);
    __half*   xh     = (__half*)dsym(g_xh);
    uint32_t* xhp    = (uint32_t*)dsym(g_xhp);
    uint32_t* Wmp    = (uint32_t*)dsym(g_Wmp);
    uint32_t* ctxp   = (uint32_t*)dsym(g_ctxp);
    __half*   Vw     = (__half*)dsym(g_Vw);
    __half*   Uw     = (__half*)dsym(g_Uw);
    __half*   tbuf   = (__half*)dsym(g_t);
    __half*   qkv    = (__half*)dsym(g_qkv);
    __half*   ctx    = (__half*)dsym(g_ctx);

    const long VW_PER = (long)BATCH*32*DIM;
    const long UW_PER = (long)BATCH*DIM*32;
    const long T_PER  = (long)BATCH*SEQ*32;

    cudaFuncSetAttribute(hgemm_wide2<__half>, cudaFuncAttributeMaxDynamicSharedMemorySize, WIDE2_SMEM);
    cudaFuncSetAttribute(hgemm_wide2<float>,  cudaFuncAttributeMaxDynamicSharedMemorySize, WIDE2_SMEM);

    // 0..2: dependencies of the wide QKV GEMM
    cvt_xp_kernel<<<(MBLK*32*512 + 255)/256, 256>>>(x, xhp);                       // 0
    cvt4p_kernel<<<(32*32*512 + 255)/256, 256>>>(Wm[0], Wm[1], Wm[2], Wm[3], Wmp); // 1
    concat_bias_kernel<<<12, 256>>>(bi[0], bi[1], bi[2], bcat);                    // 2

    // 3: fused main projection (placed 4th-launch slot for ncu capture)
    hgemm_wide2<__half><<<dim3(QKVD/128, MBLK), 256, WIDE2_SMEM>>>(
        xhp, Wmp, bcat, qkv, MROWS, QKVD);

    // 4..7: gating path + row-major fp16 x + expert folding
    cvt_kernel<<<1184, 256>>>(x, xh, (long)MROWS*DIM);                             // 4
    pool_kernel<<<dim3(8, BATCH), 256>>>(x, pooled);                               // 5
    gating_kernel<<<BATCH, 256>>>(pooled, gw1, gb1, gw2, gb2, idxp, gatesp);       // 6
    build_uv_kernel<<<128, 256>>>(Ue[0], Ue[1], Ue[2], Ue[3],
                                  Se[0], Se[1], Se[2], Se[3],
                                  Ve[0], Ve[1], Ve[2], Ve[3],
                                  idxp, gatesp, Vw, Uw);                           // 7

    // 8: fused xV for q,k,v
    hgemm<false,__half><<<hgrid(32, SEQ, 3*BATCH), 256>>>(
        xh, Vw, tbuf,
        SEQ, 32, DIM, DIM, DIM, 32,
        0, (long)SD, VW_PER, (long)32*DIM, T_PER, (long)SEQ*32, BATCH);

    // 9: fused expert accumulate
    hgemm<true,__half><<<hgrid(DIM, SEQ, 3*BATCH), 256>>>(
        tbuf, Uw, qkv,
        SEQ, DIM, 32, 32, 32, QKVD,
        T_PER, (long)SEQ*32, UW_PER, (long)DIM*32, (long)DIM, (long)SEQ*QKVD, BATCH);

    // 10: flash attention
    flash_kernel<<<dim3(3, BATCH*NHEAD), 256>>>(qkv, ctx);

    // 11: ctx low-rank projection (row-major ctx)
    hgemm<false,__half><<<hgrid(32, SEQ, BATCH), 256>>>(
        ctx, Vw + 3*VW_PER, tbuf + 3*T_PER,
        SEQ, 32, DIM, DIM, DIM, 32,
        0, (long)SD, 0, (long)32*DIM, 0, (long)SEQ*32, BATCH);

    // 12: permute ctx for the wide out-projection
    ctxp_kernel<<<(MBLK*32*512 + 255)/256, 256>>>(ctx, ctxp);

    // 13: out = ctx @ Wo^T + bo (fp32 out)
    hgemm_wide2<float><<<dim3(DIM/128, MBLK), 256, WIDE2_SMEM>>>(
        ctxp, Wmp + (long)24*32*2048, bi[3], out, MROWS, DIM);

    // 14: out += t3 @ Uw3^T (fp32 accumulate)
    hgemm<true,float><<<hgrid(DIM, SEQ, BATCH), 256>>>(
        tbuf + 3*T_PER, Uw + 3*UW_PER, out,
        SEQ, DIM, 32, 32, 32, DIM,
        0, (long)SEQ*32, 0, (long)DIM*32, 0, (long)SD, BATCH);
}

// round 10
// speedup vs baseline: 6.4757x; 1.5151x over previous
#include <cuda_runtime.h>
#include <cuda_fp16.h>
#include <math.h>
#include <stdint.h>

// ---------------- problem constants ----------------
#define BATCH 32
#define SEQ   257
#define DIM   1024
#define QKVD  3072
#define NHEAD 16
#define HDIM  64
#define NEXP  8
#define TOPK  2
#define RANK  16
#define GHID  256
#define SD    (SEQ*DIM)
#define MROWS (BATCH*SEQ)        // 8224
#define MBLK  65                 // ceil(8224/128)
#define ATTN_SCALE 0.125f

// ---------------- static device scratch ----------------
__device__ int   g_idx[BATCH*TOPK];
__device__ float g_gates[BATCH*TOPK];
__device__ float g_pooled[BATCH*DIM];
__device__ float g_bcat[QKVD];
__device__ __align__(16) __half   g_xh [MROWS*DIM];
__device__ __align__(16) uint32_t g_xhp[(long)MBLK*32*2048];    // permuted x (A frag order)
__device__ __align__(16) uint32_t g_Wmp[(long)32*32*2048];      // permuted weights (B frag order)
__device__ __align__(16) uint32_t g_ctxp[(long)MBLK*32*2048];   // permuted ctx
__device__ __align__(16) __half g_Vw[4ll*BATCH*32*DIM];
__device__ __align__(16) __half g_Uw[4ll*BATCH*DIM*32];
__device__ __align__(16) __half g_t [4ll*BATCH*SEQ*32];
__device__ __align__(16) __half g_qkv[(long)(MROWS+32)*QKVD];
__device__ __align__(16) __half g_ctx[MROWS*DIM];

__device__ __forceinline__ uint32_t smem_u32(const void* p) {
    uint32_t a;
    asm("{ .reg .u64 t; cvta.to.shared.u64 t, %1; cvt.u32.u64 %0, t; }" : "=r"(a) : "l"(p));
    return a;
}
__device__ __forceinline__ void cp16(uint32_t saddr, const void* g) {
    asm volatile("cp.async.cg.shared.global [%0], [%1], 16;" :: "r"(saddr), "l"(g));
}

// ---------------- conversion / permutation kernels ----------------
__global__ void cvt_kernel(const float* __restrict__ src, __half* __restrict__ dst, long n)
{
    long i = (long)blockIdx.x * blockDim.x + threadIdx.x;
    long stride = (long)gridDim.x * blockDim.x;
    for (; i < n; i += stride) dst[i] = __float2half_rn(src[i]);
}

// x (fp32 row-major) -> permuted fp16 A-frag layout. one uint4 per thread.
__global__ void cvt_xp_kernel(const float* __restrict__ x, uint32_t* __restrict__ xp)
{
    long idx = (long)blockIdx.x * 256 + threadIdx.x;
    if (idx >= (long)MBLK*32*512) return;
    int q  = (int)(idx & 511);
    long r = idx >> 9;
    int kc = (int)(r & 31);
    int mb = (int)(r >> 5);
    int kk = q >> 8, mt = (q >> 5) & 7, lane = q & 31;
    int g = lane >> 2, tg = lane & 3;
    int mbase = mb*128 + mt*16 + g;
    int kbase = kc*32 + kk*16 + tg*2;
    uint32_t v[4];
    #pragma unroll
    for (int j = 0; j < 4; j++) {
        int kh = j >> 1, rh = j & 1;
        int m = mbase + rh*8;
        int kz = kbase + kh*8;
        half2 h2 = (m < MROWS)
            ? __floats2half2_rn(x[(long)m*DIM + kz], x[(long)m*DIM + kz + 1])
            : __floats2half2_rn(0.f, 0.f);
        v[j] = *reinterpret_cast<uint32_t*>(&h2);
    }
    *(uint4*)(xp + idx*4) = make_uint4(v[0], v[1], v[2], v[3]);
}

// ctx (fp16 row-major) -> permuted A-frag layout
__global__ void ctxp_kernel(const __half* __restrict__ ctx, uint32_t* __restrict__ cp)
{
    long idx = (long)blockIdx.x * 256 + threadIdx.x;
    if (idx >= (long)MBLK*32*512) return;
    int q  = (int)(idx & 511);
    long r = idx >> 9;
    int kc = (int)(r & 31);
    int mb = (int)(r >> 5);
    int kk = q >> 8, mt = (q >> 5) & 7, lane = q & 31;
    int g = lane >> 2, tg = lane & 3;
    int mbase = mb*128 + mt*16 + g;
    int kbase = kc*32 + kk*16 + tg*2;
    uint32_t v[4];
    #pragma unroll
    for (int j = 0; j < 4; j++) {
        int kh = j >> 1, rh = j & 1;
        int m = mbase + rh*8;
        int kz = kbase + kh*8;
        v[j] = (m < MROWS) ? *(const uint32_t*)(ctx + (long)m*DIM + kz) : 0u;
    }
    *(uint4*)(cp + idx*4) = make_uint4(v[0], v[1], v[2], v[3]);
}

// 4 weight matrices (fp32 (N,K) row-major) -> permuted fp16 B-frag layout (4096 n-rows)
__global__ void cvt4p_kernel(const float* __restrict__ w0, const float* __restrict__ w1,
                             const float* __restrict__ w2, const float* __restrict__ w3,
                             uint32_t* __restrict__ wp)
{
    long idx = (long)blockIdx.x * 256 + threadIdx.x;
    if (idx >= (long)32*32*512) return;
    int q  = (int)(idx & 511);
    long r = idx >> 9;
    int kc = (int)(r & 31);
    int nb = (int)(r >> 5);
    int kk = q >> 8, np = (q >> 5) & 7, lane = q & 31;
    int gc = lane >> 2, tg = lane & 3;
    int kbase = kc*32 + kk*16 + tg*2;
    uint32_t v[4];
    #pragma unroll
    for (int j = 0; j < 4; j++) {
        int sub = j >> 1, kh = j & 1;
        int n = nb*128 + np*16 + sub*8 + gc;
        int p = n >> 10, row = n & 1023;
        const float* w = (p == 0) ? w0 : (p == 1) ? w1 : (p == 2) ? w2 : w3;
        int kz = kbase + kh*8;
        half2 h2 = __floats2half2_rn(w[(long)row*DIM + kz], w[(long)row*DIM + kz + 1]);
        v[j] = *reinterpret_cast<uint32_t*>(&h2);
    }
    *(uint4*)(wp + idx*4) = make_uint4(v[0], v[1], v[2], v[3]);
}

__global__ void concat_bias_kernel(const float* __restrict__ b0, const float* __restrict__ b1,
                                   const float* __restrict__ b2, float* __restrict__ dst)
{
    int i = blockIdx.x * 256 + threadIdx.x;
    if (i < DIM) dst[i] = b0[i];
    else if (i < 2*DIM) dst[i] = b1[i - DIM];
    else if (i < 3*DIM) dst[i] = b2[i - 2*DIM];
}

// ---------------- pooling (fp32, exact) ----------------
__global__ void pool_kernel(const float* __restrict__ x, float* __restrict__ pooled)
{
    int b = blockIdx.y;
    int d = blockIdx.x * 128 + (threadIdx.x & 127);
    int half = threadIdx.x >> 7;
    const float* xb = x + (long)b*SD + d;
    int t0 = half * 129;
    int t1 = half ? SEQ : 129;
    float s = 0.f;
    for (int t = t0; t < t1; t++) s += xb[(long)t*DIM];
    __shared__ float red[256];
    red[threadIdx.x] = s;
    __syncthreads();
    if (half == 0)
        pooled[b*DIM + d] = (red[threadIdx.x] + red[threadIdx.x + 128]) * (1.0f / SEQ);
}

// ---------------- gating MLP (exact fp32) ----------------
__global__ void gating_kernel(const float* __restrict__ pooled,
                              const float* __restrict__ gw1, const float* __restrict__ gb1,
                              const float* __restrict__ gw2, const float* __restrict__ gb2,
                              int* __restrict__ idx, float* __restrict__ gates)
{
    int b = blockIdx.x;
    int tid = threadIdx.x;
    __shared__ float pl[DIM];
    __shared__ float h[GHID];
    __shared__ float logits[NEXP];

    for (int d = tid; d < DIM; d += 256) pl[d] = pooled[b*DIM + d];
    __syncthreads();
    {
        float s = gb1[tid];
        const float* w = gw1 + (long)tid * DIM;
        #pragma unroll 8
        for (int d = 0; d < DIM; d++) s += pl[d] * w[d];
        h[tid] = fmaxf(s, 0.f);
    }
    __syncthreads();
    if (tid < NEXP) {
        float s = gb2[tid];
        const float* w = gw2 + (long)tid * GHID;
        for (int g = 0; g < GHID; g++) s += h[g] * w[g];
        logits[tid] = s;
    }
    __syncthreads();
    if (tid == 0) {
        int i1 = 0; float v1 = logits[0];
        for (int e = 1; e < NEXP; e++) if (logits[e] > v1) { v1 = logits[e]; i1 = e; }
        int i2 = -1; float v2 = -3.0e38f;
        for (int e = 0; e < NEXP; e++) if (e != i1 && logits[e] > v2) { v2 = logits[e]; i2 = e; }
        float e2 = expf(v2 - v1);
        float inv = 1.f / (1.f + e2);
        idx[b*2] = i1; idx[b*2+1] = i2;
        gates[b*2] = inv; gates[b*2+1] = e2 * inv;
    }
}

// ---------------- fused fold (fp16 outputs) ----------------
__global__ void build_uv_kernel(const float* __restrict__ U0, const float* __restrict__ U1,
                                const float* __restrict__ U2, const float* __restrict__ U3,
                                const float* __restrict__ S0, const float* __restrict__ S1,
                                const float* __restrict__ S2, const float* __restrict__ S3,
                                const float* __restrict__ V0, const float* __restrict__ V1,
                                const float* __restrict__ V2, const float* __restrict__ V3,
                                const int* __restrict__ idx, const float* __restrict__ gates,
                                __half* __restrict__ VwAll, __half* __restrict__ UwAll)
{
    int p = blockIdx.x >> 5, b = blockIdx.x & 31;
    const float* U = (p == 0) ? U0 : (p == 1) ? U1 : (p == 2) ? U2 : U3;
    const float* Sg = (p == 0) ? S0 : (p == 1) ? S1 : (p == 2) ? S2 : S3;
    const float* V = (p == 0) ? V0 : (p == 1) ? V1 : (p == 2) ? V2 : V3;
    int tid = threadIdx.x;
    int e0 = idx[b*2], e1 = idx[b*2+1];
    float g0 = gates[b*2], g1 = gates[b*2+1];
    __half* vw = VwAll + ((long)p*BATCH + b) * 32 * DIM;
    __half* uw = UwAll + ((long)p*BATCH + b) * DIM * 32;

    for (int i = tid; i < 32*DIM; i += 256) {
        int j = i >> 10, d = i & (DIM-1);
        int k = j >> 4, r = j & 15;
        int e = k ? e1 : e0;
        vw[i] = __float2half_rn(Sg[e*RANK + r] * V[((long)e*RANK + r)*DIM + d]);
    }
    for (int i = tid; i < DIM*32; i += 256) {
        int n = i >> 5, j = i & 31;
        int k = j >> 4, r = j & 15;
        int e = k ? e1 : e0;
        float g = k ? g1 : g0;
        uw[i] = __float2half_rn(g * U[((long)e*DIM + n)*RANK + r]);
    }
}

// ---------------- FP16 MMA primitive ----------------
__device__ __forceinline__ void mma_f16(float c[4], const uint32_t a[4], const uint32_t b0, const uint32_t b1) {
    asm volatile(
        "mma.sync.aligned.m16n8k16.row.col.f32.f16.f16.f32 "
        "{%0,%1,%2,%3}, {%4,%5,%6,%7}, {%8,%9}, {%0,%1,%2,%3};"
        : "+f"(c[0]), "+f"(c[1]), "+f"(c[2]), "+f"(c[3])
        : "r"(a[0]), "r"(a[1]), "r"(a[2]), "r"(a[3]), "r"(b0), "r"(b1));
}

__device__ __forceinline__ float2 ld2(const float* p)  { return *reinterpret_cast<const float2*>(p); }
__device__ __forceinline__ float2 ld2(const __half* p) { return __half22float2(*reinterpret_cast<const half2*>(p)); }
__device__ __forceinline__ void st2(float* p, float v0, float v1)  { *reinterpret_cast<float2*>(p) = make_float2(v0, v1); }
__device__ __forceinline__ void st2(__half* p, float v0, float v1) { *reinterpret_cast<half2*>(p) = __floats2half2_rn(v0, v1); }

// f16x2 dual exp2 — one MUFU op for two values
__device__ __forceinline__ uint32_t ex2_h2(float e0, float e1) {
    half2 h = __floats2half2_rn(e0, e1);
    uint32_t in = *reinterpret_cast<uint32_t*>(&h), r;
    asm("ex2.approx.f16x2 %0, %1;" : "=r"(r) : "r"(in));
    return r;
}

// ==================== WIDE FP16 GEMM v2: permuted operands + cp.async 4-stage ======
template<typename CT>
__global__ __launch_bounds__(256, 2)
void hgemm_wide2(const uint32_t* __restrict__ Ap, const uint32_t* __restrict__ Bp,
                 const float* __restrict__ bias, CT* __restrict__ C, int M, int ldc)
{
    extern __shared__ uint32_t sh[];   // 4 stages x (A 2048 + B 2048) u32 = 64KB
    uint32_t shb = smem_u32(sh);
    int tid = threadIdx.x;
    int warp = tid >> 5, lane = tid & 31;
    int mt0 = (warp & 3) * 2;
    int np0 = (warp >> 2) * 4;
    int g = lane >> 2, tg = lane & 3;
    int m0 = blockIdx.y * 128, n0 = blockIdx.x * 128;

    const uint32_t* Ar = Ap + (long)blockIdx.y * 32 * 2048;
    const uint32_t* Br = Bp + (long)blockIdx.x * 32 * 2048;

    float acc[2][8][4] = {};

    auto issue = [&](int kc) {
        uint32_t d = shb + (uint32_t)(kc & 3) * 16384;
        const uint32_t* a = Ar + kc * 2048;
        const uint32_t* b = Br + kc * 2048;
        cp16(d +             tid*16, a + tid*4);
        cp16(d +  4096u +    tid*16, a + 1024 + tid*4);
        cp16(d +  8192u +    tid*16, b + tid*4);
        cp16(d + 12288u +    tid*16, b + 1024 + tid*4);
        asm volatile("cp.async.commit_group;");
    };

    issue(0);
    issue(1);

    for (int kc = 0; kc < 32; kc++) {
        if (kc + 2 < 32) {
            issue(kc + 2);
            asm volatile("cp.async.wait_group 2;");
        } else {
            asm volatile("cp.async.wait_group 0;");
        }
        __syncthreads();

        const uint32_t* As = sh + (kc & 3) * 4096;
        const uint32_t* Bs = As + 2048;
        #pragma unroll
        for (int kk = 0; kk < 2; kk++) {
            uint4 a4[2];
            a4[0] = *(const uint4*)&As[((kk*8 + mt0    )*32 + lane)*4];
            a4[1] = *(const uint4*)&As[((kk*8 + mt0 + 1)*32 + lane)*4];
            uint4 bp[4];
            #pragma unroll
            for (int p = 0; p < 4; p++)
                bp[p] = *(const uint4*)&Bs[((kk*8 + np0 + p)*32 + lane)*4];
            #pragma unroll
            for (int i = 0; i < 2; i++) {
                uint32_t a[4] = { a4[i].x, a4[i].y, a4[i].z, a4[i].w };
                #pragma unroll
                for (int p = 0; p < 4; p++) {
                    mma_f16(acc[i][2*p    ], a, bp[p].x, bp[p].y);
                    mma_f16(acc[i][2*p + 1], a, bp[p].z, bp[p].w);
                }
            }
        }
    }

    #pragma unroll
    for (int i = 0; i < 2; i++) {
        #pragma unroll
        for (int rs = 0; rs < 2; rs++) {
            int gm = m0 + (mt0 + i)*16 + g + rs*8;
            if (gm >= M) continue;
            #pragma unroll
            for (int j = 0; j < 8; j++) {
                int gn = n0 + (np0*2 + j)*8 + tg*2;
                long off = (long)gm*ldc + gn;
                st2(&C[off], acc[i][j][rs*2+0] + bias[gn], acc[i][j][rs*2+1] + bias[gn+1]);
            }
        }
    }
}

// ==================== general batched FP16 GEMM (B transposed (N,K)) ====================
#define TBN 64
template<bool ACC, typename CT>
__global__ __launch_bounds__(256, 2)
void hgemm(const __half* __restrict__ A, const __half* __restrict__ B,
           CT* __restrict__ C,
           int M, int N, int K, int lda, int ldb, int ldc,
           long sA1, long sA2, long sB1, long sB2, long sC1, long sC2, int zdiv)
{
    int z = blockIdx.z;
    long zq = z / zdiv, zr = z % zdiv;
    A += zq*sA1 + zr*sA2;
    B += zq*sB1 + zr*sB2;
    C += zq*sC1 + zr*sC2;

    int m0 = blockIdx.y * 128, n0 = blockIdx.x * TBN;
    __shared__ uint32_t As[2048];
    __shared__ uint32_t Bs[1024];

    int tid = threadIdx.x;
    int warp = tid >> 5, lane = tid & 31;
    int mt0 = (warp & 3) * 2;
    int np0 = (warp >> 2) * 2;
    int g = lane >> 2, tg = lane & 3;

    float acc[2][4][4] = {};
    uint4 ar[2], br;

    const int KB = K / 32;

    auto load_regs = [&](int kb) {
        int k0 = kb * 32;
        #pragma unroll
        for (int i = 0; i < 2; i++) {
            int f4 = i*256 + tid;
            int row = f4 >> 2, c8 = f4 & 3;
            int gm = m0 + row;
            ar[i] = (gm < M) ? *(const uint4*)(A + (long)gm*lda + k0 + c8*8)
                             : make_uint4(0u,0u,0u,0u);
        }
        {
            int n = tid >> 2, c8 = tid & 3;
            int gn = n0 + n;
            br = (gn < N) ? *(const uint4*)(B + (long)gn*ldb + k0 + c8*8)
                          : make_uint4(0u,0u,0u,0u);
        }
    };

    auto sts = [&]() {
        #pragma unroll
        for (int i = 0; i < 2; i++) {
            int f4 = i*256 + tid;
            int row = f4 >> 2, c8 = f4 & 3;
            int kk = c8 >> 1, kh = c8 & 1;
            int mt = row >> 4, w = row & 15, gg = w & 7, rh = w >> 3;
            int base = ((kk*8 + mt)*32 + gg*4)*4 + kh*2 + rh;
            As[base +  0] = ar[i].x;
            As[base +  4] = ar[i].y;
            As[base +  8] = ar[i].z;
            As[base + 12] = ar[i].w;
        }
        {
            int n = tid >> 2, c8 = tid & 3;
            int kk = c8 >> 1, kh = c8 & 1;
            int nt = n >> 3, gc = n & 7, np = nt >> 1, sub = nt & 1;
            int base = ((kk*4 + np)*32 + gc*4)*4 + sub*2 + kh;
            Bs[base +  0] = br.x;
            Bs[base +  4] = br.y;
            Bs[base +  8] = br.z;
            Bs[base + 12] = br.w;
        }
    };

    load_regs(0);
    sts();
    __syncthreads();

    for (int kb = 0; kb < KB; kb++) {
        if (kb + 1 < KB) load_regs(kb + 1);

        #pragma unroll
        for (int kk = 0; kk < 2; kk++) {
            uint4 a4[2];
            a4[0] = *(const uint4*)&As[((kk*8 + mt0    )*32 + lane)*4];
            a4[1] = *(const uint4*)&As[((kk*8 + mt0 + 1)*32 + lane)*4];
            uint4 bp[2];
            bp[0] = *(const uint4*)&Bs[((kk*4 + np0    )*32 + lane)*4];
            bp[1] = *(const uint4*)&Bs[((kk*4 + np0 + 1)*32 + lane)*4];
            #pragma unroll
            for (int i = 0; i < 2; i++) {
                uint32_t a[4] = { a4[i].x, a4[i].y, a4[i].z, a4[i].w };
                #pragma unroll
                for (int p = 0; p < 2; p++) {
                    mma_f16(acc[i][2*p    ], a, bp[p].x, bp[p].y);
                    mma_f16(acc[i][2*p + 1], a, bp[p].z, bp[p].w);
                }
            }
        }

        if (kb + 1 < KB) {
            __syncthreads();
            sts();
            __syncthreads();
        }
    }

    #pragma unroll
    for (int i = 0; i < 2; i++) {
        #pragma unroll
        for (int rs = 0; rs < 2; rs++) {
            int gm = m0 + (mt0 + i)*16 + g + rs*8;
            if (gm >= M) continue;
            #pragma unroll
            for (int j = 0; j < 4; j++) {
                int gn = n0 + (np0*2 + j)*8 + tg*2;
                if (gn >= N) continue;
                long off = (long)gm*ldc + gn;
                float v0 = acc[i][j][rs*2+0];
                float v1 = acc[i][j][rs*2+1];
                if (ACC) { float2 c2 = ld2(&C[off]); v0 += c2.x; v1 += c2.y; }
                st2(&C[off], v0, v1);
            }
        }
    }
}

// ==================== FLASH ATTENTION (fp16 in, fp32 accum, f16x2 exp) ====================
__global__ __launch_bounds__(256)
void flash_kernel(const __half* __restrict__ qkv, __half* __restrict__ ctx)
{
    __shared__ uint32_t ks[2048];
    __shared__ uint32_t vs[2048];
    __shared__ uint32_t ps[4096];

    int tid = threadIdx.x, warp = tid >> 5, lane = tid & 31;
    int g = lane >> 2, tg = lane & 3;
    int bh = blockIdx.y;
    int b = bh >> 4, h = bh & 15;
    int m0 = blockIdx.x * 128;

    const __half* qb = qkv + (long)b*SEQ*QKVD + h*HDIM;
    const __half* kb = qkv + (long)b*SEQ*QKVD + DIM + h*HDIM;
    const __half* vb = qkv + (long)b*SEQ*QKVD + 2*DIM + h*HDIM;

    int r0 = m0 + warp*16 + g;
    int r1 = r0 + 8;
    bool warp_active = (m0 + warp*16) < SEQ;   // warp-uniform

    uint32_t qa[4][4];
    if (warp_active) {
        #pragma unroll
        for (int kk = 0; kk < 4; kk++) {
            qa[kk][0] = (r0 < SEQ) ? *(const uint32_t*)(qb + (long)r0*QKVD + kk*16 + 2*tg)     : 0u;
            qa[kk][1] = (r1 < SEQ) ? *(const uint32_t*)(qb + (long)r1*QKVD + kk*16 + 2*tg)     : 0u;
            qa[kk][2] = (r0 < SEQ) ? *(const uint32_t*)(qb + (long)r0*QKVD + kk*16 + 8 + 2*tg) : 0u;
            qa[kk][3] = (r1 < SEQ) ? *(const uint32_t*)(qb + (long)r1*QKVD + kk*16 + 8 + 2*tg) : 0u;
        }
    }

    float o[8][4] = {};
    float m0r = -1e30f, m1r = -1e30f, l0r = 0.f, l1r = 0.f;
    const float LOG2E = 1.4426950408889634f;

    for (int j = 0; j < 5; j++) {
        int kv0 = j * 64;
        // K tile load (all threads)
        #pragma unroll
        for (int i = 0; i < 2; i++) {
            int f4 = i*256 + tid;
            int n = f4 >> 3, c8 = f4 & 7;
            int gr = kv0 + n;
            uint4 v = (gr < SEQ) ? *(const uint4*)(kb + (long)gr*QKVD + c8*8)
                                 : make_uint4(0u,0u,0u,0u);
            int kk = c8 >> 1, kh = c8 & 1;
            int nt = n >> 3, gc = n & 7;
            int base = ((kk*8 + nt)*32 + gc*4)*2 + kh;
            ks[base + 0] = v.x;
            ks[base + 2] = v.y;
            ks[base + 4] = v.z;
            ks[base + 6] = v.w;
        }
        // V tile load (all threads)
        {
            int kvpair = tid >> 3, nt = tid & 7;
            int rA = kv0 + kvpair*2, rB = rA + 1;
            union { uint4 u; __half hx[8]; } ua, ub;
            ua.u = (rA < SEQ) ? *(const uint4*)(vb + (long)rA*QKVD + nt*8) : make_uint4(0u,0u,0u,0u);
            ub.u = (rB < SEQ) ? *(const uint4*)(vb + (long)rB*QKVD + nt*8) : make_uint4(0u,0u,0u,0u);
            int klocal = kvpair*2;
            int kk = klocal >> 4, kin = klocal & 15;
            int kh = kin >> 3, t = (kin & 7) >> 1;
            #pragma unroll
            for (int jj = 0; jj < 8; jj++) {
                half2 h2 = __halves2half2(ua.hx[jj], ub.hx[jj]);
                vs[((kk*8 + nt)*32 + jj*4 + t)*2 + kh] = *reinterpret_cast<uint32_t*>(&h2);
            }
        }
        __syncthreads();

        if (warp_active) {
            float s[8][4] = {};
            #pragma unroll
            for (int kk = 0; kk < 4; kk++) {
                #pragma unroll
                for (int nt = 0; nt < 8; nt++) {
                    uint2 bb = *(const uint2*)&ks[((kk*8 + nt)*32 + lane)*2];
                    mma_f16(s[nt], qa[kk], bb.x, bb.y);
                }
            }

            float tmax0 = -1e30f, tmax1 = -1e30f;
            #pragma unroll
            for (int nt = 0; nt < 8; nt++) {
                int c0 = kv0 + nt*8 + 2*tg;
                s[nt][0] = (c0     < SEQ) ? s[nt][0]*ATTN_SCALE : -1e30f;
                s[nt][1] = (c0 + 1 < SEQ) ? s[nt][1]*ATTN_SCALE : -1e30f;
                s[nt][2] = (c0     < SEQ) ? s[nt][2]*ATTN_SCALE : -1e30f;
                s[nt][3] = (c0 + 1 < SEQ) ? s[nt][3]*ATTN_SCALE : -1e30f;
                tmax0 = fmaxf(tmax0, fmaxf(s[nt][0], s[nt][1]));
                tmax1 = fmaxf(tmax1, fmaxf(s[nt][2], s[nt][3]));
            }
            tmax0 = fmaxf(tmax0, __shfl_xor_sync(0xffffffffu, tmax0, 1));
            tmax0 = fmaxf(tmax0, __shfl_xor_sync(0xffffffffu, tmax0, 2));
            tmax1 = fmaxf(tmax1, __shfl_xor_sync(0xffffffffu, tmax1, 1));
            tmax1 = fmaxf(tmax1, __shfl_xor_sync(0xffffffffu, tmax1, 2));
            float nm0 = fmaxf(m0r, tmax0), nm1 = fmaxf(m1r, tmax1);
            float f0 = __expf(m0r - nm0), f1 = __expf(m1r - nm1);

            float sum0 = 0.f, sum1 = 0.f;
            #pragma unroll
            for (int nt = 0; nt < 8; nt++) {
                // dual-f16 exp2: p = 2^((s-m)*log2e); masked -> -inf -> 0
                uint32_t r01 = ex2_h2((s[nt][0] - nm0)*LOG2E, (s[nt][1] - nm0)*LOG2E);
                uint32_t r23 = ex2_h2((s[nt][2] - nm1)*LOG2E, (s[nt][3] - nm1)*LOG2E);
                float2 f01 = __half22float2(*reinterpret_cast<half2*>(&r01));
                float2 f23 = __half22float2(*reinterpret_cast<half2*>(&r23));
                sum0 += f01.x + f01.y;
                sum1 += f23.x + f23.y;
                int kkp = nt >> 1, kh = nt & 1;
                int base = ((kkp*8 + warp)*32 + lane)*4 + kh*2;
                ps[base + 0] = r01;
                ps[base + 1] = r23;
            }
            sum0 += __shfl_xor_sync(0xffffffffu, sum0, 1);
            sum0 += __shfl_xor_sync(0xffffffffu, sum0, 2);
            sum1 += __shfl_xor_sync(0xffffffffu, sum1, 1);
            sum1 += __shfl_xor_sync(0xffffffffu, sum1, 2);
            l0r = l0r*f0 + sum0;
            l1r = l1r*f1 + sum1;
            m0r = nm0; m1r = nm1;
            #pragma unroll
            for (int nt = 0; nt < 8; nt++) {
                o[nt][0] *= f0; o[nt][1] *= f0;
                o[nt][2] *= f1; o[nt][3] *= f1;
            }

            #pragma unroll
            for (int kk = 0; kk < 4; kk++) {
                uint4 p4 = *(const uint4*)&ps[((kk*8 + warp)*32 + lane)*4];
                uint32_t pa[4] = { p4.x, p4.y, p4.z, p4.w };
                #pragma unroll
                for (int nt = 0; nt < 8; nt++) {
                    uint2 vv = *(const uint2*)&vs[((kk*8 + nt)*32 + lane)*2];
                    mma_f16(o[nt], pa, vv.x, vv.y);
                }
            }
        }
        __syncthreads();
    }

    if (warp_active) {
        float inv0 = 1.f / l0r, inv1 = 1.f / l1r;
        __half* cb = ctx + (long)b*SEQ*DIM + h*HDIM;
        #pragma unroll
        for (int nt = 0; nt < 8; nt++) {
            int col = nt*8 + 2*tg;
            if (r0 < SEQ) {
                half2 h2 = __floats2half2_rn(o[nt][0]*inv0, o[nt][1]*inv0);
                *reinterpret_cast<half2*>(cb + (long)r0*DIM + col) = h2;
            }
            if (r1 < SEQ) {
                half2 h2 = __floats2half2_rn(o[nt][2]*inv1, o[nt][3]*inv1);
                *reinterpret_cast<half2*>(cb + (long)r1*DIM + col) = h2;
            }
        }
    }
}

// ---------------- host launch ----------------
static void* dsym(const void* symbol) { void* p = nullptr; cudaGetSymbolAddress(&p, symbol); return p; }
static inline dim3 hgrid(int N, int M, int Z) { return dim3((N+TBN-1)/TBN, (M+127)/128, Z); }
#define WIDE2_SMEM 65536

extern "C" void kernel_launch(void* const* d_in, const int* in_sizes, int n_in,
                              void* d_out, int out_size)
{
    const float* x   = (const float*)d_in[0];
    const float* gw1 = (const float*)d_in[1];
    const float* gb1 = (const float*)d_in[2];
    const float* gw2 = (const float*)d_in[3];
    const float* gb2 = (const float*)d_in[4];
    const float* Wm[4]; const float* Ue[4]; const float* Se[4]; const float* Ve[4]; const float* bi[4];
    for (int p = 0; p < 4; p++) {
        Wm[p] = (const float*)d_in[5 + p*5 + 0];
        Ue[p] = (const float*)d_in[5 + p*5 + 1];
        Se[p] = (const float*)d_in[5 + p*5 + 2];
        Ve[p] = (const float*)d_in[5 + p*5 + 3];
        bi[p] = (const float*)d_in[5 + p*5 + 4];
    }
    float* out = (float*)d_out;

    int*      idxp   = (int*)dsym(g_idx);
    float*    gatesp = (float*)dsym(g_gates);
    float*    pooled = (float*)dsym(g_pooled);
    float*    bcat   = (float*)dsym(g_bcat);
    __half*   xh     = (__half*)dsym(g_xh);
    uint32_t* xhp    = (uint32_t*)dsym(g_xhp);
    uint32_t* Wmp    = (uint32_t*)dsym(g_Wmp);
    uint32_t* ctxp   = (uint32_t*)dsym(g_ctxp);
    __half*   Vw     = (__half*)dsym(g_Vw);
    __half*   Uw     = (__half*)dsym(g_Uw);
    __half*   tbuf   = (__half*)dsym(g_t);
    __half*   qkv    = (__half*)dsym(g_qkv);
    __half*   ctx    = (__half*)dsym(g_ctx);

    const long VW_PER = (long)BATCH*32*DIM;
    const long UW_PER = (long)BATCH*DIM*32;
    const long T_PER  = (long)BATCH*SEQ*32;

    cudaFuncSetAttribute(hgemm_wide2<__half>, cudaFuncAttributeMaxDynamicSharedMemorySize, WIDE2_SMEM);
    cudaFuncSetAttribute(hgemm_wide2<float>,  cudaFuncAttributeMaxDynamicSharedMemorySize, WIDE2_SMEM);

    // 0..2: dependencies of the wide QKV GEMM
    cvt_xp_kernel<<<(MBLK*32*512 + 255)/256, 256>>>(x, xhp);                       // 0
    cvt4p_kernel<<<(32*32*512 + 255)/256, 256>>>(Wm[0], Wm[1], Wm[2], Wm[3], Wmp); // 1
    concat_bias_kernel<<<12, 256>>>(bi[0], bi[1], bi[2], bcat);                    // 2

    // 3: fused main projection (4th-launch slot for ncu capture)
    hgemm_wide2<__half><<<dim3(QKVD/128, MBLK), 256, WIDE2_SMEM>>>(
        xhp, Wmp, bcat, qkv, MROWS, QKVD);

    // 4..7: gating path + row-major fp16 x + expert folding
    cvt_kernel<<<1184, 256>>>(x, xh, (long)MROWS*DIM);                             // 4
    pool_kernel<<<dim3(8, BATCH), 256>>>(x, pooled);                               // 5
    gating_kernel<<<BATCH, 256>>>(pooled, gw1, gb1, gw2, gb2, idxp, gatesp);       // 6
    build_uv_kernel<<<128, 256>>>(Ue[0], Ue[1], Ue[2], Ue[3],
                                  Se[0], Se[1], Se[2], Se[3],
                                  Ve[0], Ve[1], Ve[2], Ve[3],
                                  idxp, gatesp, Vw, Uw);                           // 7

    // 8: fused xV for q,k,v
    hgemm<false,__half><<<hgrid(32, SEQ, 3*BATCH), 256>>>(
        xh, Vw, tbuf,
        SEQ, 32, DIM, DIM, DIM, 32,
        0, (long)SD, VW_PER, (long)32*DIM, T_PER, (long)SEQ*32, BATCH);

    // 9: fused expert accumulate
    hgemm<true,__half><<<hgrid(DIM, SEQ, 3*BATCH), 256>>>(
        tbuf, Uw, qkv,
        SEQ, DIM, 32, 32, 32, QKVD,
        T_PER, (long)SEQ*32, UW_PER, (long)DIM*32, (long)DIM, (long)SEQ*QKVD, BATCH);

    // 10: flash attention
    flash_kernel<<<dim3(3, BATCH*NHEAD), 256>>>(qkv, ctx);

    // 11: ctx low-rank projection
    hgemm<false,__half><<<hgrid(32, SEQ, BATCH), 256>>>(
        ctx, Vw + 3*VW_PER, tbuf + 3*T_PER,
        SEQ, 32, DIM, DIM, DIM, 32,
        0, (long)SD, 0, (long)32*DIM, 0, (long)SEQ*32, BATCH);

    // 12: permute ctx for the wide out-projection
    ctxp_kernel<<<(MBLK*32*512 + 255)/256, 256>>>(ctx, ctxp);

    // 13: out = ctx @ Wo^T + bo (fp32 out)
    hgemm_wide2<float><<<dim3(DIM/128, MBLK), 256, WIDE2_SMEM>>>(
        ctxp, Wmp + (long)24*32*2048, bi[3], out, MROWS, DIM);

    // 14: out += t3 @ Uw3^T (fp32 accumulate)
    hgemm<true,float><<<hgrid(DIM, SEQ, BATCH), 256>>>(
        tbuf + 3*T_PER, Uw + 3*UW_PER, out,
        SEQ, DIM, 32, 32, 32, DIM,
        0, (long)SEQ*32, 0, (long)DIM*32, 0, (long)SD, BATCH);
}

// round 11
// speedup vs baseline: 6.5559x; 1.0124x over previous
#include <cuda_runtime.h>
#include <cuda_fp16.h>
#include <math.h>
#include <stdint.h>

// ---------------- problem constants ----------------
#define BATCH 32
#define SEQ   257
#define DIM   1024
#define QKVD  3072
#define NHEAD 16
#define HDIM  64
#define NEXP  8
#define TOPK  2
#define RANK  16
#define GHID  256
#define SD    (SEQ*DIM)
#define MROWS (BATCH*SEQ)        // 8224
#define MBLK  65                 // ceil(8224/128)
#define ATTN_SCALE 0.125f

// ---------------- static device scratch ----------------
__device__ int   g_idx[BATCH*TOPK];
__device__ float g_gates[BATCH*TOPK];
__device__ float g_pooled[BATCH*DIM];
__device__ float g_bcat[QKVD];
__device__ __align__(16) __half   g_xh [MROWS*DIM];
__device__ __align__(16) uint32_t g_xhp[(long)MBLK*32*2048];    // permuted x (A frag order)
__device__ __align__(16) uint32_t g_Wmp[(long)32*32*2048];      // permuted weights (B frag order)
__device__ __align__(16) uint32_t g_ctxp[(long)MBLK*32*2048];   // permuted ctx
__device__ __align__(16) __half g_Vw[(long)BATCH*128*DIM];      // [b][p*32+j][d]
__device__ __align__(16) __half g_Uw[4ll*BATCH*DIM*32];         // [p][b][n][j]
__device__ __align__(16) __half g_t [(long)BATCH*SEQ*96];       // qkv low-rank t [b][s][96]
__device__ __align__(16) __half g_t3[(long)BATCH*SEQ*32];       // o low-rank t
__device__ __align__(16) __half g_qkv[(long)(MROWS+32)*QKVD];
__device__ __align__(16) __half g_ctx[MROWS*DIM];

__device__ __forceinline__ uint32_t smem_u32(const void* p) {
    uint32_t a;
    asm("{ .reg .u64 t; cvta.to.shared.u64 t, %1; cvt.u32.u64 %0, t; }" : "=r"(a) : "l"(p));
    return a;
}
__device__ __forceinline__ void cp16(uint32_t saddr, const void* g) {
    asm volatile("cp.async.cg.shared.global [%0], [%1], 16;" :: "r"(saddr), "l"(g));
}

// ---------------- conversion / permutation kernels ----------------
__global__ void cvt_kernel(const float* __restrict__ src, __half* __restrict__ dst, long n)
{
    long i = (long)blockIdx.x * blockDim.x + threadIdx.x;
    long stride = (long)gridDim.x * blockDim.x;
    for (; i < n; i += stride) dst[i] = __float2half_rn(src[i]);
}

// x (fp32 row-major) -> permuted fp16 A-frag layout. one uint4 per thread.
__global__ void cvt_xp_kernel(const float* __restrict__ x, uint32_t* __restrict__ xp)
{
    long idx = (long)blockIdx.x * 256 + threadIdx.x;
    if (idx >= (long)MBLK*32*512) return;
    int q  = (int)(idx & 511);
    long r = idx >> 9;
    int kc = (int)(r & 31);
    int mb = (int)(r >> 5);
    int kk = q >> 8, mt = (q >> 5) & 7, lane = q & 31;
    int g = lane >> 2, tg = lane & 3;
    int mbase = mb*128 + mt*16 + g;
    int kbase = kc*32 + kk*16 + tg*2;
    uint32_t v[4];
    #pragma unroll
    for (int j = 0; j < 4; j++) {
        int kh = j >> 1, rh = j & 1;
        int m = mbase + rh*8;
        int kz = kbase + kh*8;
        half2 h2 = (m < MROWS)
            ? __floats2half2_rn(x[(long)m*DIM + kz], x[(long)m*DIM + kz + 1])
            : __floats2half2_rn(0.f, 0.f);
        v[j] = *reinterpret_cast<uint32_t*>(&h2);
    }
    *(uint4*)(xp + idx*4) = make_uint4(v[0], v[1], v[2], v[3]);
}

// ctx (fp16 row-major) -> permuted A-frag layout
__global__ void ctxp_kernel(const __half* __restrict__ ctx, uint32_t* __restrict__ cp)
{
    long idx = (long)blockIdx.x * 256 + threadIdx.x;
    if (idx >= (long)MBLK*32*512) return;
    int q  = (int)(idx & 511);
    long r = idx >> 9;
    int kc = (int)(r & 31);
    int mb = (int)(r >> 5);
    int kk = q >> 8, mt = (q >> 5) & 7, lane = q & 31;
    int g = lane >> 2, tg = lane & 3;
    int mbase = mb*128 + mt*16 + g;
    int kbase = kc*32 + kk*16 + tg*2;
    uint32_t v[4];
    #pragma unroll
    for (int j = 0; j < 4; j++) {
        int kh = j >> 1, rh = j & 1;
        int m = mbase + rh*8;
        int kz = kbase + kh*8;
        v[j] = (m < MROWS) ? *(const uint32_t*)(ctx + (long)m*DIM + kz) : 0u;
    }
    *(uint4*)(cp + idx*4) = make_uint4(v[0], v[1], v[2], v[3]);
}

// 4 weight matrices (fp32 (N,K) row-major) -> permuted fp16 B-frag layout (4096 n-rows)
__global__ void cvt4p_kernel(const float* __restrict__ w0, const float* __restrict__ w1,
                             const float* __restrict__ w2, const float* __restrict__ w3,
                             uint32_t* __restrict__ wp)
{
    long idx = (long)blockIdx.x * 256 + threadIdx.x;
    if (idx >= (long)32*32*512) return;
    int q  = (int)(idx & 511);
    long r = idx >> 9;
    int kc = (int)(r & 31);
    int nb = (int)(r >> 5);
    int kk = q >> 8, np = (q >> 5) & 7, lane = q & 31;
    int gc = lane >> 2, tg = lane & 3;
    int kbase = kc*32 + kk*16 + tg*2;
    uint32_t v[4];
    #pragma unroll
    for (int j = 0; j < 4; j++) {
        int sub = j >> 1, kh = j & 1;
        int n = nb*128 + np*16 + sub*8 + gc;
        int p = n >> 10, row = n & 1023;
        const float* w = (p == 0) ? w0 : (p == 1) ? w1 : (p == 2) ? w2 : w3;
        int kz = kbase + kh*8;
        half2 h2 = __floats2half2_rn(w[(long)row*DIM + kz], w[(long)row*DIM + kz + 1]);
        v[j] = *reinterpret_cast<uint32_t*>(&h2);
    }
    *(uint4*)(wp + idx*4) = make_uint4(v[0], v[1], v[2], v[3]);
}

__global__ void concat_bias_kernel(const float* __restrict__ b0, const float* __restrict__ b1,
                                   const float* __restrict__ b2, float* __restrict__ dst)
{
    int i = blockIdx.x * 256 + threadIdx.x;
    if (i < DIM) dst[i] = b0[i];
    else if (i < 2*DIM) dst[i] = b1[i - DIM];
    else if (i < 3*DIM) dst[i] = b2[i - 2*DIM];
}

// ---------------- pooling (fp32, exact) ----------------
__global__ void pool_kernel(const float* __restrict__ x, float* __restrict__ pooled)
{
    int b = blockIdx.y;
    int d = blockIdx.x * 128 + (threadIdx.x & 127);
    int half = threadIdx.x >> 7;
    const float* xb = x + (long)b*SD + d;
    int t0 = half * 129;
    int t1 = half ? SEQ : 129;
    float s = 0.f;
    for (int t = t0; t < t1; t++) s += xb[(long)t*DIM];
    __shared__ float red[256];
    red[threadIdx.x] = s;
    __syncthreads();
    if (half == 0)
        pooled[b*DIM + d] = (red[threadIdx.x] + red[threadIdx.x + 128]) * (1.0f / SEQ);
}

// ---------------- gating MLP (exact fp32) ----------------
__global__ void gating_kernel(const float* __restrict__ pooled,
                              const float* __restrict__ gw1, const float* __restrict__ gb1,
                              const float* __restrict__ gw2, const float* __restrict__ gb2,
                              int* __restrict__ idx, float* __restrict__ gates)
{
    int b = blockIdx.x;
    int tid = threadIdx.x;
    __shared__ float pl[DIM];
    __shared__ float h[GHID];
    __shared__ float logits[NEXP];

    for (int d = tid; d < DIM; d += 256) pl[d] = pooled[b*DIM + d];
    __syncthreads();
    {
        float s = gb1[tid];
        const float* w = gw1 + (long)tid * DIM;
        #pragma unroll 8
        for (int d = 0; d < DIM; d++) s += pl[d] * w[d];
        h[tid] = fmaxf(s, 0.f);
    }
    __syncthreads();
    if (tid < NEXP) {
        float s = gb2[tid];
        const float* w = gw2 + (long)tid * GHID;
        for (int g = 0; g < GHID; g++) s += h[g] * w[g];
        logits[tid] = s;
    }
    __syncthreads();
    if (tid == 0) {
        int i1 = 0; float v1 = logits[0];
        for (int e = 1; e < NEXP; e++) if (logits[e] > v1) { v1 = logits[e]; i1 = e; }
        int i2 = -1; float v2 = -3.0e38f;
        for (int e = 0; e < NEXP; e++) if (e != i1 && logits[e] > v2) { v2 = logits[e]; i2 = e; }
        float e2 = expf(v2 - v1);
        float inv = 1.f / (1.f + e2);
        idx[b*2] = i1; idx[b*2+1] = i2;
        gates[b*2] = inv; gates[b*2+1] = e2 * inv;
    }
}

// ---------------- fused fold: Vw -> [b][p*32+j][d], Uw -> [p][b][n][j] ----------------
__global__ void build_uv_kernel(const float* __restrict__ U0, const float* __restrict__ U1,
                                const float* __restrict__ U2, const float* __restrict__ U3,
                                const float* __restrict__ S0, const float* __restrict__ S1,
                                const float* __restrict__ S2, const float* __restrict__ S3,
                                const float* __restrict__ V0, const float* __restrict__ V1,
                                const float* __restrict__ V2, const float* __restrict__ V3,
                                const int* __restrict__ idx, const float* __restrict__ gates,
                                __half* __restrict__ VwAll, __half* __restrict__ UwAll)
{
    int p = blockIdx.x >> 5, b = blockIdx.x & 31;
    const float* U = (p == 0) ? U0 : (p == 1) ? U1 : (p == 2) ? U2 : U3;
    const float* Sg = (p == 0) ? S0 : (p == 1) ? S1 : (p == 2) ? S2 : S3;
    const float* V = (p == 0) ? V0 : (p == 1) ? V1 : (p == 2) ? V2 : V3;
    int tid = threadIdx.x;
    int e0 = idx[b*2], e1 = idx[b*2+1];
    float g0 = gates[b*2], g1 = gates[b*2+1];
    __half* vw = VwAll + ((long)b*128 + p*32) * DIM;
    __half* uw = UwAll + ((long)p*BATCH + b) * DIM * 32;

    for (int i = tid; i < 32*DIM; i += 256) {
        int j = i >> 10, d = i & (DIM-1);
        int k = j >> 4, r = j & 15;
        int e = k ? e1 : e0;
        vw[i] = __float2half_rn(Sg[e*RANK + r] * V[((long)e*RANK + r)*DIM + d]);
    }
    for (int i = tid; i < DIM*32; i += 256) {
        int n = i >> 5, j = i & 31;
        int k = j >> 4, r = j & 15;
        int e = k ? e1 : e0;
        float g = k ? g1 : g0;
        uw[i] = __float2half_rn(g * U[((long)e*DIM + n)*RANK + r]);
    }
}

// ---------------- FP16 MMA primitive ----------------
__device__ __forceinline__ void mma_f16(float c[4], const uint32_t a[4], const uint32_t b0, const uint32_t b1) {
    asm volatile(
        "mma.sync.aligned.m16n8k16.row.col.f32.f16.f16.f32 "
        "{%0,%1,%2,%3}, {%4,%5,%6,%7}, {%8,%9}, {%0,%1,%2,%3};"
        : "+f"(c[0]), "+f"(c[1]), "+f"(c[2]), "+f"(c[3])
        : "r"(a[0]), "r"(a[1]), "r"(a[2]), "r"(a[3]), "r"(b0), "r"(b1));
}

__device__ __forceinline__ float2 ld2(const float* p)  { return *reinterpret_cast<const float2*>(p); }
__device__ __forceinline__ float2 ld2(const __half* p) { return __half22float2(*reinterpret_cast<const half2*>(p)); }
__device__ __forceinline__ void st2(float* p, float v0, float v1)  { *reinterpret_cast<float2*>(p) = make_float2(v0, v1); }
__device__ __forceinline__ void st2(__half* p, float v0, float v1) { *reinterpret_cast<half2*>(p) = __floats2half2_rn(v0, v1); }

// f16x2 dual exp2 — one MUFU op for two values
__device__ __forceinline__ uint32_t ex2_h2(float e0, float e1) {
    half2 h = __floats2half2_rn(e0, e1);
    uint32_t in = *reinterpret_cast<uint32_t*>(&h), r;
    asm("ex2.approx.f16x2 %0, %1;" : "=r"(r) : "r"(in));
    return r;
}

// ==================== WIDE FP16 GEMM v3: 2-chunk stages, 3-stage ring (96KB) ======
// One barrier + one wait per TWO k-chunks. K=1024 fixed.
template<typename CT>
__global__ __launch_bounds__(256, 2)
void hgemm_wide2(const uint32_t* __restrict__ Ap, const uint32_t* __restrict__ Bp,
                 const float* __restrict__ bias, CT* __restrict__ C, int M, int ldc)
{
    extern __shared__ uint32_t sh[];   // 3 stages x 2 chunks x (A 2048 + B 2048) u32 = 96KB
    uint32_t shb = smem_u32(sh);
    int tid = threadIdx.x;
    int warp = tid >> 5, lane = tid & 31;
    int mt0 = (warp & 3) * 2;
    int np0 = (warp >> 2) * 4;
    int g = lane >> 2, tg = lane & 3;
    int m0 = blockIdx.y * 128, n0 = blockIdx.x * 128;

    const uint32_t* Ar = Ap + (long)blockIdx.y * 32 * 2048;
    const uint32_t* Br = Bp + (long)blockIdx.x * 32 * 2048;

    float acc[2][8][4] = {};

    auto issue = [&](int pr) {                 // copy pair pr (chunks 2pr, 2pr+1)
        uint32_t sbase = shb + (uint32_t)(pr % 3) * 32768;
        #pragma unroll
        for (int c = 0; c < 2; c++) {
            int kc = pr*2 + c;
            uint32_t d = sbase + c*16384u;
            const uint32_t* a = Ar + kc * 2048;
            const uint32_t* b = Br + kc * 2048;
            cp16(d +          tid*16, a + tid*4);
            cp16(d +  4096u + tid*16, a + 1024 + tid*4);
            cp16(d +  8192u + tid*16, b + tid*4);
            cp16(d + 12288u + tid*16, b + 1024 + tid*4);
        }
        asm volatile("cp.async.commit_group;");
    };

    issue(0);
    issue(1);

    for (int j = 0; j < 16; j++) {
        if (j < 15) asm volatile("cp.async.wait_group 1;");
        else        asm volatile("cp.async.wait_group 0;");
        __syncthreads();
        if (j + 2 < 16) issue(j + 2);

        uint32_t* stage = sh + (j % 3) * 8192;
        #pragma unroll
        for (int c = 0; c < 2; c++) {
            const uint32_t* As = stage + c*4096;
            const uint32_t* Bs = As + 2048;
            #pragma unroll
            for (int kk = 0; kk < 2; kk++) {
                uint4 a4[2];
                a4[0] = *(const uint4*)&As[((kk*8 + mt0    )*32 + lane)*4];
                a4[1] = *(const uint4*)&As[((kk*8 + mt0 + 1)*32 + lane)*4];
                uint4 bp[4];
                #pragma unroll
                for (int p = 0; p < 4; p++)
                    bp[p] = *(const uint4*)&Bs[((kk*8 + np0 + p)*32 + lane)*4];
                #pragma unroll
                for (int i = 0; i < 2; i++) {
                    uint32_t a[4] = { a4[i].x, a4[i].y, a4[i].z, a4[i].w };
                    #pragma unroll
                    for (int p = 0; p < 4; p++) {
                        mma_f16(acc[i][2*p    ], a, bp[p].x, bp[p].y);
                        mma_f16(acc[i][2*p + 1], a, bp[p].z, bp[p].w);
                    }
                }
            }
        }
    }

    #pragma unroll
    for (int i = 0; i < 2; i++) {
        #pragma unroll
        for (int rs = 0; rs < 2; rs++) {
            int gm = m0 + (mt0 + i)*16 + g + rs*8;
            if (gm >= M) continue;
            #pragma unroll
            for (int j = 0; j < 8; j++) {
                int gn = n0 + (np0*2 + j)*8 + tg*2;
                long off = (long)gm*ldc + gn;
                st2(&C[off], acc[i][j][rs*2+0] + bias[gn], acc[i][j][rs*2+1] + bias[gn+1]);
            }
        }
    }
}

// ==================== general batched FP16 GEMM (double-buffered) ====================
#define TBN 64
template<bool ACC, typename CT>
__global__ __launch_bounds__(256, 2)
void hgemm(const __half* __restrict__ A, const __half* __restrict__ B,
           CT* __restrict__ C,
           int M, int N, int K, int lda, int ldb, int ldc,
           long sA1, long sA2, long sB1, long sB2, long sC1, long sC2, int zdiv)
{
    int z = blockIdx.z;
    long zq = z / zdiv, zr = z % zdiv;
    A += zq*sA1 + zr*sA2;
    B += zq*sB1 + zr*sB2;
    C += zq*sC1 + zr*sC2;

    int m0 = blockIdx.y * 128, n0 = blockIdx.x * TBN;
    __shared__ uint32_t As[2][2048];
    __shared__ uint32_t Bs[2][1024];

    int tid = threadIdx.x;
    int warp = tid >> 5, lane = tid & 31;
    int mt0 = (warp & 3) * 2;
    int np0 = (warp >> 2) * 2;
    int g = lane >> 2, tg = lane & 3;

    float acc[2][4][4] = {};
    uint4 ar[2], br;

    const int KB = K / 32;

    auto load_regs = [&](int kb) {
        int k0 = kb * 32;
        #pragma unroll
        for (int i = 0; i < 2; i++) {
            int f4 = i*256 + tid;
            int row = f4 >> 2, c8 = f4 & 3;
            int gm = m0 + row;
            ar[i] = (gm < M) ? *(const uint4*)(A + (long)gm*lda + k0 + c8*8)
                             : make_uint4(0u,0u,0u,0u);
        }
        {
            int n = tid >> 2, c8 = tid & 3;
            int gn = n0 + n;
            br = (gn < N) ? *(const uint4*)(B + (long)gn*ldb + k0 + c8*8)
                          : make_uint4(0u,0u,0u,0u);
        }
    };

    auto sts = [&](int s) {
        #pragma unroll
        for (int i = 0; i < 2; i++) {
            int f4 = i*256 + tid;
            int row = f4 >> 2, c8 = f4 & 3;
            int kk = c8 >> 1, kh = c8 & 1;
            int mt = row >> 4, w = row & 15, gg = w & 7, rh = w >> 3;
            int base = ((kk*8 + mt)*32 + gg*4)*4 + kh*2 + rh;
            As[s][base +  0] = ar[i].x;
            As[s][base +  4] = ar[i].y;
            As[s][base +  8] = ar[i].z;
            As[s][base + 12] = ar[i].w;
        }
        {
            int n = tid >> 2, c8 = tid & 3;
            int kk = c8 >> 1, kh = c8 & 1;
            int nt = n >> 3, gc = n & 7, np = nt >> 1, sub = nt & 1;
            int base = ((kk*4 + np)*32 + gc*4)*4 + sub*2 + kh;
            Bs[s][base +  0] = br.x;
            Bs[s][base +  4] = br.y;
            Bs[s][base +  8] = br.z;
            Bs[s][base + 12] = br.w;
        }
    };

    load_regs(0);
    sts(0);
    __syncthreads();

    for (int kb = 0; kb < KB; kb++) {
        int s = kb & 1;
        if (kb + 1 < KB) load_regs(kb + 1);

        #pragma unroll
        for (int kk = 0; kk < 2; kk++) {
            uint4 a4[2];
            a4[0] = *(const uint4*)&As[s][((kk*8 + mt0    )*32 + lane)*4];
            a4[1] = *(const uint4*)&As[s][((kk*8 + mt0 + 1)*32 + lane)*4];
            uint4 bp[2];
            bp[0] = *(const uint4*)&Bs[s][((kk*4 + np0    )*32 + lane)*4];
            bp[1] = *(const uint4*)&Bs[s][((kk*4 + np0 + 1)*32 + lane)*4];
            #pragma unroll
            for (int i = 0; i < 2; i++) {
                uint32_t a[4] = { a4[i].x, a4[i].y, a4[i].z, a4[i].w };
                #pragma unroll
                for (int p = 0; p < 2; p++) {
                    mma_f16(acc[i][2*p    ], a, bp[p].x, bp[p].y);
                    mma_f16(acc[i][2*p + 1], a, bp[p].z, bp[p].w);
                }
            }
        }

        if (kb + 1 < KB) {
            sts(s ^ 1);
            __syncthreads();
        }
    }

    #pragma unroll
    for (int i = 0; i < 2; i++) {
        #pragma unroll
        for (int rs = 0; rs < 2; rs++) {
            int gm = m0 + (mt0 + i)*16 + g + rs*8;
            if (gm >= M) continue;
            #pragma unroll
            for (int j = 0; j < 4; j++) {
                int gn = n0 + (np0*2 + j)*8 + tg*2;
                if (gn >= N) continue;
                long off = (long)gm*ldc + gn;
                float v0 = acc[i][j][rs*2+0];
                float v1 = acc[i][j][rs*2+1];
                if (ACC) { float2 c2 = ld2(&C[off]); v0 += c2.x; v1 += c2.y; }
                st2(&C[off], v0, v1);
            }
        }
    }
}

// ==================== FLASH ATTENTION (fp16 in, fp32 accum, f16x2 exp) ====================
__global__ __launch_bounds__(256)
void flash_kernel(const __half* __restrict__ qkv, __half* __restrict__ ctx)
{
    __shared__ uint32_t ks[2048];
    __shared__ uint32_t vs[2048];
    __shared__ uint32_t ps[4096];

    int tid = threadIdx.x, warp = tid >> 5, lane = tid & 31;
    int g = lane >> 2, tg = lane & 3;
    int bh = blockIdx.y;
    int b = bh >> 4, h = bh & 15;
    int m0 = blockIdx.x * 128;

    const __half* qb = qkv + (long)b*SEQ*QKVD + h*HDIM;
    const __half* kb = qkv + (long)b*SEQ*QKVD + DIM + h*HDIM;
    const __half* vb = qkv + (long)b*SEQ*QKVD + 2*DIM + h*HDIM;

    int r0 = m0 + warp*16 + g;
    int r1 = r0 + 8;
    bool warp_active = (m0 + warp*16) < SEQ;

    uint32_t qa[4][4];
    if (warp_active) {
        #pragma unroll
        for (int kk = 0; kk < 4; kk++) {
            qa[kk][0] = (r0 < SEQ) ? *(const uint32_t*)(qb + (long)r0*QKVD + kk*16 + 2*tg)     : 0u;
            qa[kk][1] = (r1 < SEQ) ? *(const uint32_t*)(qb + (long)r1*QKVD + kk*16 + 2*tg)     : 0u;
            qa[kk][2] = (r0 < SEQ) ? *(const uint32_t*)(qb + (long)r0*QKVD + kk*16 + 8 + 2*tg) : 0u;
            qa[kk][3] = (r1 < SEQ) ? *(const uint32_t*)(qb + (long)r1*QKVD + kk*16 + 8 + 2*tg) : 0u;
        }
    }

    float o[8][4] = {};
    float m0r = -1e30f, m1r = -1e30f, l0r = 0.f, l1r = 0.f;
    const float LOG2E = 1.4426950408889634f;

    for (int j = 0; j < 5; j++) {
        int kv0 = j * 64;
        #pragma unroll
        for (int i = 0; i < 2; i++) {
            int f4 = i*256 + tid;
            int n = f4 >> 3, c8 = f4 & 7;
            int gr = kv0 + n;
            uint4 v = (gr < SEQ) ? *(const uint4*)(kb + (long)gr*QKVD + c8*8)
                                 : make_uint4(0u,0u,0u,0u);
            int kk = c8 >> 1, kh = c8 & 1;
            int nt = n >> 3, gc = n & 7;
            int base = ((kk*8 + nt)*32 + gc*4)*2 + kh;
            ks[base + 0] = v.x;
            ks[base + 2] = v.y;
            ks[base + 4] = v.z;
            ks[base + 6] = v.w;
        }
        {
            int kvpair = tid >> 3, nt = tid & 7;
            int rA = kv0 + kvpair*2, rB = rA + 1;
            union { uint4 u; __half hx[8]; } ua, ub;
            ua.u = (rA < SEQ) ? *(const uint4*)(vb + (long)rA*QKVD + nt*8) : make_uint4(0u,0u,0u,0u);
            ub.u = (rB < SEQ) ? *(const uint4*)(vb + (long)rB*QKVD + nt*8) : make_uint4(0u,0u,0u,0u);
            int klocal = kvpair*2;
            int kk = klocal >> 4, kin = klocal & 15;
            int kh = kin >> 3, t = (kin & 7) >> 1;
            #pragma unroll
            for (int jj = 0; jj < 8; jj++) {
                half2 h2 = __halves2half2(ua.hx[jj], ub.hx[jj]);
                vs[((kk*8 + nt)*32 + jj*4 + t)*2 + kh] = *reinterpret_cast<uint32_t*>(&h2);
            }
        }
        __syncthreads();

        if (warp_active) {
            float s[8][4] = {};
            #pragma unroll
            for (int kk = 0; kk < 4; kk++) {
                #pragma unroll
                for (int nt = 0; nt < 8; nt++) {
                    uint2 bb = *(const uint2*)&ks[((kk*8 + nt)*32 + lane)*2];
                    mma_f16(s[nt], qa[kk], bb.x, bb.y);
                }
            }

            float tmax0 = -1e30f, tmax1 = -1e30f;
            #pragma unroll
            for (int nt = 0; nt < 8; nt++) {
                int c0 = kv0 + nt*8 + 2*tg;
                s[nt][0] = (c0     < SEQ) ? s[nt][0]*ATTN_SCALE : -1e30f;
                s[nt][1] = (c0 + 1 < SEQ) ? s[nt][1]*ATTN_SCALE : -1e30f;
                s[nt][2] = (c0     < SEQ) ? s[nt][2]*ATTN_SCALE : -1e30f;
                s[nt][3] = (c0 + 1 < SEQ) ? s[nt][3]*ATTN_SCALE : -1e30f;
                tmax0 = fmaxf(tmax0, fmaxf(s[nt][0], s[nt][1]));
                tmax1 = fmaxf(tmax1, fmaxf(s[nt][2], s[nt][3]));
            }
            tmax0 = fmaxf(tmax0, __shfl_xor_sync(0xffffffffu, tmax0, 1));
            tmax0 = fmaxf(tmax0, __shfl_xor_sync(0xffffffffu, tmax0, 2));
            tmax1 = fmaxf(tmax1, __shfl_xor_sync(0xffffffffu, tmax1, 1));
            tmax1 = fmaxf(tmax1, __shfl_xor_sync(0xffffffffu, tmax1, 2));
            float nm0 = fmaxf(m0r, tmax0), nm1 = fmaxf(m1r, tmax1);
            float f0 = __expf(m0r - nm0), f1 = __expf(m1r - nm1);

            float sum0 = 0.f, sum1 = 0.f;
            #pragma unroll
            for (int nt = 0; nt < 8; nt++) {
                uint32_t r01 = ex2_h2((s[nt][0] - nm0)*LOG2E, (s[nt][1] - nm0)*LOG2E);
                uint32_t r23 = ex2_h2((s[nt][2] - nm1)*LOG2E, (s[nt][3] - nm1)*LOG2E);
                float2 f01 = __half22float2(*reinterpret_cast<half2*>(&r01));
                float2 f23 = __half22float2(*reinterpret_cast<half2*>(&r23));
                sum0 += f01.x + f01.y;
                sum1 += f23.x + f23.y;
                int kkp = nt >> 1, kh = nt & 1;
                int base = ((kkp*8 + warp)*32 + lane)*4 + kh*2;
                ps[base + 0] = r01;
                ps[base + 1] = r23;
            }
            sum0 += __shfl_xor_sync(0xffffffffu, sum0, 1);
            sum0 += __shfl_xor_sync(0xffffffffu, sum0, 2);
            sum1 += __shfl_xor_sync(0xffffffffu, sum1, 1);
            sum1 += __shfl_xor_sync(0xffffffffu, sum1, 2);
            l0r = l0r*f0 + sum0;
            l1r = l1r*f1 + sum1;
            m0r = nm0; m1r = nm1;
            #pragma unroll
            for (int nt = 0; nt < 8; nt++) {
                o[nt][0] *= f0; o[nt][1] *= f0;
                o[nt][2] *= f1; o[nt][3] *= f1;
            }

            #pragma unroll
            for (int kk = 0; kk < 4; kk++) {
                uint4 p4 = *(const uint4*)&ps[((kk*8 + warp)*32 + lane)*4];
                uint32_t pa[4] = { p4.x, p4.y, p4.z, p4.w };
                #pragma unroll
                for (int nt = 0; nt < 8; nt++) {
                    uint2 vv = *(const uint2*)&vs[((kk*8 + nt)*32 + lane)*2];
                    mma_f16(o[nt], pa, vv.x, vv.y);
                }
            }
        }
        __syncthreads();
    }

    if (warp_active) {
        float inv0 = 1.f / l0r, inv1 = 1.f / l1r;
        __half* cb = ctx + (long)b*SEQ*DIM + h*HDIM;
        #pragma unroll
        for (int nt = 0; nt < 8; nt++) {
            int col = nt*8 + 2*tg;
            if (r0 < SEQ) {
                half2 h2 = __floats2half2_rn(o[nt][0]*inv0, o[nt][1]*inv0);
                *reinterpret_cast<half2*>(cb + (long)r0*DIM + col) = h2;
            }
            if (r1 < SEQ) {
                half2 h2 = __floats2half2_rn(o[nt][2]*inv1, o[nt][3]*inv1);
                *reinterpret_cast<half2*>(cb + (long)r1*DIM + col) = h2;
            }
        }
    }
}

// ---------------- host launch ----------------
static void* dsym(const void* symbol) { void* p = nullptr; cudaGetSymbolAddress(&p, symbol); return p; }
static inline dim3 hgrid(int N, int M, int Z) { return dim3((N+TBN-1)/TBN, (M+127)/128, Z); }
#define WIDE2_SMEM 98304

extern "C" void kernel_launch(void* const* d_in, const int* in_sizes, int n_in,
                              void* d_out, int out_size)
{
    const float* x   = (const float*)d_in[0];
    const float* gw1 = (const float*)d_in[1];
    const float* gb1 = (const float*)d_in[2];
    const float* gw2 = (const float*)d_in[3];
    const float* gb2 = (const float*)d_in[4];
    const float* Wm[4]; const float* Ue[4]; const float* Se[4]; const float* Ve[4]; const float* bi[4];
    for (int p = 0; p < 4; p++) {
        Wm[p] = (const float*)d_in[5 + p*5 + 0];
        Ue[p] = (const float*)d_in[5 + p*5 + 1];
        Se[p] = (const float*)d_in[5 + p*5 + 2];
        Ve[p] = (const float*)d_in[5 + p*5 + 3];
        bi[p] = (const float*)d_in[5 + p*5 + 4];
    }
    float* out = (float*)d_out;

    int*      idxp   = (int*)dsym(g_idx);
    float*    gatesp = (float*)dsym(g_gates);
    float*    pooled = (float*)dsym(g_pooled);
    float*    bcat   = (float*)dsym(g_bcat);
    __half*   xh     = (__half*)dsym(g_xh);
    uint32_t* xhp    = (uint32_t*)dsym(g_xhp);
    uint32_t* Wmp    = (uint32_t*)dsym(g_Wmp);
    uint32_t* ctxp   = (uint32_t*)dsym(g_ctxp);
    __half*   Vw     = (__half*)dsym(g_Vw);
    __half*   Uw     = (__half*)dsym(g_Uw);
    __half*   tbuf   = (__half*)dsym(g_t);
    __half*   t3     = (__half*)dsym(g_t3);
    __half*   qkv    = (__half*)dsym(g_qkv);
    __half*   ctx    = (__half*)dsym(g_ctx);

    const long UW_PER = (long)BATCH*DIM*32;

    cudaFuncSetAttribute(hgemm_wide2<__half>, cudaFuncAttributeMaxDynamicSharedMemorySize, WIDE2_SMEM);
    cudaFuncSetAttribute(hgemm_wide2<float>,  cudaFuncAttributeMaxDynamicSharedMemorySize, WIDE2_SMEM);

    // 0..2: dependencies of the wide QKV GEMM
    cvt_xp_kernel<<<(MBLK*32*512 + 255)/256, 256>>>(x, xhp);                       // 0
    cvt4p_kernel<<<(32*32*512 + 255)/256, 256>>>(Wm[0], Wm[1], Wm[2], Wm[3], Wmp); // 1
    concat_bias_kernel<<<12, 256>>>(bi[0], bi[1], bi[2], bcat);                    // 2

    // 3: fused main projection (4th-launch slot for ncu capture)
    hgemm_wide2<__half><<<dim3(QKVD/128, MBLK), 256, WIDE2_SMEM>>>(
        xhp, Wmp, bcat, qkv, MROWS, QKVD);

    // 4..7: gating path + row-major fp16 x + expert folding
    cvt_kernel<<<1184, 256>>>(x, xh, (long)MROWS*DIM);                             // 4
    pool_kernel<<<dim3(8, BATCH), 256>>>(x, pooled);                               // 5
    gating_kernel<<<BATCH, 256>>>(pooled, gw1, gb1, gw2, gb2, idxp, gatesp);       // 6
    build_uv_kernel<<<128, 256>>>(Ue[0], Ue[1], Ue[2], Ue[3],
                                  Se[0], Se[1], Se[2], Se[3],
                                  Ve[0], Ve[1], Ve[2], Ve[3],
                                  idxp, gatesp, Vw, Uw);                           // 7

    // 8: fused xV for q,k,v in ONE launch: t[b] = x_b @ Vw_b[0:96]^T  (N=96)
    hgemm<false,__half><<<hgrid(96, SEQ, BATCH), 256>>>(
        xh, Vw, tbuf,
        SEQ, 96, DIM, DIM, DIM, 96,
        0, (long)SD, 0, (long)128*DIM, 0, (long)SEQ*96, BATCH);

    // 9: fused expert accumulate: qkv[:, p*1024 + n] += t[:, p*32:(p+1)*32] @ Uw_p^T
    hgemm<true,__half><<<hgrid(DIM, SEQ, 3*BATCH), 256>>>(
        tbuf, Uw, qkv,
        SEQ, DIM, 32, 96, 32, QKVD,
        32, (long)SEQ*96, UW_PER, (long)DIM*32, (long)DIM, (long)SEQ*QKVD, BATCH);

    // 10: flash attention
    flash_kernel<<<dim3(3, BATCH*NHEAD), 256>>>(qkv, ctx);

    // 11: ctx low-rank projection: t3[b] = ctx_b @ Vw_b[96:128]^T
    hgemm<false,__half><<<hgrid(32, SEQ, BATCH), 256>>>(
        ctx, Vw + 96*DIM, t3,
        SEQ, 32, DIM, DIM, DIM, 32,
        0, (long)SD, 0, (long)128*DIM, 0, (long)SEQ*32, BATCH);

    // 12: permute ctx for the wide out-projection
    ctxp_kernel<<<(MBLK*32*512 + 255)/256, 256>>>(ctx, ctxp);

    // 13: out = ctx @ Wo^T + bo (fp32 out)
    hgemm_wide2<float><<<dim3(DIM/128, MBLK), 256, WIDE2_SMEM>>>(
        ctxp, Wmp + (long)24*32*2048, bi[3], out, MROWS, DIM);

    // 14: out += t3 @ Uw3^T (fp32 accumulate)
    hgemm<true,float><<<hgrid(DIM, SEQ, BATCH), 256>>>(
        t3, Uw + 3*UW_PER, out,
        SEQ, DIM, 32, 32, 32, DIM,
        0, (long)SEQ*32, 0, (long)DIM*32, 0, (long)SD, BATCH);
}

// round 12
// speedup vs baseline: 7.2799x; 1.1104x over previous
#include <cuda_runtime.h>
#include <cuda_fp16.h>
#include <math.h>
#include <stdint.h>

// ---------------- problem constants ----------------
#define BATCH 32
#define SEQ   257
#define DIM   1024
#define QKVD  3072
#define NHEAD 16
#define HDIM  64
#define NEXP  8
#define TOPK  2
#define RANK  16
#define GHID  256
#define SD    (SEQ*DIM)
#define MROWS (BATCH*SEQ)        // 8224
#define MBLK  65                 // ceil(8224/128)
#define ATTN_SCALE 0.125f

// ---------------- static device scratch ----------------
__device__ int   g_idx[BATCH*TOPK];
__device__ float g_gates[BATCH*TOPK];
__device__ float g_pooled[BATCH*DIM];
__device__ float g_bcat[QKVD];
__device__ __align__(16) __half   g_xh [MROWS*DIM];
__device__ __align__(16) uint32_t g_xhp[(long)MBLK*32*2048];    // permuted x (A frag order)
__device__ __align__(16) uint32_t g_Wmp[(long)32*32*2048];      // permuted weights (B frag order)
__device__ __align__(16) uint32_t g_ctxp[(long)MBLK*32*2048];   // permuted ctx
__device__ __align__(16) __half g_Vw[(long)BATCH*128*DIM];      // [b][p*32+j][d]
__device__ __align__(16) __half g_Uw[4ll*BATCH*DIM*32];         // [p][b][n][j]
__device__ __align__(16) __half g_t [(long)BATCH*SEQ*96];       // qkv low-rank t [b][s][96]
__device__ __align__(16) __half g_t3[(long)BATCH*SEQ*32];       // o low-rank t
__device__ __align__(16) __half g_qkv[(long)(MROWS+32)*QKVD];
__device__ __align__(16) __half g_ctx[MROWS*DIM];

__device__ __forceinline__ uint32_t smem_u32(const void* p) {
    uint32_t a;
    asm("{ .reg .u64 t; cvta.to.shared.u64 t, %1; cvt.u32.u64 %0, t; }" : "=r"(a) : "l"(p));
    return a;
}
__device__ __forceinline__ void cp16(uint32_t saddr, const void* g) {
    asm volatile("cp.async.cg.shared.global [%0], [%1], 16;" :: "r"(saddr), "l"(g));
}

// ---------------- conversion / permutation kernels ----------------
__global__ void cvt_kernel(const float* __restrict__ src, __half* __restrict__ dst, long n)
{
    long i = (long)blockIdx.x * blockDim.x + threadIdx.x;
    long stride = (long)gridDim.x * blockDim.x;
    for (; i < n; i += stride) dst[i] = __float2half_rn(src[i]);
}

__global__ void cvt_xp_kernel(const float* __restrict__ x, uint32_t* __restrict__ xp)
{
    long idx = (long)blockIdx.x * 256 + threadIdx.x;
    if (idx >= (long)MBLK*32*512) return;
    int q  = (int)(idx & 511);
    long r = idx >> 9;
    int kc = (int)(r & 31);
    int mb = (int)(r >> 5);
    int kk = q >> 8, mt = (q >> 5) & 7, lane = q & 31;
    int g = lane >> 2, tg = lane & 3;
    int mbase = mb*128 + mt*16 + g;
    int kbase = kc*32 + kk*16 + tg*2;
    uint32_t v[4];
    #pragma unroll
    for (int j = 0; j < 4; j++) {
        int kh = j >> 1, rh = j & 1;
        int m = mbase + rh*8;
        int kz = kbase + kh*8;
        half2 h2 = (m < MROWS)
            ? __floats2half2_rn(x[(long)m*DIM + kz], x[(long)m*DIM + kz + 1])
            : __floats2half2_rn(0.f, 0.f);
        v[j] = *reinterpret_cast<uint32_t*>(&h2);
    }
    *(uint4*)(xp + idx*4) = make_uint4(v[0], v[1], v[2], v[3]);
}

__global__ void ctxp_kernel(const __half* __restrict__ ctx, uint32_t* __restrict__ cp)
{
    long idx = (long)blockIdx.x * 256 + threadIdx.x;
    if (idx >= (long)MBLK*32*512) return;
    int q  = (int)(idx & 511);
    long r = idx >> 9;
    int kc = (int)(r & 31);
    int mb = (int)(r >> 5);
    int kk = q >> 8, mt = (q >> 5) & 7, lane = q & 31;
    int g = lane >> 2, tg = lane & 3;
    int mbase = mb*128 + mt*16 + g;
    int kbase = kc*32 + kk*16 + tg*2;
    uint32_t v[4];
    #pragma unroll
    for (int j = 0; j < 4; j++) {
        int kh = j >> 1, rh = j & 1;
        int m = mbase + rh*8;
        int kz = kbase + kh*8;
        v[j] = (m < MROWS) ? *(const uint32_t*)(ctx + (long)m*DIM + kz) : 0u;
    }
    *(uint4*)(cp + idx*4) = make_uint4(v[0], v[1], v[2], v[3]);
}

__global__ void cvt4p_kernel(const float* __restrict__ w0, const float* __restrict__ w1,
                             const float* __restrict__ w2, const float* __restrict__ w3,
                             uint32_t* __restrict__ wp)
{
    long idx = (long)blockIdx.x * 256 + threadIdx.x;
    if (idx >= (long)32*32*512) return;
    int q  = (int)(idx & 511);
    long r = idx >> 9;
    int kc = (int)(r & 31);
    int nb = (int)(r >> 5);
    int kk = q >> 8, np = (q >> 5) & 7, lane = q & 31;
    int gc = lane >> 2, tg = lane & 3;
    int kbase = kc*32 + kk*16 + tg*2;
    uint32_t v[4];
    #pragma unroll
    for (int j = 0; j < 4; j++) {
        int sub = j >> 1, kh = j & 1;
        int n = nb*128 + np*16 + sub*8 + gc;
        int p = n >> 10, row = n & 1023;
        const float* w = (p == 0) ? w0 : (p == 1) ? w1 : (p == 2) ? w2 : w3;
        int kz = kbase + kh*8;
        half2 h2 = __floats2half2_rn(w[(long)row*DIM + kz], w[(long)row*DIM + kz + 1]);
        v[j] = *reinterpret_cast<uint32_t*>(&h2);
    }
    *(uint4*)(wp + idx*4) = make_uint4(v[0], v[1], v[2], v[3]);
}

__global__ void concat_bias_kernel(const float* __restrict__ b0, const float* __restrict__ b1,
                                   const float* __restrict__ b2, float* __restrict__ dst)
{
    int i = blockIdx.x * 256 + threadIdx.x;
    if (i < DIM) dst[i] = b0[i];
    else if (i < 2*DIM) dst[i] = b1[i - DIM];
    else if (i < 3*DIM) dst[i] = b2[i - 2*DIM];
}

// ---------------- pooling (fp32, exact) ----------------
__global__ void pool_kernel(const float* __restrict__ x, float* __restrict__ pooled)
{
    int b = blockIdx.y;
    int d = blockIdx.x * 128 + (threadIdx.x & 127);
    int half = threadIdx.x >> 7;
    const float* xb = x + (long)b*SD + d;
    int t0 = half * 129;
    int t1 = half ? SEQ : 129;
    float s = 0.f;
    for (int t = t0; t < t1; t++) s += xb[(long)t*DIM];
    __shared__ float red[256];
    red[threadIdx.x] = s;
    __syncthreads();
    if (half == 0)
        pooled[b*DIM + d] = (red[threadIdx.x] + red[threadIdx.x + 128]) * (1.0f / SEQ);
}

// ---------------- gating MLP (exact fp32, float4 loads) ----------------
__global__ void gating_kernel(const float* __restrict__ pooled,
                              const float* __restrict__ gw1, const float* __restrict__ gb1,
                              const float* __restrict__ gw2, const float* __restrict__ gb2,
                              int* __restrict__ idx, float* __restrict__ gates)
{
    int b = blockIdx.x;
    int tid = threadIdx.x;
    __shared__ float pl[DIM];
    __shared__ float h[GHID];
    __shared__ float logits[NEXP];

    for (int d = tid; d < DIM; d += 256) pl[d] = pooled[b*DIM + d];
    __syncthreads();
    {
        float s = gb1[tid];
        const float4* w4 = (const float4*)(gw1 + (long)tid * DIM);
        #pragma unroll 4
        for (int d = 0; d < DIM/4; d++) {
            float4 wv = w4[d];
            const float* pv = &pl[d*4];
            s += pv[0]*wv.x + pv[1]*wv.y + pv[2]*wv.z + pv[3]*wv.w;
        }
        h[tid] = fmaxf(s, 0.f);
    }
    __syncthreads();
    if (tid < NEXP) {
        float s = gb2[tid];
        const float* w = gw2 + (long)tid * GHID;
        for (int g = 0; g < GHID; g++) s += h[g] * w[g];
        logits[tid] = s;
    }
    __syncthreads();
    if (tid == 0) {
        int i1 = 0; float v1 = logits[0];
        for (int e = 1; e < NEXP; e++) if (logits[e] > v1) { v1 = logits[e]; i1 = e; }
        int i2 = -1; float v2 = -3.0e38f;
        for (int e = 0; e < NEXP; e++) if (e != i1 && logits[e] > v2) { v2 = logits[e]; i2 = e; }
        float e2 = expf(v2 - v1);
        float inv = 1.f / (1.f + e2);
        idx[b*2] = i1; idx[b*2+1] = i2;
        gates[b*2] = inv; gates[b*2+1] = e2 * inv;
    }
}

// ---------------- fused fold: Vw -> [b][p*32+j][d], Uw -> [p][b][n][j] ----------------
__global__ void build_uv_kernel(const float* __restrict__ U0, const float* __restrict__ U1,
                                const float* __restrict__ U2, const float* __restrict__ U3,
                                const float* __restrict__ S0, const float* __restrict__ S1,
                                const float* __restrict__ S2, const float* __restrict__ S3,
                                const float* __restrict__ V0, const float* __restrict__ V1,
                                const float* __restrict__ V2, const float* __restrict__ V3,
                                const int* __restrict__ idx, const float* __restrict__ gates,
                                __half* __restrict__ VwAll, __half* __restrict__ UwAll)
{
    int p = blockIdx.x >> 5, b = blockIdx.x & 31;
    const float* U = (p == 0) ? U0 : (p == 1) ? U1 : (p == 2) ? U2 : U3;
    const float* Sg = (p == 0) ? S0 : (p == 1) ? S1 : (p == 2) ? S2 : S3;
    const float* V = (p == 0) ? V0 : (p == 1) ? V1 : (p == 2) ? V2 : V3;
    int tid = threadIdx.x;
    int e0 = idx[b*2], e1 = idx[b*2+1];
    float g0 = gates[b*2], g1 = gates[b*2+1];
    __half* vw = VwAll + ((long)b*128 + p*32) * DIM;
    __half* uw = UwAll + ((long)p*BATCH + b) * DIM * 32;

    for (int i = tid; i < 32*DIM; i += 256) {
        int j = i >> 10, d = i & (DIM-1);
        int k = j >> 4, r = j & 15;
        int e = k ? e1 : e0;
        vw[i] = __float2half_rn(Sg[e*RANK + r] * V[((long)e*RANK + r)*DIM + d]);
    }
    for (int i = tid; i < DIM*32; i += 256) {
        int n = i >> 5, j = i & 31;
        int k = j >> 4, r = j & 15;
        int e = k ? e1 : e0;
        float g = k ? g1 : g0;
        uw[i] = __float2half_rn(g * U[((long)e*DIM + n)*RANK + r]);
    }
}

// ---------------- FP16 MMA primitive ----------------
__device__ __forceinline__ void mma_f16(float c[4], const uint32_t a[4], const uint32_t b0, const uint32_t b1) {
    asm volatile(
        "mma.sync.aligned.m16n8k16.row.col.f32.f16.f16.f32 "
        "{%0,%1,%2,%3}, {%4,%5,%6,%7}, {%8,%9}, {%0,%1,%2,%3};"
        : "+f"(c[0]), "+f"(c[1]), "+f"(c[2]), "+f"(c[3])
        : "r"(a[0]), "r"(a[1]), "r"(a[2]), "r"(a[3]), "r"(b0), "r"(b1));
}

__device__ __forceinline__ float2 ld2(const float* p)  { return *reinterpret_cast<const float2*>(p); }
__device__ __forceinline__ float2 ld2(const __half* p) { return __half22float2(*reinterpret_cast<const half2*>(p)); }
__device__ __forceinline__ void st2(float* p, float v0, float v1)  { *reinterpret_cast<float2*>(p) = make_float2(v0, v1); }
__device__ __forceinline__ void st2(__half* p, float v0, float v1) { *reinterpret_cast<half2*>(p) = __floats2half2_rn(v0, v1); }

__device__ __forceinline__ uint32_t ex2_h2(float e0, float e1) {
    half2 h = __floats2half2_rn(e0, e1);
    uint32_t in = *reinterpret_cast<uint32_t*>(&h), r;
    asm("ex2.approx.f16x2 %0, %1;" : "=r"(r) : "r"(in));
    return r;
}

// ==================== WIDE FP16 GEMM v3: 2-chunk stages, 3-stage ring (96KB) ======
template<typename CT>
__global__ __launch_bounds__(256, 2)
void hgemm_wide2(const uint32_t* __restrict__ Ap, const uint32_t* __restrict__ Bp,
                 const float* __restrict__ bias, CT* __restrict__ C, int M, int ldc)
{
    extern __shared__ uint32_t sh[];
    uint32_t shb = smem_u32(sh);
    int tid = threadIdx.x;
    int warp = tid >> 5, lane = tid & 31;
    int mt0 = (warp & 3) * 2;
    int np0 = (warp >> 2) * 4;
    int g = lane >> 2, tg = lane & 3;
    int m0 = blockIdx.y * 128, n0 = blockIdx.x * 128;

    const uint32_t* Ar = Ap + (long)blockIdx.y * 32 * 2048;
    const uint32_t* Br = Bp + (long)blockIdx.x * 32 * 2048;

    float acc[2][8][4] = {};

    auto issue = [&](int pr) {
        uint32_t sbase = shb + (uint32_t)(pr % 3) * 32768;
        #pragma unroll
        for (int c = 0; c < 2; c++) {
            int kc = pr*2 + c;
            uint32_t d = sbase + c*16384u;
            const uint32_t* a = Ar + kc * 2048;
            const uint32_t* b = Br + kc * 2048;
            cp16(d +          tid*16, a + tid*4);
            cp16(d +  4096u + tid*16, a + 1024 + tid*4);
            cp16(d +  8192u + tid*16, b + tid*4);
            cp16(d + 12288u + tid*16, b + 1024 + tid*4);
        }
        asm volatile("cp.async.commit_group;");
    };

    issue(0);
    issue(1);

    for (int j = 0; j < 16; j++) {
        if (j < 15) asm volatile("cp.async.wait_group 1;");
        else        asm volatile("cp.async.wait_group 0;");
        __syncthreads();
        if (j + 2 < 16) issue(j + 2);

        uint32_t* stage = sh + (j % 3) * 8192;
        #pragma unroll
        for (int c = 0; c < 2; c++) {
            const uint32_t* As = stage + c*4096;
            const uint32_t* Bs = As + 2048;
            #pragma unroll
            for (int kk = 0; kk < 2; kk++) {
                uint4 a4[2];
                a4[0] = *(const uint4*)&As[((kk*8 + mt0    )*32 + lane)*4];
                a4[1] = *(const uint4*)&As[((kk*8 + mt0 + 1)*32 + lane)*4];
                uint4 bp[4];
                #pragma unroll
                for (int p = 0; p < 4; p++)
                    bp[p] = *(const uint4*)&Bs[((kk*8 + np0 + p)*32 + lane)*4];
                #pragma unroll
                for (int i = 0; i < 2; i++) {
                    uint32_t a[4] = { a4[i].x, a4[i].y, a4[i].z, a4[i].w };
                    #pragma unroll
                    for (int p = 0; p < 4; p++) {
                        mma_f16(acc[i][2*p    ], a, bp[p].x, bp[p].y);
                        mma_f16(acc[i][2*p + 1], a, bp[p].z, bp[p].w);
                    }
                }
            }
        }
    }

    #pragma unroll
    for (int i = 0; i < 2; i++) {
        #pragma unroll
        for (int rs = 0; rs < 2; rs++) {
            int gm = m0 + (mt0 + i)*16 + g + rs*8;
            if (gm >= M) continue;
            #pragma unroll
            for (int j = 0; j < 8; j++) {
                int gn = n0 + (np0*2 + j)*8 + tg*2;
                long off = (long)gm*ldc + gn;
                st2(&C[off], acc[i][j][rs*2+0] + bias[gn], acc[i][j][rs*2+1] + bias[gn+1]);
            }
        }
    }
}

// ==================== general batched FP16 GEMM (double-buffered) ====================
#define TBN 64
template<bool ACC, typename CT>
__global__ __launch_bounds__(256, 2)
void hgemm(const __half* __restrict__ A, const __half* __restrict__ B,
           CT* __restrict__ C,
           int M, int N, int K, int lda, int ldb, int ldc,
           long sA1, long sA2, long sB1, long sB2, long sC1, long sC2, int zdiv)
{
    int z = blockIdx.z;
    long zq = z / zdiv, zr = z % zdiv;
    A += zq*sA1 + zr*sA2;
    B += zq*sB1 + zr*sB2;
    C += zq*sC1 + zr*sC2;

    int m0 = blockIdx.y * 128, n0 = blockIdx.x * TBN;
    __shared__ uint32_t As[2][2048];
    __shared__ uint32_t Bs[2][1024];

    int tid = threadIdx.x;
    int warp = tid >> 5, lane = tid & 31;
    int mt0 = (warp & 3) * 2;
    int np0 = (warp >> 2) * 2;
    int g = lane >> 2, tg = lane & 3;

    float acc[2][4][4] = {};
    uint4 ar[2], br;

    const int KB = K / 32;

    auto load_regs = [&](int kb) {
        int k0 = kb * 32;
        #pragma unroll
        for (int i = 0; i < 2; i++) {
            int f4 = i*256 + tid;
            int row = f4 >> 2, c8 = f4 & 3;
            int gm = m0 + row;
            ar[i] = (gm < M) ? *(const uint4*)(A + (long)gm*lda + k0 + c8*8)
                             : make_uint4(0u,0u,0u,0u);
        }
        {
            int n = tid >> 2, c8 = tid & 3;
            int gn = n0 + n;
            br = (gn < N) ? *(const uint4*)(B + (long)gn*ldb + k0 + c8*8)
                          : make_uint4(0u,0u,0u,0u);
        }
    };

    auto sts = [&](int s) {
        #pragma unroll
        for (int i = 0; i < 2; i++) {
            int f4 = i*256 + tid;
            int row = f4 >> 2, c8 = f4 & 3;
            int kk = c8 >> 1, kh = c8 & 1;
            int mt = row >> 4, w = row & 15, gg = w & 7, rh = w >> 3;
            int base = ((kk*8 + mt)*32 + gg*4)*4 + kh*2 + rh;
            As[s][base +  0] = ar[i].x;
            As[s][base +  4] = ar[i].y;
            As[s][base +  8] = ar[i].z;
            As[s][base + 12] = ar[i].w;
        }
        {
            int n = tid >> 2, c8 = tid & 3;
            int kk = c8 >> 1, kh = c8 & 1;
            int nt = n >> 3, gc = n & 7, np = nt >> 1, sub = nt & 1;
            int base = ((kk*4 + np)*32 + gc*4)*4 + sub*2 + kh;
            Bs[s][base +  0] = br.x;
            Bs[s][base +  4] = br.y;
            Bs[s][base +  8] = br.z;
            Bs[s][base + 12] = br.w;
        }
    };

    load_regs(0);
    sts(0);
    __syncthreads();

    for (int kb = 0; kb < KB; kb++) {
        int s = kb & 1;
        if (kb + 1 < KB) load_regs(kb + 1);

        #pragma unroll
        for (int kk = 0; kk < 2; kk++) {
            uint4 a4[2];
            a4[0] = *(const uint4*)&As[s][((kk*8 + mt0    )*32 + lane)*4];
            a4[1] = *(const uint4*)&As[s][((kk*8 + mt0 + 1)*32 + lane)*4];
            uint4 bp[2];
            bp[0] = *(const uint4*)&Bs[s][((kk*4 + np0    )*32 + lane)*4];
            bp[1] = *(const uint4*)&Bs[s][((kk*4 + np0 + 1)*32 + lane)*4];
            #pragma unroll
            for (int i = 0; i < 2; i++) {
                uint32_t a[4] = { a4[i].x, a4[i].y, a4[i].z, a4[i].w };
                #pragma unroll
                for (int p = 0; p < 2; p++) {
                    mma_f16(acc[i][2*p    ], a, bp[p].x, bp[p].y);
                    mma_f16(acc[i][2*p + 1], a, bp[p].z, bp[p].w);
                }
            }
        }

        if (kb + 1 < KB) {
            sts(s ^ 1);
            __syncthreads();
        }
    }

    #pragma unroll
    for (int i = 0; i < 2; i++) {
        #pragma unroll
        for (int rs = 0; rs < 2; rs++) {
            int gm = m0 + (mt0 + i)*16 + g + rs*8;
            if (gm >= M) continue;
            #pragma unroll
            for (int j = 0; j < 4; j++) {
                int gn = n0 + (np0*2 + j)*8 + tg*2;
                if (gn >= N) continue;
                long off = (long)gm*ldc + gn;
                float v0 = acc[i][j][rs*2+0];
                float v1 = acc[i][j][rs*2+1];
                if (ACC) { float2 c2 = ld2(&C[off]); v0 += c2.x; v1 += c2.y; }
                st2(&C[off], v0, v1);
            }
        }
    }
}

// ==================== FLASH ATTENTION rows 0..255 (no row predicates) ====================
__global__ __launch_bounds__(256)
void flash_kernel(const __half* __restrict__ qkv, __half* __restrict__ ctx)
{
    __shared__ uint32_t ks[2048];
    __shared__ uint32_t vs[2048];
    __shared__ uint32_t ps[4096];

    int tid = threadIdx.x, warp = tid >> 5, lane = tid & 31;
    int g = lane >> 2, tg = lane & 3;
    int bh = blockIdx.y;
    int b = bh >> 4, h = bh & 15;
    int m0 = blockIdx.x * 128;

    const __half* qb = qkv + (long)b*SEQ*QKVD + h*HDIM;
    const __half* kb = qkv + (long)b*SEQ*QKVD + DIM + h*HDIM;
    const __half* vb = qkv + (long)b*SEQ*QKVD + 2*DIM + h*HDIM;

    int r0 = m0 + warp*16 + g;      // always < 256
    int r1 = r0 + 8;

    uint32_t qa[4][4];
    #pragma unroll
    for (int kk = 0; kk < 4; kk++) {
        qa[kk][0] = *(const uint32_t*)(qb + (long)r0*QKVD + kk*16 + 2*tg);
        qa[kk][1] = *(const uint32_t*)(qb + (long)r1*QKVD + kk*16 + 2*tg);
        qa[kk][2] = *(const uint32_t*)(qb + (long)r0*QKVD + kk*16 + 8 + 2*tg);
        qa[kk][3] = *(const uint32_t*)(qb + (long)r1*QKVD + kk*16 + 8 + 2*tg);
    }

    float o[8][4] = {};
    float m0r = -1e30f, m1r = -1e30f, l0r = 0.f, l1r = 0.f;
    const float LOG2E = 1.4426950408889634f;

    for (int j = 0; j < 5; j++) {
        int kv0 = j * 64;
        #pragma unroll
        for (int i = 0; i < 2; i++) {
            int f4 = i*256 + tid;
            int n = f4 >> 3, c8 = f4 & 7;
            int gr = kv0 + n;
            uint4 v = (gr < SEQ) ? *(const uint4*)(kb + (long)gr*QKVD + c8*8)
                                 : make_uint4(0u,0u,0u,0u);
            int kk = c8 >> 1, kh = c8 & 1;
            int nt = n >> 3, gc = n & 7;
            int base = ((kk*8 + nt)*32 + gc*4)*2 + kh;
            ks[base + 0] = v.x;
            ks[base + 2] = v.y;
            ks[base + 4] = v.z;
            ks[base + 6] = v.w;
        }
        {
            int kvpair = tid >> 3, nt = tid & 7;
            int rA = kv0 + kvpair*2, rB = rA + 1;
            union { uint4 u; __half hx[8]; } ua, ub;
            ua.u = (rA < SEQ) ? *(const uint4*)(vb + (long)rA*QKVD + nt*8) : make_uint4(0u,0u,0u,0u);
            ub.u = (rB < SEQ) ? *(const uint4*)(vb + (long)rB*QKVD + nt*8) : make_uint4(0u,0u,0u,0u);
            int klocal = kvpair*2;
            int kk = klocal >> 4, kin = klocal & 15;
            int kh = kin >> 3, t = (kin & 7) >> 1;
            #pragma unroll
            for (int jj = 0; jj < 8; jj++) {
                half2 h2 = __halves2half2(ua.hx[jj], ub.hx[jj]);
                vs[((kk*8 + nt)*32 + jj*4 + t)*2 + kh] = *reinterpret_cast<uint32_t*>(&h2);
            }
        }
        __syncthreads();

        float s[8][4] = {};
        #pragma unroll
        for (int kk = 0; kk < 4; kk++) {
            #pragma unroll
            for (int nt = 0; nt < 8; nt++) {
                uint2 bb = *(const uint2*)&ks[((kk*8 + nt)*32 + lane)*2];
                mma_f16(s[nt], qa[kk], bb.x, bb.y);
            }
        }

        float tmax0 = -1e30f, tmax1 = -1e30f;
        #pragma unroll
        for (int nt = 0; nt < 8; nt++) {
            int c0 = kv0 + nt*8 + 2*tg;
            s[nt][0] = (c0     < SEQ) ? s[nt][0]*ATTN_SCALE : -1e30f;
            s[nt][1] = (c0 + 1 < SEQ) ? s[nt][1]*ATTN_SCALE : -1e30f;
            s[nt][2] = (c0     < SEQ) ? s[nt][2]*ATTN_SCALE : -1e30f;
            s[nt][3] = (c0 + 1 < SEQ) ? s[nt][3]*ATTN_SCALE : -1e30f;
            tmax0 = fmaxf(tmax0, fmaxf(s[nt][0], s[nt][1]));
            tmax1 = fmaxf(tmax1, fmaxf(s[nt][2], s[nt][3]));
        }
        tmax0 = fmaxf(tmax0, __shfl_xor_sync(0xffffffffu, tmax0, 1));
        tmax0 = fmaxf(tmax0, __shfl_xor_sync(0xffffffffu, tmax0, 2));
        tmax1 = fmaxf(tmax1, __shfl_xor_sync(0xffffffffu, tmax1, 1));
        tmax1 = fmaxf(tmax1, __shfl_xor_sync(0xffffffffu, tmax1, 2));
        float nm0 = fmaxf(m0r, tmax0), nm1 = fmaxf(m1r, tmax1);
        float f0 = __expf(m0r - nm0), f1 = __expf(m1r - nm1);

        float sum0 = 0.f, sum1 = 0.f;
        #pragma unroll
        for (int nt = 0; nt < 8; nt++) {
            uint32_t r01 = ex2_h2((s[nt][0] - nm0)*LOG2E, (s[nt][1] - nm0)*LOG2E);
            uint32_t r23 = ex2_h2((s[nt][2] - nm1)*LOG2E, (s[nt][3] - nm1)*LOG2E);
            float2 f01 = __half22float2(*reinterpret_cast<half2*>(&r01));
            float2 f23 = __half22float2(*reinterpret_cast<half2*>(&r23));
            sum0 += f01.x + f01.y;
            sum1 += f23.x + f23.y;
            int kkp = nt >> 1, kh = nt & 1;
            int base = ((kkp*8 + warp)*32 + lane)*4 + kh*2;
            ps[base + 0] = r01;
            ps[base + 1] = r23;
        }
        sum0 += __shfl_xor_sync(0xffffffffu, sum0, 1);
        sum0 += __shfl_xor_sync(0xffffffffu, sum0, 2);
        sum1 += __shfl_xor_sync(0xffffffffu, sum1, 1);
        sum1 += __shfl_xor_sync(0xffffffffu, sum1, 2);
        l0r = l0r*f0 + sum0;
        l1r = l1r*f1 + sum1;
        m0r = nm0; m1r = nm1;
        #pragma unroll
        for (int nt = 0; nt < 8; nt++) {
            o[nt][0] *= f0; o[nt][1] *= f0;
            o[nt][2] *= f1; o[nt][3] *= f1;
        }

        #pragma unroll
        for (int kk = 0; kk < 4; kk++) {
            uint4 p4 = *(const uint4*)&ps[((kk*8 + warp)*32 + lane)*4];
            uint32_t pa[4] = { p4.x, p4.y, p4.z, p4.w };
            #pragma unroll
            for (int nt = 0; nt < 8; nt++) {
                uint2 vv = *(const uint2*)&vs[((kk*8 + nt)*32 + lane)*2];
                mma_f16(o[nt], pa, vv.x, vv.y);
            }
        }
        __syncthreads();
    }

    float inv0 = 1.f / l0r, inv1 = 1.f / l1r;
    __half* cb = ctx + (long)b*SEQ*DIM + h*HDIM;
    #pragma unroll
    for (int nt = 0; nt < 8; nt++) {
        int col = nt*8 + 2*tg;
        half2 h2a = __floats2half2_rn(o[nt][0]*inv0, o[nt][1]*inv0);
        *reinterpret_cast<half2*>(cb + (long)r0*DIM + col) = h2a;
        half2 h2b = __floats2half2_rn(o[nt][2]*inv1, o[nt][3]*inv1);
        *reinterpret_cast<half2*>(cb + (long)r1*DIM + col) = h2b;
    }
}

// ---------------- attention tail: q-row 256, one block per (b,h) ----------------
__global__ __launch_bounds__(256)
void attn_tail_kernel(const __half* __restrict__ qkv, __half* __restrict__ ctx)
{
    int bh = blockIdx.x;
    int b = bh >> 4, h = bh & 15;
    const __half* qb = qkv + (long)b*SEQ*QKVD + 256l*QKVD + h*HDIM;
    const __half* kb = qkv + (long)b*SEQ*QKVD + DIM + h*HDIM;
    const __half* vb = qkv + (long)b*SEQ*QKVD + 2*DIM + h*HDIM;
    int tid = threadIdx.x;

    __shared__ float q[HDIM];
    __shared__ float sc[SEQ];
    __shared__ float red[256];

    if (tid < HDIM) q[tid] = __half2float(qb[tid]);
    __syncthreads();

    for (int j = tid; j < SEQ; j += 256) {
        const half2* kr = (const half2*)(kb + (long)j*QKVD);
        float s = 0.f;
        #pragma unroll
        for (int d = 0; d < HDIM/2; d++) {
            float2 kv = __half22float2(kr[d]);
            s += q[d*2]*kv.x + q[d*2+1]*kv.y;
        }
        sc[j] = s * ATTN_SCALE;
    }
    __syncthreads();

    float m = -3.0e38f;
    for (int j = tid; j < SEQ; j += 256) m = fmaxf(m, sc[j]);
    red[tid] = m; __syncthreads();
    for (int s = 128; s > 0; s >>= 1) { if (tid < s) red[tid] = fmaxf(red[tid], red[tid+s]); __syncthreads(); }
    m = red[0]; __syncthreads();

    float sum = 0.f;
    for (int j = tid; j < SEQ; j += 256) { float e = __expf(sc[j] - m); sc[j] = e; sum += e; }
    red[tid] = sum; __syncthreads();
    for (int s = 128; s > 0; s >>= 1) { if (tid < s) red[tid] += red[tid+s]; __syncthreads(); }
    float inv = 1.f / red[0];
    __syncthreads();

    int d = tid & 63, grp = tid >> 6;   // 4 groups x 64 dims
    float acc = 0.f;
    for (int j = grp; j < SEQ; j += 4)
        acc += sc[j] * __half2float(vb[(long)j*QKVD + d]);
    red[tid] = acc; __syncthreads();
    if (grp == 0) {
        float o = (red[d] + red[64+d] + red[128+d] + red[192+d]) * inv;
        ctx[(long)b*SEQ*DIM + 256l*DIM + h*HDIM + d] = __float2half_rn(o);
    }
}

// ---------------- host launch ----------------
static void* dsym(const void* symbol) { void* p = nullptr; cudaGetSymbolAddress(&p, symbol); return p; }
static inline dim3 hgrid(int N, int M, int Z) { return dim3((N+TBN-1)/TBN, (M+127)/128, Z); }
#define WIDE2_SMEM 98304

extern "C" void kernel_launch(void* const* d_in, const int* in_sizes, int n_in,
                              void* d_out, int out_size)
{
    const float* x   = (const float*)d_in[0];
    const float* gw1 = (const float*)d_in[1];
    const float* gb1 = (const float*)d_in[2];
    const float* gw2 = (const float*)d_in[3];
    const float* gb2 = (const float*)d_in[4];
    const float* Wm[4]; const float* Ue[4]; const float* Se[4]; const float* Ve[4]; const float* bi[4];
    for (int p = 0; p < 4; p++) {
        Wm[p] = (const float*)d_in[5 + p*5 + 0];
        Ue[p] = (const float*)d_in[5 + p*5 + 1];
        Se[p] = (const float*)d_in[5 + p*5 + 2];
        Ve[p] = (const float*)d_in[5 + p*5 + 3];
        bi[p] = (const float*)d_in[5 + p*5 + 4];
    }
    float* out = (float*)d_out;

    int*      idxp   = (int*)dsym(g_idx);
    float*    gatesp = (float*)dsym(g_gates);
    float*    pooled = (float*)dsym(g_pooled);
    float*    bcat   = (float*)dsym(g_bcat);
    __half*   xh     = (__half*)dsym(g_xh);
    uint32_t* xhp    = (uint32_t*)dsym(g_xhp);
    uint32_t* Wmp    = (uint32_t*)dsym(g_Wmp);
    uint32_t* ctxp   = (uint32_t*)dsym(g_ctxp);
    __half*   Vw     = (__half*)dsym(g_Vw);
    __half*   Uw     = (__half*)dsym(g_Uw);
    __half*   tbuf   = (__half*)dsym(g_t);
    __half*   t3     = (__half*)dsym(g_t3);
    __half*   qkv    = (__half*)dsym(g_qkv);
    __half*   ctx    = (__half*)dsym(g_ctx);

    const long UW_PER = (long)BATCH*DIM*32;

    cudaFuncSetAttribute(hgemm_wide2<__half>, cudaFuncAttributeMaxDynamicSharedMemorySize, WIDE2_SMEM);
    cudaFuncSetAttribute(hgemm_wide2<float>,  cudaFuncAttributeMaxDynamicSharedMemorySize, WIDE2_SMEM);

    // 0..2: dependencies of the wide QKV GEMM
    cvt_xp_kernel<<<(MBLK*32*512 + 255)/256, 256>>>(x, xhp);                       // 0
    cvt4p_kernel<<<(32*32*512 + 255)/256, 256>>>(Wm[0], Wm[1], Wm[2], Wm[3], Wmp); // 1
    concat_bias_kernel<<<12, 256>>>(bi[0], bi[1], bi[2], bcat);                    // 2

    // 3: fused main projection (4th-launch slot for ncu capture)
    hgemm_wide2<__half><<<dim3(QKVD/128, MBLK), 256, WIDE2_SMEM>>>(
        xhp, Wmp, bcat, qkv, MROWS, QKVD);

    // 4..7: gating path + row-major fp16 x + expert folding
    cvt_kernel<<<1184, 256>>>(x, xh, (long)MROWS*DIM);                             // 4
    pool_kernel<<<dim3(8, BATCH), 256>>>(x, pooled);                               // 5
    gating_kernel<<<BATCH, 256>>>(pooled, gw1, gb1, gw2, gb2, idxp, gatesp);       // 6
    build_uv_kernel<<<128, 256>>>(Ue[0], Ue[1], Ue[2], Ue[3],
                                  Se[0], Se[1], Se[2], Se[3],
                                  Ve[0], Ve[1], Ve[2], Ve[3],
                                  idxp, gatesp, Vw, Uw);                           // 7

    // 8: fused xV for q,k,v in ONE launch: t[b] = x_b @ Vw_b[0:96]^T  (N=96)
    hgemm<false,__half><<<hgrid(96, SEQ, BATCH), 256>>>(
        xh, Vw, tbuf,
        SEQ, 96, DIM, DIM, DIM, 96,
        0, (long)SD, 0, (long)128*DIM, 0, (long)SEQ*96, BATCH);

    // 9: fused expert accumulate: qkv[:, p*1024 + n] += t[:, p*32:(p+1)*32] @ Uw_p^T
    hgemm<true,__half><<<hgrid(DIM, SEQ, 3*BATCH), 256>>>(
        tbuf, Uw, qkv,
        SEQ, DIM, 32, 96, 32, QKVD,
        32, (long)SEQ*96, UW_PER, (long)DIM*32, (long)DIM, (long)SEQ*QKVD, BATCH);

    // 10: flash attention (rows 0..255) + 11: tail row 256
    flash_kernel<<<dim3(2, BATCH*NHEAD), 256>>>(qkv, ctx);
    attn_tail_kernel<<<BATCH*NHEAD, 256>>>(qkv, ctx);

    // 12: ctx low-rank projection: t3[b] = ctx_b @ Vw_b[96:128]^T
    hgemm<false,__half><<<hgrid(32, SEQ, BATCH), 256>>>(
        ctx, Vw + 96*DIM, t3,
        SEQ, 32, DIM, DIM, DIM, 32,
        0, (long)SD, 0, (long)128*DIM, 0, (long)SEQ*32, BATCH);

    // 13: permute ctx for the wide out-projection
    ctxp_kernel<<<(MBLK*32*512 + 255)/256, 256>>>(ctx, ctxp);

    // 14: out = ctx @ Wo^T + bo (fp32 out)
    hgemm_wide2<float><<<dim3(DIM/128, MBLK), 256, WIDE2_SMEM>>>(
        ctxp, Wmp + (long)24*32*2048, bi[3], out, MROWS, DIM);

    // 15: out += t3 @ Uw3^T (fp32 accumulate)
    hgemm<true,float><<<hgrid(DIM, SEQ, BATCH), 256>>>(
        t3, Uw + 3*UW_PER, out,
        SEQ, DIM, 32, 32, 32, DIM,
        0, (long)SEQ*32, 0, (long)DIM*32, 0, (long)SD, BATCH);
}

// round 13
// speedup vs baseline: 7.3491x; 1.0095x over previous
#include <cuda_runtime.h>
#include <cuda_fp16.h>
#include <math.h>
#include <stdint.h>

// ---------------- problem constants ----------------
#define BATCH 32
#define SEQ   257
#define DIM   1024
#define QKVD  3072
#define NHEAD 16
#define HDIM  64
#define NEXP  8
#define TOPK  2
#define RANK  16
#define GHID  256
#define SD    (SEQ*DIM)
#define MROWS (BATCH*SEQ)        // 8224
#define MBLK  65                 // ceil(8224/128)
#define ATTN_SCALE 0.125f
#define SCL2E 0.18033688011112042f   // ATTN_SCALE * log2(e)

// ---------------- static device scratch ----------------
__device__ int   g_idx[BATCH*TOPK];
__device__ float g_gates[BATCH*TOPK];
__device__ float g_pooled[BATCH*DIM];
__device__ float g_bcat[QKVD];
__device__ __align__(16) uint32_t g_xhp[(long)MBLK*32*2048];    // permuted x (A frag order)
__device__ __align__(16) uint32_t g_Wmp[(long)32*32*2048];      // permuted weights (B frag order)
__device__ __align__(16) uint32_t g_ctxp[(long)MBLK*32*2048];   // permuted ctx (zero-init padding)
__device__ __align__(16) __half g_Vw[(long)BATCH*128*DIM];      // [b][p*32+j][d]
__device__ __align__(16) __half g_Uw[4ll*BATCH*DIM*32];         // [p][b][n][j]
__device__ __align__(16) __half g_t [(long)BATCH*SEQ*96];       // qkv low-rank t [b][s][96]
__device__ __align__(16) __half g_t3[(long)BATCH*SEQ*32];       // o low-rank t
__device__ __align__(16) __half g_qkv[(long)(MROWS+32)*QKVD];
__device__ __align__(16) __half g_ctx[MROWS*DIM];

__device__ __forceinline__ uint32_t smem_u32(const void* p) {
    uint32_t a;
    asm("{ .reg .u64 t; cvta.to.shared.u64 t, %1; cvt.u32.u64 %0, t; }" : "=r"(a) : "l"(p));
    return a;
}
__device__ __forceinline__ void cp16(uint32_t saddr, const void* g) {
    asm volatile("cp.async.cg.shared.global [%0], [%1], 16;" :: "r"(saddr), "l"(g));
}

// permuted-ctx scatter: write half2 bits for (global row m, even col kz)
__device__ __forceinline__ void store_ctxp(uint32_t* __restrict__ cp, int m, int kz, uint32_t val)
{
    int mb = m >> 7, mrem = m & 127;
    int mt = mrem >> 4, w16 = mrem & 15;
    int g = w16 & 7, rh = w16 >> 3;
    int kc = kz >> 5, krem = kz & 31;
    int kk = krem >> 4, kin = krem & 15;
    int tg = (kin & 7) >> 1, kh = kin >> 3;
    long off = ((long)(mb*32 + kc)*512 + kk*256 + mt*32 + g*4 + tg)*4 + kh*2 + rh;
    cp[off] = val;
}

// ---------------- permutation kernels ----------------
__global__ void cvt_xp_kernel(const float* __restrict__ x, uint32_t* __restrict__ xp)
{
    long idx = (long)blockIdx.x * 256 + threadIdx.x;
    if (idx >= (long)MBLK*32*512) return;
    int q  = (int)(idx & 511);
    long r = idx >> 9;
    int kc = (int)(r & 31);
    int mb = (int)(r >> 5);
    int kk = q >> 8, mt = (q >> 5) & 7, lane = q & 31;
    int g = lane >> 2, tg = lane & 3;
    int mbase = mb*128 + mt*16 + g;
    int kbase = kc*32 + kk*16 + tg*2;
    uint32_t v[4];
    #pragma unroll
    for (int j = 0; j < 4; j++) {
        int kh = j >> 1, rh = j & 1;
        int m = mbase + rh*8;
        int kz = kbase + kh*8;
        half2 h2 = (m < MROWS)
            ? __floats2half2_rn(x[(long)m*DIM + kz], x[(long)m*DIM + kz + 1])
            : __floats2half2_rn(0.f, 0.f);
        v[j] = *reinterpret_cast<uint32_t*>(&h2);
    }
    *(uint4*)(xp + idx*4) = make_uint4(v[0], v[1], v[2], v[3]);
}

__global__ void cvt4p_kernel(const float* __restrict__ w0, const float* __restrict__ w1,
                             const float* __restrict__ w2, const float* __restrict__ w3,
                             uint32_t* __restrict__ wp)
{
    long idx = (long)blockIdx.x * 256 + threadIdx.x;
    if (idx >= (long)32*32*512) return;
    int q  = (int)(idx & 511);
    long r = idx >> 9;
    int kc = (int)(r & 31);
    int nb = (int)(r >> 5);
    int kk = q >> 8, np = (q >> 5) & 7, lane = q & 31;
    int gc = lane >> 2, tg = lane & 3;
    int kbase = kc*32 + kk*16 + tg*2;
    uint32_t v[4];
    #pragma unroll
    for (int j = 0; j < 4; j++) {
        int sub = j >> 1, kh = j & 1;
        int n = nb*128 + np*16 + sub*8 + gc;
        int p = n >> 10, row = n & 1023;
        const float* w = (p == 0) ? w0 : (p == 1) ? w1 : (p == 2) ? w2 : w3;
        int kz = kbase + kh*8;
        half2 h2 = __floats2half2_rn(w[(long)row*DIM + kz], w[(long)row*DIM + kz + 1]);
        v[j] = *reinterpret_cast<uint32_t*>(&h2);
    }
    *(uint4*)(wp + idx*4) = make_uint4(v[0], v[1], v[2], v[3]);
}

__global__ void concat_bias_kernel(const float* __restrict__ b0, const float* __restrict__ b1,
                                   const float* __restrict__ b2, float* __restrict__ dst)
{
    int i = blockIdx.x * 256 + threadIdx.x;
    if (i < DIM) dst[i] = b0[i];
    else if (i < 2*DIM) dst[i] = b1[i - DIM];
    else if (i < 3*DIM) dst[i] = b2[i - 2*DIM];
}

// ---------------- pooling (fp32, exact) ----------------
__global__ void pool_kernel(const float* __restrict__ x, float* __restrict__ pooled)
{
    int b = blockIdx.y;
    int d = blockIdx.x * 128 + (threadIdx.x & 127);
    int half = threadIdx.x >> 7;
    const float* xb = x + (long)b*SD + d;
    int t0 = half * 129;
    int t1 = half ? SEQ : 129;
    float s = 0.f;
    for (int t = t0; t < t1; t++) s += xb[(long)t*DIM];
    __shared__ float red[256];
    red[threadIdx.x] = s;
    __syncthreads();
    if (half == 0)
        pooled[b*DIM + d] = (red[threadIdx.x] + red[threadIdx.x + 128]) * (1.0f / SEQ);
}

// ---------------- gating MLP (exact fp32, float4 loads) ----------------
__global__ void gating_kernel(const float* __restrict__ pooled,
                              const float* __restrict__ gw1, const float* __restrict__ gb1,
                              const float* __restrict__ gw2, const float* __restrict__ gb2,
                              int* __restrict__ idx, float* __restrict__ gates)
{
    int b = blockIdx.x;
    int tid = threadIdx.x;
    __shared__ float pl[DIM];
    __shared__ float h[GHID];
    __shared__ float logits[NEXP];

    for (int d = tid; d < DIM; d += 256) pl[d] = pooled[b*DIM + d];
    __syncthreads();
    {
        float s = gb1[tid];
        const float4* w4 = (const float4*)(gw1 + (long)tid * DIM);
        #pragma unroll 4
        for (int d = 0; d < DIM/4; d++) {
            float4 wv = w4[d];
            const float* pv = &pl[d*4];
            s += pv[0]*wv.x + pv[1]*wv.y + pv[2]*wv.z + pv[3]*wv.w;
        }
        h[tid] = fmaxf(s, 0.f);
    }
    __syncthreads();
    if (tid < NEXP) {
        float s = gb2[tid];
        const float* w = gw2 + (long)tid * GHID;
        for (int g = 0; g < GHID; g++) s += h[g] * w[g];
        logits[tid] = s;
    }
    __syncthreads();
    if (tid == 0) {
        int i1 = 0; float v1 = logits[0];
        for (int e = 1; e < NEXP; e++) if (logits[e] > v1) { v1 = logits[e]; i1 = e; }
        int i2 = -1; float v2 = -3.0e38f;
        for (int e = 0; e < NEXP; e++) if (e != i1 && logits[e] > v2) { v2 = logits[e]; i2 = e; }
        float e2 = expf(v2 - v1);
        float inv = 1.f / (1.f + e2);
        idx[b*2] = i1; idx[b*2+1] = i2;
        gates[b*2] = inv; gates[b*2+1] = e2 * inv;
    }
}

// ---------------- fused fold: Vw -> [b][p*32+j][d], Uw -> [p][b][n][j] ----------------
__global__ void build_uv_kernel(const float* __restrict__ U0, const float* __restrict__ U1,
                                const float* __restrict__ U2, const float* __restrict__ U3,
                                const float* __restrict__ S0, const float* __restrict__ S1,
                                const float* __restrict__ S2, const float* __restrict__ S3,
                                const float* __restrict__ V0, const float* __restrict__ V1,
                                const float* __restrict__ V2, const float* __restrict__ V3,
                                const int* __restrict__ idx, const float* __restrict__ gates,
                                __half* __restrict__ VwAll, __half* __restrict__ UwAll)
{
    int p = blockIdx.x >> 5, b = blockIdx.x & 31;
    const float* U = (p == 0) ? U0 : (p == 1) ? U1 : (p == 2) ? U2 : U3;
    const float* Sg = (p == 0) ? S0 : (p == 1) ? S1 : (p == 2) ? S2 : S3;
    const float* V = (p == 0) ? V0 : (p == 1) ? V1 : (p == 2) ? V2 : V3;
    int tid = threadIdx.x;
    int e0 = idx[b*2], e1 = idx[b*2+1];
    float g0 = gates[b*2], g1 = gates[b*2+1];
    __half* vw = VwAll + ((long)b*128 + p*32) * DIM;
    __half* uw = UwAll + ((long)p*BATCH + b) * DIM * 32;

    for (int i = tid; i < 32*DIM; i += 256) {
        int j = i >> 10, d = i & (DIM-1);
        int k = j >> 4, r = j & 15;
        int e = k ? e1 : e0;
        vw[i] = __float2half_rn(Sg[e*RANK + r] * V[((long)e*RANK + r)*DIM + d]);
    }
    for (int i = tid; i < DIM*32; i += 256) {
        int n = i >> 5, j = i & 31;
        int k = j >> 4, r = j & 15;
        int e = k ? e1 : e0;
        float g = k ? g1 : g0;
        uw[i] = __float2half_rn(g * U[((long)e*DIM + n)*RANK + r]);
    }
}

// ---------------- FP16 MMA primitive ----------------
__device__ __forceinline__ void mma_f16(float c[4], const uint32_t a[4], const uint32_t b0, const uint32_t b1) {
    asm volatile(
        "mma.sync.aligned.m16n8k16.row.col.f32.f16.f16.f32 "
        "{%0,%1,%2,%3}, {%4,%5,%6,%7}, {%8,%9}, {%0,%1,%2,%3};"
        : "+f"(c[0]), "+f"(c[1]), "+f"(c[2]), "+f"(c[3])
        : "r"(a[0]), "r"(a[1]), "r"(a[2]), "r"(a[3]), "r"(b0), "r"(b1));
}

__device__ __forceinline__ float2 ld2(const float* p)  { return *reinterpret_cast<const float2*>(p); }
__device__ __forceinline__ float2 ld2(const __half* p) { return __half22float2(*reinterpret_cast<const half2*>(p)); }
__device__ __forceinline__ void st2(float* p, float v0, float v1)  { *reinterpret_cast<float2*>(p) = make_float2(v0, v1); }
__device__ __forceinline__ void st2(__half* p, float v0, float v1) { *reinterpret_cast<half2*>(p) = __floats2half2_rn(v0, v1); }

// 8-element (16B-as-half) A loaders: half passthrough, float converts
__device__ __forceinline__ uint4 ldA8(const __half* p) { return *(const uint4*)p; }
__device__ __forceinline__ uint4 ldA8(const float* p) {
    float4 a = *(const float4*)p;
    float4 b = *(const float4*)(p + 4);
    half2 h0 = __floats2half2_rn(a.x, a.y);
    half2 h1 = __floats2half2_rn(a.z, a.w);
    half2 h2 = __floats2half2_rn(b.x, b.y);
    half2 h3 = __floats2half2_rn(b.z, b.w);
    return make_uint4(*reinterpret_cast<uint32_t*>(&h0), *reinterpret_cast<uint32_t*>(&h1),
                      *reinterpret_cast<uint32_t*>(&h2), *reinterpret_cast<uint32_t*>(&h3));
}

__device__ __forceinline__ uint32_t ex2_h2(float e0, float e1) {
    half2 h = __floats2half2_rn(e0, e1);
    uint32_t in = *reinterpret_cast<uint32_t*>(&h), r;
    asm("ex2.approx.f16x2 %0, %1;" : "=r"(r) : "r"(in));
    return r;
}

// ==================== WIDE FP16 GEMM: 2-chunk stages, 3-stage ring (96KB) ======
template<typename CT>
__global__ __launch_bounds__(256, 2)
void hgemm_wide2(const uint32_t* __restrict__ Ap, const uint32_t* __restrict__ Bp,
                 const float* __restrict__ bias, CT* __restrict__ C, int M, int ldc)
{
    extern __shared__ uint32_t sh[];
    uint32_t shb = smem_u32(sh);
    int tid = threadIdx.x;
    int warp = tid >> 5, lane = tid & 31;
    int mt0 = (warp & 3) * 2;
    int np0 = (warp >> 2) * 4;
    int g = lane >> 2, tg = lane & 3;
    int m0 = blockIdx.y * 128, n0 = blockIdx.x * 128;

    const uint32_t* Ar = Ap + (long)blockIdx.y * 32 * 2048;
    const uint32_t* Br = Bp + (long)blockIdx.x * 32 * 2048;

    float acc[2][8][4] = {};

    auto issue = [&](int pr) {
        uint32_t sbase = shb + (uint32_t)(pr % 3) * 32768;
        #pragma unroll
        for (int c = 0; c < 2; c++) {
            int kc = pr*2 + c;
            uint32_t d = sbase + c*16384u;
            const uint32_t* a = Ar + kc * 2048;
            const uint32_t* b = Br + kc * 2048;
            cp16(d +          tid*16, a + tid*4);
            cp16(d +  4096u + tid*16, a + 1024 + tid*4);
            cp16(d +  8192u + tid*16, b + tid*4);
            cp16(d + 12288u + tid*16, b + 1024 + tid*4);
        }
        asm volatile("cp.async.commit_group;");
    };

    issue(0);
    issue(1);

    for (int j = 0; j < 16; j++) {
        if (j < 15) asm volatile("cp.async.wait_group 1;");
        else        asm volatile("cp.async.wait_group 0;");
        __syncthreads();
        if (j + 2 < 16) issue(j + 2);

        uint32_t* stage = sh + (j % 3) * 8192;
        #pragma unroll
        for (int c = 0; c < 2; c++) {
            const uint32_t* As = stage + c*4096;
            const uint32_t* Bs = As + 2048;
            #pragma unroll
            for (int kk = 0; kk < 2; kk++) {
                uint4 a4[2];
                a4[0] = *(const uint4*)&As[((kk*8 + mt0    )*32 + lane)*4];
                a4[1] = *(const uint4*)&As[((kk*8 + mt0 + 1)*32 + lane)*4];
                uint4 bp[4];
                #pragma unroll
                for (int p = 0; p < 4; p++)
                    bp[p] = *(const uint4*)&Bs[((kk*8 + np0 + p)*32 + lane)*4];
                #pragma unroll
                for (int i = 0; i < 2; i++) {
                    uint32_t a[4] = { a4[i].x, a4[i].y, a4[i].z, a4[i].w };
                    #pragma unroll
                    for (int p = 0; p < 4; p++) {
                        mma_f16(acc[i][2*p    ], a, bp[p].x, bp[p].y);
                        mma_f16(acc[i][2*p + 1], a, bp[p].z, bp[p].w);
                    }
                }
            }
        }
    }

    #pragma unroll
    for (int i = 0; i < 2; i++) {
        #pragma unroll
        for (int rs = 0; rs < 2; rs++) {
            int gm = m0 + (mt0 + i)*16 + g + rs*8;
            if (gm >= M) continue;
            #pragma unroll
            for (int j = 0; j < 8; j++) {
                int gn = n0 + (np0*2 + j)*8 + tg*2;
                long off = (long)gm*ldc + gn;
                st2(&C[off], acc[i][j][rs*2+0] + bias[gn], acc[i][j][rs*2+1] + bias[gn+1]);
            }
        }
    }
}

// ==================== general batched FP16 GEMM (double-buffered, typed A) ==========
#define TBN 64
template<bool ACC, typename AT, typename CT>
__global__ __launch_bounds__(256, 2)
void hgemm(const AT* __restrict__ A, const __half* __restrict__ B,
           CT* __restrict__ C,
           int M, int N, int K, int lda, int ldb, int ldc,
           long sA1, long sA2, long sB1, long sB2, long sC1, long sC2, int zdiv)
{
    int z = blockIdx.z;
    long zq = z / zdiv, zr = z % zdiv;
    A += zq*sA1 + zr*sA2;
    B += zq*sB1 + zr*sB2;
    C += zq*sC1 + zr*sC2;

    int m0 = blockIdx.y * 128, n0 = blockIdx.x * TBN;
    __shared__ uint32_t As[2][2048];
    __shared__ uint32_t Bs[2][1024];

    int tid = threadIdx.x;
    int warp = tid >> 5, lane = tid & 31;
    int mt0 = (warp & 3) * 2;
    int np0 = (warp >> 2) * 2;
    int g = lane >> 2, tg = lane & 3;

    float acc[2][4][4] = {};
    uint4 ar[2], br;

    const int KB = K / 32;

    auto load_regs = [&](int kb) {
        int k0 = kb * 32;
        #pragma unroll
        for (int i = 0; i < 2; i++) {
            int f4 = i*256 + tid;
            int row = f4 >> 2, c8 = f4 & 3;
            int gm = m0 + row;
            ar[i] = (gm < M) ? ldA8(A + (long)gm*lda + k0 + c8*8)
                             : make_uint4(0u,0u,0u,0u);
        }
        {
            int n = tid >> 2, c8 = tid & 3;
            int gn = n0 + n;
            br = (gn < N) ? *(const uint4*)(B + (long)gn*ldb + k0 + c8*8)
                          : make_uint4(0u,0u,0u,0u);
        }
    };

    auto sts = [&](int s) {
        #pragma unroll
        for (int i = 0; i < 2; i++) {
            int f4 = i*256 + tid;
            int row = f4 >> 2, c8 = f4 & 3;
            int kk = c8 >> 1, kh = c8 & 1;
            int mt = row >> 4, w = row & 15, gg = w & 7, rh = w >> 3;
            int base = ((kk*8 + mt)*32 + gg*4)*4 + kh*2 + rh;
            As[s][base +  0] = ar[i].x;
            As[s][base +  4] = ar[i].y;
            As[s][base +  8] = ar[i].z;
            As[s][base + 12] = ar[i].w;
        }
        {
            int n = tid >> 2, c8 = tid & 3;
            int kk = c8 >> 1, kh = c8 & 1;
            int nt = n >> 3, gc = n & 7, np = nt >> 1, sub = nt & 1;
            int base = ((kk*4 + np)*32 + gc*4)*4 + sub*2 + kh;
            Bs[s][base +  0] = br.x;
            Bs[s][base +  4] = br.y;
            Bs[s][base +  8] = br.z;
            Bs[s][base + 12] = br.w;
        }
    };

    load_regs(0);
    sts(0);
    __syncthreads();

    for (int kb = 0; kb < KB; kb++) {
        int s = kb & 1;
        if (kb + 1 < KB) load_regs(kb + 1);

        #pragma unroll
        for (int kk = 0; kk < 2; kk++) {
            uint4 a4[2];
            a4[0] = *(const uint4*)&As[s][((kk*8 + mt0    )*32 + lane)*4];
            a4[1] = *(const uint4*)&As[s][((kk*8 + mt0 + 1)*32 + lane)*4];
            uint4 bp[2];
            bp[0] = *(const uint4*)&Bs[s][((kk*4 + np0    )*32 + lane)*4];
            bp[1] = *(const uint4*)&Bs[s][((kk*4 + np0 + 1)*32 + lane)*4];
            #pragma unroll
            for (int i = 0; i < 2; i++) {
                uint32_t a[4] = { a4[i].x, a4[i].y, a4[i].z, a4[i].w };
                #pragma unroll
                for (int p = 0; p < 2; p++) {
                    mma_f16(acc[i][2*p    ], a, bp[p].x, bp[p].y);
                    mma_f16(acc[i][2*p + 1], a, bp[p].z, bp[p].w);
                }
            }
        }

        if (kb + 1 < KB) {
            sts(s ^ 1);
            __syncthreads();
        }
    }

    #pragma unroll
    for (int i = 0; i < 2; i++) {
        #pragma unroll
        for (int rs = 0; rs < 2; rs++) {
            int gm = m0 + (mt0 + i)*16 + g + rs*8;
            if (gm >= M) continue;
            #pragma unroll
            for (int j = 0; j < 4; j++) {
                int gn = n0 + (np0*2 + j)*8 + tg*2;
                if (gn >= N) continue;
                long off = (long)gm*ldc + gn;
                float v0 = acc[i][j][rs*2+0];
                float v1 = acc[i][j][rs*2+1];
                if (ACC) { float2 c2 = ld2(&C[off]); v0 += c2.x; v1 += c2.y; }
                st2(&C[off], v0, v1);
            }
        }
    }
}

// ==================== FLASH ATTENTION rows 0..255 ====================
// scale folded into exp2 constant; masking only on last kv tile; writes ctx AND ctxp
__global__ __launch_bounds__(256)
void flash_kernel(const __half* __restrict__ qkv, __half* __restrict__ ctx,
                  uint32_t* __restrict__ ctxp)
{
    __shared__ uint32_t ks[2048];
    __shared__ uint32_t vs[2048];
    __shared__ uint32_t ps[4096];

    int tid = threadIdx.x, warp = tid >> 5, lane = tid & 31;
    int g = lane >> 2, tg = lane & 3;
    int bh = blockIdx.y;
    int b = bh >> 4, h = bh & 15;
    int m0 = blockIdx.x * 128;

    const __half* qb = qkv + (long)b*SEQ*QKVD + h*HDIM;
    const __half* kb = qkv + (long)b*SEQ*QKVD + DIM + h*HDIM;
    const __half* vb = qkv + (long)b*SEQ*QKVD + 2*DIM + h*HDIM;

    int r0 = m0 + warp*16 + g;      // always < 256
    int r1 = r0 + 8;

    uint32_t qa[4][4];
    #pragma unroll
    for (int kk = 0; kk < 4; kk++) {
        qa[kk][0] = *(const uint32_t*)(qb + (long)r0*QKVD + kk*16 + 2*tg);
        qa[kk][1] = *(const uint32_t*)(qb + (long)r1*QKVD + kk*16 + 2*tg);
        qa[kk][2] = *(const uint32_t*)(qb + (long)r0*QKVD + kk*16 + 8 + 2*tg);
        qa[kk][3] = *(const uint32_t*)(qb + (long)r1*QKVD + kk*16 + 8 + 2*tg);
    }

    float o[8][4] = {};
    float m0r = -1e30f, m1r = -1e30f, l0r = 0.f, l1r = 0.f;

    for (int j = 0; j < 5; j++) {
        int kv0 = j * 64;
        #pragma unroll
        for (int i = 0; i < 2; i++) {
            int f4 = i*256 + tid;
            int n = f4 >> 3, c8 = f4 & 7;
            int gr = kv0 + n;
            uint4 v = (gr < SEQ) ? *(const uint4*)(kb + (long)gr*QKVD + c8*8)
                                 : make_uint4(0u,0u,0u,0u);
            int kk = c8 >> 1, kh = c8 & 1;
            int nt = n >> 3, gc = n & 7;
            int base = ((kk*8 + nt)*32 + gc*4)*2 + kh;
            ks[base + 0] = v.x;
            ks[base + 2] = v.y;
            ks[base + 4] = v.z;
            ks[base + 6] = v.w;
        }
        {
            int kvpair = tid >> 3, nt = tid & 7;
            int rA = kv0 + kvpair*2, rB = rA + 1;
            union { uint4 u; __half hx[8]; } ua, ub;
            ua.u = (rA < SEQ) ? *(const uint4*)(vb + (long)rA*QKVD + nt*8) : make_uint4(0u,0u,0u,0u);
            ub.u = (rB < SEQ) ? *(const uint4*)(vb + (long)rB*QKVD + nt*8) : make_uint4(0u,0u,0u,0u);
            int klocal = kvpair*2;
            int kk = klocal >> 4, kin = klocal & 15;
            int kh = kin >> 3, t = (kin & 7) >> 1;
            #pragma unroll
            for (int jj = 0; jj < 8; jj++) {
                half2 h2 = __halves2half2(ua.hx[jj], ub.hx[jj]);
                vs[((kk*8 + nt)*32 + jj*4 + t)*2 + kh] = *reinterpret_cast<uint32_t*>(&h2);
            }
        }
        __syncthreads();

        float s[8][4] = {};
        #pragma unroll
        for (int kk = 0; kk < 4; kk++) {
            #pragma unroll
            for (int nt = 0; nt < 8; nt++) {
                uint2 bb = *(const uint2*)&ks[((kk*8 + nt)*32 + lane)*2];
                mma_f16(s[nt], qa[kk], bb.x, bb.y);
            }
        }

        // raw-score max (scale folded into exp constant); mask only the last tile
        float tmax0 = -1e30f, tmax1 = -1e30f;
        if (j < 4) {
            #pragma unroll
            for (int nt = 0; nt < 8; nt++) {
                tmax0 = fmaxf(tmax0, fmaxf(s[nt][0], s[nt][1]));
                tmax1 = fmaxf(tmax1, fmaxf(s[nt][2], s[nt][3]));
            }
        } else {
            #pragma unroll
            for (int nt = 0; nt < 8; nt++) {
                int c0 = kv0 + nt*8 + 2*tg;
                if (c0     >= SEQ) { s[nt][0] = -1e30f; s[nt][2] = -1e30f; }
                if (c0 + 1 >= SEQ) { s[nt][1] = -1e30f; s[nt][3] = -1e30f; }
                tmax0 = fmaxf(tmax0, fmaxf(s[nt][0], s[nt][1]));
                tmax1 = fmaxf(tmax1, fmaxf(s[nt][2], s[nt][3]));
            }
        }
        tmax0 = fmaxf(tmax0, __shfl_xor_sync(0xffffffffu, tmax0, 1));
        tmax0 = fmaxf(tmax0, __shfl_xor_sync(0xffffffffu, tmax0, 2));
        tmax1 = fmaxf(tmax1, __shfl_xor_sync(0xffffffffu, tmax1, 1));
        tmax1 = fmaxf(tmax1, __shfl_xor_sync(0xffffffffu, tmax1, 2));
        float nm0 = fmaxf(m0r, tmax0), nm1 = fmaxf(m1r, tmax1);
        float f0 = exp2f((m0r - nm0)*SCL2E), f1 = exp2f((m1r - nm1)*SCL2E);

        float sum0 = 0.f, sum1 = 0.f;
        #pragma unroll
        for (int nt = 0; nt < 8; nt++) {
            uint32_t r01 = ex2_h2((s[nt][0] - nm0)*SCL2E, (s[nt][1] - nm0)*SCL2E);
            uint32_t r23 = ex2_h2((s[nt][2] - nm1)*SCL2E, (s[nt][3] - nm1)*SCL2E);
            float2 f01 = __half22float2(*reinterpret_cast<half2*>(&r01));
            float2 f23 = __half22float2(*reinterpret_cast<half2*>(&r23));
            sum0 += f01.x + f01.y;
            sum1 += f23.x + f23.y;
            int kkp = nt >> 1, kh = nt & 1;
            int base = ((kkp*8 + warp)*32 + lane)*4 + kh*2;
            ps[base + 0] = r01;
            ps[base + 1] = r23;
        }
        sum0 += __shfl_xor_sync(0xffffffffu, sum0, 1);
        sum0 += __shfl_xor_sync(0xffffffffu, sum0, 2);
        sum1 += __shfl_xor_sync(0xffffffffu, sum1, 1);
        sum1 += __shfl_xor_sync(0xffffffffu, sum1, 2);
        l0r = l0r*f0 + sum0;
        l1r = l1r*f1 + sum1;
        m0r = nm0; m1r = nm1;
        #pragma unroll
        for (int nt = 0; nt < 8; nt++) {
            o[nt][0] *= f0; o[nt][1] *= f0;
            o[nt][2] *= f1; o[nt][3] *= f1;
        }

        #pragma unroll
        for (int kk = 0; kk < 4; kk++) {
            uint4 p4 = *(const uint4*)&ps[((kk*8 + warp)*32 + lane)*4];
            uint32_t pa[4] = { p4.x, p4.y, p4.z, p4.w };
            #pragma unroll
            for (int nt = 0; nt < 8; nt++) {
                uint2 vv = *(const uint2*)&vs[((kk*8 + nt)*32 + lane)*2];
                mma_f16(o[nt], pa, vv.x, vv.y);
            }
        }
        __syncthreads();
    }

    float inv0 = 1.f / l0r, inv1 = 1.f / l1r;
    __half* cb = ctx + (long)b*SEQ*DIM + h*HDIM;
    int gm0 = b*SEQ + r0, gm1 = b*SEQ + r1;
    #pragma unroll
    for (int nt = 0; nt < 8; nt++) {
        int col = nt*8 + 2*tg;
        half2 h2a = __floats2half2_rn(o[nt][0]*inv0, o[nt][1]*inv0);
        *reinterpret_cast<half2*>(cb + (long)r0*DIM + col) = h2a;
        store_ctxp(ctxp, gm0, h*HDIM + col, *reinterpret_cast<uint32_t*>(&h2a));
        half2 h2b = __floats2half2_rn(o[nt][2]*inv1, o[nt][3]*inv1);
        *reinterpret_cast<half2*>(cb + (long)r1*DIM + col) = h2b;
        store_ctxp(ctxp, gm1, h*HDIM + col, *reinterpret_cast<uint32_t*>(&h2b));
    }
}

// ---------------- attention tail: q-row 256 (writes ctx + ctxp) ----------------
__global__ __launch_bounds__(256)
void attn_tail_kernel(const __half* __restrict__ qkv, __half* __restrict__ ctx,
                      uint32_t* __restrict__ ctxp)
{
    int bh = blockIdx.x;
    int b = bh >> 4, h = bh & 15;
    const __half* qb = qkv + (long)b*SEQ*QKVD + 256l*QKVD + h*HDIM;
    const __half* kb = qkv + (long)b*SEQ*QKVD + DIM + h*HDIM;
    const __half* vb = qkv + (long)b*SEQ*QKVD + 2*DIM + h*HDIM;
    int tid = threadIdx.x;

    __shared__ float q[HDIM];
    __shared__ float sc[SEQ];
    __shared__ float red[256];

    if (tid < HDIM) q[tid] = __half2float(qb[tid]);
    __syncthreads();

    for (int j = tid; j < SEQ; j += 256) {
        const half2* kr = (const half2*)(kb + (long)j*QKVD);
        float s = 0.f;
        #pragma unroll
        for (int d = 0; d < HDIM/2; d++) {
            float2 kv = __half22float2(kr[d]);
            s += q[d*2]*kv.x + q[d*2+1]*kv.y;
        }
        sc[j] = s * ATTN_SCALE;
    }
    __syncthreads();

    float m = -3.0e38f;
    for (int j = tid; j < SEQ; j += 256) m = fmaxf(m, sc[j]);
    red[tid] = m; __syncthreads();
    for (int s = 128; s > 0; s >>= 1) { if (tid < s) red[tid] = fmaxf(red[tid], red[tid+s]); __syncthreads(); }
    m = red[0]; __syncthreads();

    float sum = 0.f;
    for (int j = tid; j < SEQ; j += 256) { float e = __expf(sc[j] - m); sc[j] = e; sum += e; }
    red[tid] = sum; __syncthreads();
    for (int s = 128; s > 0; s >>= 1) { if (tid < s) red[tid] += red[tid+s]; __syncthreads(); }
    float inv = 1.f / red[0];
    __syncthreads();

    int d = tid & 63, grp = tid >> 6;
    float acc = 0.f;
    for (int j = grp; j < SEQ; j += 4)
        acc += sc[j] * __half2float(vb[(long)j*QKVD + d]);
    red[tid] = acc; __syncthreads();
    if (grp == 0) {
        float o = (red[d] + red[64+d] + red[128+d] + red[192+d]) * inv;
        ctx[(long)b*SEQ*DIM + 256l*DIM + h*HDIM + d] = __float2half_rn(o);
        float o2 = __shfl_down_sync(0xffffffffu, o, 1);
        if ((d & 1) == 0) {
            half2 hv = __floats2half2_rn(o, o2);
            store_ctxp(ctxp, b*SEQ + 256, h*HDIM + d, *reinterpret_cast<uint32_t*>(&hv));
        }
    }
}

// ---------------- host launch ----------------
static void* dsym(const void* symbol) { void* p = nullptr; cudaGetSymbolAddress(&p, symbol); return p; }
static inline dim3 hgrid(int N, int M, int Z) { return dim3((N+TBN-1)/TBN, (M+127)/128, Z); }
#define WIDE2_SMEM 98304

extern "C" void kernel_launch(void* const* d_in, const int* in_sizes, int n_in,
                              void* d_out, int out_size)
{
    const float* x   = (const float*)d_in[0];
    const float* gw1 = (const float*)d_in[1];
    const float* gb1 = (const float*)d_in[2];
    const float* gw2 = (const float*)d_in[3];
    const float* gb2 = (const float*)d_in[4];
    const float* Wm[4]; const float* Ue[4]; const float* Se[4]; const float* Ve[4]; const float* bi[4];
    for (int p = 0; p < 4; p++) {
        Wm[p] = (const float*)d_in[5 + p*5 + 0];
        Ue[p] = (const float*)d_in[5 + p*5 + 1];
        Se[p] = (const float*)d_in[5 + p*5 + 2];
        Ve[p] = (const float*)d_in[5 + p*5 + 3];
        bi[p] = (const float*)d_in[5 + p*5 + 4];
    }
    float* out = (float*)d_out;

    int*      idxp   = (int*)dsym(g_idx);
    float*    gatesp = (float*)dsym(g_gates);
    float*    pooled = (float*)dsym(g_pooled);
    float*    bcat   = (float*)dsym(g_bcat);
    uint32_t* xhp    = (uint32_t*)dsym(g_xhp);
    uint32_t* Wmp    = (uint32_t*)dsym(g_Wmp);
    uint32_t* ctxp   = (uint32_t*)dsym(g_ctxp);
    __half*   Vw     = (__half*)dsym(g_Vw);
    __half*   Uw     = (__half*)dsym(g_Uw);
    __half*   tbuf   = (__half*)dsym(g_t);
    __half*   t3     = (__half*)dsym(g_t3);
    __half*   qkv    = (__half*)dsym(g_qkv);
    __half*   ctx    = (__half*)dsym(g_ctx);

    const long UW_PER = (long)BATCH*DIM*32;

    cudaFuncSetAttribute(hgemm_wide2<__half>, cudaFuncAttributeMaxDynamicSharedMemorySize, WIDE2_SMEM);
    cudaFuncSetAttribute(hgemm_wide2<float>,  cudaFuncAttributeMaxDynamicSharedMemorySize, WIDE2_SMEM);

    // 0..2: dependencies of the wide QKV GEMM
    cvt_xp_kernel<<<(MBLK*32*512 + 255)/256, 256>>>(x, xhp);                       // 0
    cvt4p_kernel<<<(32*32*512 + 255)/256, 256>>>(Wm[0], Wm[1], Wm[2], Wm[3], Wmp); // 1
    concat_bias_kernel<<<12, 256>>>(bi[0], bi[1], bi[2], bcat);                    // 2

    // 3: fused main projection
    hgemm_wide2<__half><<<dim3(QKVD/128, MBLK), 256, WIDE2_SMEM>>>(
        xhp, Wmp, bcat, qkv, MROWS, QKVD);

    // 4..6: gating path + expert folding
    pool_kernel<<<dim3(8, BATCH), 256>>>(x, pooled);                               // 4
    gating_kernel<<<BATCH, 256>>>(pooled, gw1, gb1, gw2, gb2, idxp, gatesp);       // 5
    build_uv_kernel<<<128, 256>>>(Ue[0], Ue[1], Ue[2], Ue[3],
                                  Se[0], Se[1], Se[2], Se[3],
                                  Ve[0], Ve[1], Ve[2], Ve[3],
                                  idxp, gatesp, Vw, Uw);                           // 6

    // 7: fused xV for q,k,v (reads fp32 x directly): t[b] = x_b @ Vw_b[0:96]^T
    hgemm<false, float, __half><<<hgrid(96, SEQ, BATCH), 256>>>(
        x, Vw, tbuf,
        SEQ, 96, DIM, DIM, DIM, 96,
        0, (long)SD, 0, (long)128*DIM, 0, (long)SEQ*96, BATCH);

    // 8: fused expert accumulate: qkv[:, p*1024 + n] += t[:, p*32:(p+1)*32] @ Uw_p^T
    hgemm<true, __half, __half><<<hgrid(DIM, SEQ, 3*BATCH), 256>>>(
        tbuf, Uw, qkv,
        SEQ, DIM, 32, 96, 32, QKVD,
        32, (long)SEQ*96, UW_PER, (long)DIM*32, (long)DIM, (long)SEQ*QKVD, BATCH);

    // 9: flash attention (rows 0..255, writes ctx + ctxp) + 10: tail row 256
    flash_kernel<<<dim3(2, BATCH*NHEAD), 256>>>(qkv, ctx, ctxp);
    attn_tail_kernel<<<BATCH*NHEAD, 256>>>(qkv, ctx, ctxp);

    // 11: ctx low-rank projection: t3[b] = ctx_b @ Vw_b[96:128]^T
    hgemm<false, __half, __half><<<hgrid(32, SEQ, BATCH), 256>>>(
        ctx, Vw + 96*DIM, t3,
        SEQ, 32, DIM, DIM, DIM, 32,
        0, (long)SD, 0, (long)128*DIM, 0, (long)SEQ*32, BATCH);

    // 12: out = ctx @ Wo^T + bo (fp32 out; ctxp written by flash/tail)
    hgemm_wide2<float><<<dim3(DIM/128, MBLK), 256, WIDE2_SMEM>>>(
        ctxp, Wmp + (long)24*32*2048, bi[3], out, MROWS, DIM);

    // 13: out += t3 @ Uw3^T (fp32 accumulate)
    hgemm<true, __half, float><<<hgrid(DIM, SEQ, BATCH), 256>>>(
        t3, Uw + 3*UW_PER, out,
        SEQ, DIM, 32, 32, 32, DIM,
        0, (long)SEQ*32, 0, (long)DIM*32, 0, (long)SD, BATCH);
}